// round 8
// baseline (speedup 1.0000x reference)
#include <cuda_runtime.h>
#include <cstdint>
#include <math.h>

#define H       256
#define FH      1024
#define NNODE   20000
#define NEDGE   160000
#define NLG     640000

// ---------------- scratch (static device memory; no allocations) ----------------
__device__ float g_x[2][(size_t)NNODE * H];
__device__ float g_lg[2][(size_t)NEDGE * H];
__device__ float g_fn[(size_t)NNODE * H];
__device__ float g_fe[(size_t)NEDGE * H];
__device__ float g_z[4][(size_t)NEDGE * H];    // edge-core khop scratch
__device__ float g_zn[4][(size_t)NNODE * H];   // node-core khop scratch
__device__ float g_out1[(size_t)NEDGE * H];    // edge-core out1
__device__ float g_out1n[(size_t)NNODE * H];   // node-core out1 (stream overlap)

// packed (tf32-rounded, fragment-order) weights
#define OFF_WSELF 0
#define OFF_WKHOP (OFF_WSELF + 4 * H * H)
#define OFF_WFUSE (OFF_WKHOP + 16 * H * H)
#define OFF_WFF1  (OFF_WFUSE + 4 * H * H)
#define OFF_WFF2  (OFF_WFF1 + 4 * H * FH)
#define WBUF_TOT  (OFF_WFF2 + 4 * FH * H)
__device__ float g_wbuf[WBUF_TOT];

// CSR structures
__device__ int g_rp_nd[NNODE + 1];
__device__ int g_ci_nd[NEDGE];
__device__ int g_rp_fn[NNODE + 1];
__device__ int g_ci_fn[2 * NEDGE];
__device__ int g_rp_lg[NEDGE + 1];
__device__ int g_ci_lg[NLG];
__device__ int g_cnt[NEDGE];
__device__ int g_cur[NEDGE];
__device__ int g_bs[1024];

__device__ __forceinline__ float gelu_exact(float v) {
    return 0.5f * v * (1.0f + erff(v * 0.70710678118654752f));
}

__device__ __forceinline__ float f2tf32f(float f) {
    uint32_t r;
    asm("cvt.rna.tf32.f32 %0, %1;" : "=r"(r) : "f"(f));
    return __uint_as_float(r);
}

__device__ __forceinline__ void mma_tf32(float* c, const uint32_t* a, const uint32_t* b) {
    asm volatile(
        "mma.sync.aligned.m16n8k8.row.col.f32.tf32.tf32.f32 "
        "{%0,%1,%2,%3}, {%4,%5,%6,%7}, {%8,%9}, {%0,%1,%2,%3};"
        : "+f"(c[0]), "+f"(c[1]), "+f"(c[2]), "+f"(c[3])
        : "r"(a[0]), "r"(a[1]), "r"(a[2]), "r"(a[3]), "r"(b[0]), "r"(b[1]));
}

// ---------------- CSR build kernels ----------------

__global__ void hist_kernel(const int* __restrict__ key, int* cnt, int n) {
    int i = blockIdx.x * 256 + threadIdx.x;
    if (i < n) atomicAdd(&cnt[__ldg(key + i)], 1);
}

__global__ void scan1_kernel(const int* __restrict__ in, int* __restrict__ out,
                             int* __restrict__ bsums, int n) {
    __shared__ int sh[1024];
    int i = blockIdx.x * 1024 + threadIdx.x;
    int v = (i < n) ? in[i] : 0;
    sh[threadIdx.x] = v;
    __syncthreads();
#pragma unroll
    for (int o = 1; o < 1024; o <<= 1) {
        int t = (threadIdx.x >= o) ? sh[threadIdx.x - o] : 0;
        __syncthreads();
        sh[threadIdx.x] += t;
        __syncthreads();
    }
    if (i < n) out[i] = sh[threadIdx.x] - v;     // exclusive
    if (threadIdx.x == 1023) bsums[blockIdx.x] = sh[1023];
}

__global__ void scan2_kernel(int* bsums, int nb) {
    __shared__ int sh[1024];
    int v = (threadIdx.x < nb) ? bsums[threadIdx.x] : 0;
    sh[threadIdx.x] = v;
    __syncthreads();
#pragma unroll
    for (int o = 1; o < 1024; o <<= 1) {
        int t = (threadIdx.x >= o) ? sh[threadIdx.x - o] : 0;
        __syncthreads();
        sh[threadIdx.x] += t;
        __syncthreads();
    }
    if (threadIdx.x < nb) bsums[threadIdx.x] = sh[threadIdx.x] - v;  // exclusive
}

__global__ void scan3_kernel(int* __restrict__ out, const int* __restrict__ bsums,
                             const int* __restrict__ cnt, int n) {
    int i = blockIdx.x * 1024 + threadIdx.x;
    if (i < n) {
        int v = out[i] + bsums[i >> 10];
        out[i] = v;
        if (i == n - 1) out[n] = v + cnt[i];
    }
}

__global__ void fill_kernel(const int* __restrict__ key, const int* __restrict__ val,
                            int* cursor, int* __restrict__ ci, int n) {
    int i = blockIdx.x * 256 + threadIdx.x;
    if (i >= n) return;
    int pos = atomicAdd(&cursor[__ldg(key + i)], 1);
    ci[pos] = val ? __ldg(val + i) : i;
}

// ---------------- weight pack kernels (tf32 round + fragment permutation) ----------------
// float4 = { W[k][n], W[k+4][n], W[k][n+8], W[k+4][n+8] }, k = kt*32+ks*8+t

// H x H (gemm1 weights), m32n64 warp tile: [kt(8)][ks(4)][wN(4)][nf2(4)][lane(32)]
__global__ void pack256_kernel(const float* __restrict__ W, float* __restrict__ out, int nmat) {
    int gid = blockIdx.x * 256 + threadIdx.x;
    if (gid >= nmat * 16384) return;
    int m = gid >> 14, o = gid & 16383;
    int kt = o >> 11, i4 = o & 2047;
    int ks = i4 >> 9, r = i4 & 511;
    int wN = r >> 7, r2 = r & 127;
    int nf2 = r2 >> 5, lane = r2 & 31;
    int t = lane & 3, g = lane >> 2;
    int k = kt * 32 + ks * 8 + t;
    int n = wN * 64 + nf2 * 16 + g;
    const float* Wm = W + (size_t)m * 65536;
    float4 v;
    v.x = f2tf32f(Wm[k * 256 + n]);
    v.y = f2tf32f(Wm[(k + 4) * 256 + n]);
    v.z = f2tf32f(Wm[k * 256 + n + 8]);
    v.w = f2tf32f(Wm[(k + 4) * 256 + n + 8]);
    ((float4*)out)[gid] = v;
}

// w_ff1 [256, 1024]: [c(8)][kt(8)][ks(4)][wN(4)][nf2(2)][lane] float4
__global__ void packff1_kernel(const float* __restrict__ W, float* __restrict__ out, int nmat) {
    int gid = blockIdx.x * 256 + threadIdx.x;
    if (gid >= nmat * 65536) return;
    int m = gid >> 16, o = gid & 65535;
    int c = o >> 13, r = o & 8191;
    int kt = r >> 10, i4 = r & 1023;
    int ks = i4 >> 8, r2 = i4 & 255;
    int wN = r2 >> 6, r3 = r2 & 63;
    int nf2 = r3 >> 5, lane = r3 & 31;
    int t = lane & 3, g = lane >> 2;
    int k = kt * 32 + ks * 8 + t;
    int n = c * 128 + wN * 32 + nf2 * 16 + g;
    const float* Wm = W + (size_t)m * 262144;
    float4 v;
    v.x = f2tf32f(Wm[k * 1024 + n]);
    v.y = f2tf32f(Wm[(k + 4) * 1024 + n]);
    v.z = f2tf32f(Wm[k * 1024 + n + 8]);
    v.w = f2tf32f(Wm[(k + 4) * 1024 + n + 8]);
    ((float4*)out)[gid] = v;
}

// w_ff2 [1024, 256]: [c(8)][kt(4)][ks(4)][wN(4)][nf2(4)][lane] float4
__global__ void packff2_kernel(const float* __restrict__ W, float* __restrict__ out, int nmat) {
    int gid = blockIdx.x * 256 + threadIdx.x;
    if (gid >= nmat * 65536) return;
    int m = gid >> 16, o = gid & 65535;
    int c = o >> 13, r = o & 8191;
    int kt = r >> 11, i4 = r & 2047;
    int ks = i4 >> 9, r2 = i4 & 511;
    int wN = r2 >> 7, r3 = r2 & 127;
    int nf2 = r3 >> 5, lane = r3 & 31;
    int t = lane & 3, g = lane >> 2;
    int k = c * 128 + kt * 32 + ks * 8 + t;
    int n = wN * 64 + nf2 * 16 + g;
    const float* Wm = W + (size_t)m * 262144;
    float4 v;
    v.x = f2tf32f(Wm[k * 256 + n]);
    v.y = f2tf32f(Wm[(k + 4) * 256 + n]);
    v.z = f2tf32f(Wm[k * 256 + n + 8]);
    v.w = f2tf32f(Wm[(k + 4) * 256 + n + 8]);
    ((float4*)out)[gid] = v;
}

// ---------------- small kernels ----------------

__global__ void cvt_kernel(const float* __restrict__ in, float* __restrict__ out, int n4) {
    int i = blockIdx.x * 256 + threadIdx.x;
    if (i >= n4) return;
    float4 v = ((const float4*)in)[i];
    v.x = f2tf32f(v.x); v.y = f2tf32f(v.y); v.z = f2tf32f(v.z); v.w = f2tf32f(v.w);
    ((float4*)out)[i] = v;
}

__global__ void embed_kernel(const float* __restrict__ rel, const int* __restrict__ feat,
                             float* __restrict__ out) {
    int gid = blockIdx.x * blockDim.x + threadIdx.x;
    int e = gid >> 6;
    if (e >= NEDGE) return;
    int c = (gid & 63) << 2;
    int r = __ldg(feat + e);
    float4 v = *(const float4*)(rel + (size_t)r * H + c);
    v.x = f2tf32f(v.x); v.y = f2tf32f(v.y); v.z = f2tf32f(v.z); v.w = f2tf32f(v.w);
    *(float4*)(out + (size_t)e * H + c) = v;
}

__global__ void gather2_kernel(const float* __restrict__ x, const int* __restrict__ s,
                               const int* __restrict__ d, float* __restrict__ out, int n) {
    int gid = blockIdx.x * blockDim.x + threadIdx.x;
    int e = gid >> 6;
    if (e >= n) return;
    int c = (gid & 63) << 2;
    int si = __ldg(s + e), di = __ldg(d + e);
    float4 a = *(const float4*)(x + (size_t)si * H + c);
    float4 b = *(const float4*)(x + (size_t)di * H + c);
    a.x = f2tf32f(a.x + b.x); a.y = f2tf32f(a.y + b.y);
    a.z = f2tf32f(a.z + b.z); a.w = f2tf32f(a.w + b.w);
    *(float4*)(out + (size_t)e * H + c) = a;
}

// CSR gather segment-sum (2-way unrolled)
__global__ void segsum_kernel(const float* __restrict__ rows, const int* __restrict__ rp,
                              const int* __restrict__ ci, float* __restrict__ out, int nseg) {
    int row = blockIdx.x * 8 + (threadIdx.x >> 5);
    if (row >= nseg) return;
    int lane = threadIdx.x & 31;
    int beg = __ldg(rp + row), end = __ldg(rp + row + 1);
    float a[8] = {0.f, 0.f, 0.f, 0.f, 0.f, 0.f, 0.f, 0.f};
    float b[8] = {0.f, 0.f, 0.f, 0.f, 0.f, 0.f, 0.f, 0.f};
    int j = beg;
    for (; j + 1 < end; j += 2) {
        const float* p0 = rows + (size_t)__ldg(ci + j) * H + lane * 8;
        const float* p1 = rows + (size_t)__ldg(ci + j + 1) * H + lane * 8;
        float4 u0 = ((const float4*)p0)[0], u1 = ((const float4*)p0)[1];
        float4 w0 = ((const float4*)p1)[0], w1 = ((const float4*)p1)[1];
        a[0] += u0.x; a[1] += u0.y; a[2] += u0.z; a[3] += u0.w;
        a[4] += u1.x; a[5] += u1.y; a[6] += u1.z; a[7] += u1.w;
        b[0] += w0.x; b[1] += w0.y; b[2] += w0.z; b[3] += w0.w;
        b[4] += w1.x; b[5] += w1.y; b[6] += w1.z; b[7] += w1.w;
    }
    if (j < end) {
        const float* p0 = rows + (size_t)__ldg(ci + j) * H + lane * 8;
        float4 u0 = ((const float4*)p0)[0], u1 = ((const float4*)p0)[1];
        a[0] += u0.x; a[1] += u0.y; a[2] += u0.z; a[3] += u0.w;
        a[4] += u1.x; a[5] += u1.y; a[6] += u1.z; a[7] += u1.w;
    }
#pragma unroll
    for (int i = 0; i < 8; i++) a[i] = f2tf32f(a[i] + b[i]);
    float* po = out + (size_t)row * H + lane * 8;
    ((float4*)po)[0] = make_float4(a[0], a[1], a[2], a[3]);
    ((float4*)po)[1] = make_float4(a[4], a[5], a[6], a[7]);
}

// hop1 of layer-0 edge core: gather rel[feat[ci[j]]]
__global__ void segsum_rel_kernel(const float* __restrict__ rel, const int* __restrict__ feat,
                                  const int* __restrict__ rp, const int* __restrict__ ci,
                                  float* __restrict__ out, int nseg) {
    int row = blockIdx.x * 8 + (threadIdx.x >> 5);
    if (row >= nseg) return;
    int lane = threadIdx.x & 31;
    int beg = __ldg(rp + row), end = __ldg(rp + row + 1);
    float a[8] = {0.f, 0.f, 0.f, 0.f, 0.f, 0.f, 0.f, 0.f};
    for (int j = beg; j < end; j++) {
        int r = __ldg(feat + __ldg(ci + j));
        const float* p = rel + (size_t)r * H + lane * 8;
        float4 u0 = ((const float4*)p)[0], u1 = ((const float4*)p)[1];
        a[0] += f2tf32f(u0.x); a[1] += f2tf32f(u0.y);
        a[2] += f2tf32f(u0.z); a[3] += f2tf32f(u0.w);
        a[4] += f2tf32f(u1.x); a[5] += f2tf32f(u1.y);
        a[6] += f2tf32f(u1.z); a[7] += f2tf32f(u1.w);
    }
#pragma unroll
    for (int i = 0; i < 8; i++) a[i] = f2tf32f(a[i]);
    float* po = out + (size_t)row * H + lane * 8;
    ((float4*)po)[0] = make_float4(a[0], a[1], a[2], a[3]);
    ((float4*)po)[1] = make_float4(a[4], a[5], a[6], a[7]);
}

// ================= GEMM1 + LN1 fused, m32n64 warp tile =================
// out1 = tf32( LN( xres + gelu( sum_j A_j @ W_j + sum_j bias_j ) ) )
// BM=64, BN=256, 256 threads, warps: 2 along M (m32) x 4 along N (n64).

#define G_ASTR 36
#define G_AST (64 * G_ASTR)       // 2304
#define G_BST 8192
#define G1_SMEM_FLOATS (2 * G_AST + 2 * G_BST + 3 * 256 + 2 * 256)
#define G1_SMEM_BYTES (G1_SMEM_FLOATS * 4)

struct G1Args {
    const float* A[6];
    const float* W[6];       // packed
    const float* Bias[6];
    const float* xres;
    const float* gamma;
    const float* beta;
};

__global__ void __launch_bounds__(256, 2)
gemm1_ln_kernel(G1Args args, int M, float* __restrict__ out) {
    extern __shared__ float sm[];
    float* As = sm;
    float* Bs = sm + 2 * G_AST;
    float* bias_s = Bs + 2 * G_BST;
    float* gs = bias_s + 256;
    float* bt = gs + 256;
    float* lnS = bt + 256;
    float* lnQ = lnS + 256;
    float* xs = sm;                 // alias; reused after mainloop, stride 264

    int tid = threadIdx.x;
    int bm = blockIdx.x * 64;

    {
        float b = 0.f;
#pragma unroll
        for (int j = 0; j < 6; j++) b += __ldg(args.Bias[j] + tid);
        bias_s[tid] = b;
        gs[tid] = __ldg(args.gamma + tid);
        bt[tid] = __ldg(args.beta + tid);
    }

    uint32_t a_base = (uint32_t)__cvta_generic_to_shared(As);
    uint32_t b_base = (uint32_t)__cvta_generic_to_shared(Bs);

    int warp = tid >> 5, lane = tid & 31, g = lane >> 2, t = lane & 3;
    int wm = (warp >> 2) * 32;    // 2 warps along M, 32 rows each
    int wN = warp & 3;            // 4 warps along N, 64 cols each
    int wn = wN * 64;

    float acc[2][8][4];
#pragma unroll
    for (int mt = 0; mt < 2; mt++)
#pragma unroll
        for (int nf = 0; nf < 8; nf++)
#pragma unroll
            for (int i = 0; i < 4; i++) acc[mt][nf][i] = 0.f;

    auto issue = [&](int tt, int buf) {
        int j = tt >> 3;
        int kk = (tt & 7) * 32;
        const float* A = args.A[j];
        const float4* Wp = (const float4*)args.W[j] + (size_t)(tt & 7) * 2048;
#pragma unroll
        for (int i = 0; i < 2; i++) {
            int idx = tid + i * 256;
            int r = idx >> 3, kv = (idx & 7) << 2;
            int row = bm + r;
            uint32_t dst = a_base + (uint32_t)((buf * G_AST + r * G_ASTR + kv) * 4);
            const float* src = A + (size_t)row * H + kk + kv;
            int sz = (row < M) ? 16 : 0;
            asm volatile("cp.async.cg.shared.global [%0], [%1], 16, %2;\n"
                         :: "r"(dst), "l"(src), "r"(sz));
        }
#pragma unroll
        for (int i = 0; i < 8; i++) {
            int idx = tid + i * 256;
            uint32_t dst = b_base + (uint32_t)((buf * G_BST + idx * 4) * 4);
            asm volatile("cp.async.cg.shared.global [%0], [%1], 16;\n"
                         :: "r"(dst), "l"(Wp + idx));
        }
        asm volatile("cp.async.commit_group;\n");
    };

    issue(0, 0);
    for (int tt = 0; tt < 48; tt++) {
        if (tt + 1 < 48) {
            issue(tt + 1, (tt + 1) & 1);
            asm volatile("cp.async.wait_group 1;\n");
        } else {
            asm volatile("cp.async.wait_group 0;\n");
        }
        __syncthreads();
        const float* Ab = As + (tt & 1) * G_AST;
        const float4* Bb4 = (const float4*)(Bs + (tt & 1) * G_BST) + wN * 128 + lane;
#pragma unroll
        for (int ks = 0; ks < 4; ks++) {
            int k0 = ks * 8;
            uint32_t a0[4], a1[4];
            a0[0] = __float_as_uint(Ab[(wm + g) * G_ASTR + k0 + t]);
            a0[1] = __float_as_uint(Ab[(wm + 8 + g) * G_ASTR + k0 + t]);
            a0[2] = __float_as_uint(Ab[(wm + g) * G_ASTR + k0 + t + 4]);
            a0[3] = __float_as_uint(Ab[(wm + 8 + g) * G_ASTR + k0 + t + 4]);
            a1[0] = __float_as_uint(Ab[(wm + 16 + g) * G_ASTR + k0 + t]);
            a1[1] = __float_as_uint(Ab[(wm + 24 + g) * G_ASTR + k0 + t]);
            a1[2] = __float_as_uint(Ab[(wm + 16 + g) * G_ASTR + k0 + t + 4]);
            a1[3] = __float_as_uint(Ab[(wm + 24 + g) * G_ASTR + k0 + t + 4]);
#pragma unroll
            for (int nf2 = 0; nf2 < 4; nf2++) {
                float4 bv = Bb4[ks * 512 + nf2 * 32];
                uint32_t b0[2] = {__float_as_uint(bv.x), __float_as_uint(bv.y)};
                mma_tf32(acc[0][2 * nf2], a0, b0);
                mma_tf32(acc[1][2 * nf2], a1, b0);
                uint32_t b1[2] = {__float_as_uint(bv.z), __float_as_uint(bv.w)};
                mma_tf32(acc[0][2 * nf2 + 1], a0, b1);
                mma_tf32(acc[1][2 * nf2 + 1], a1, b1);
            }
        }
        __syncthreads();
    }

    // cooperative residual tile load into xs (stride 264)
#pragma unroll
    for (int i = 0; i < 16; i++) {
        int idx = tid + i * 256;
        int r = idx >> 6, cv = (idx & 63) << 2;
        int row = bm + r;
        float4 v = make_float4(0.f, 0.f, 0.f, 0.f);
        if (row < M) v = *(const float4*)(args.xres + (size_t)row * H + cv);
        *(float4*)(xs + r * 264 + cv) = v;
    }
    __syncthreads();

    // bias+gelu+residual, per-row partial sums
#pragma unroll
    for (int mt = 0; mt < 2; mt++) {
#pragma unroll
        for (int h = 0; h < 2; h++) {
            int row = wm + mt * 16 + h * 8 + g;
            float s = 0.f, q = 0.f;
#pragma unroll
            for (int nf = 0; nf < 8; nf++) {
                int col = wn + nf * 8 + 2 * t;
                float v0 = xs[row * 264 + col]     + gelu_exact(acc[mt][nf][2 * h]     + bias_s[col]);
                float v1 = xs[row * 264 + col + 1] + gelu_exact(acc[mt][nf][2 * h + 1] + bias_s[col + 1]);
                acc[mt][nf][2 * h] = v0; acc[mt][nf][2 * h + 1] = v1;
                s += v0 + v1; q += v0 * v0 + v1 * v1;
            }
#pragma unroll
            for (int o = 1; o <= 2; o <<= 1) {
                s += __shfl_xor_sync(0xffffffffu, s, o);
                q += __shfl_xor_sync(0xffffffffu, q, o);
            }
            if (t == 0) { lnS[row * 4 + wN] = s; lnQ[row * 4 + wN] = q; }
        }
    }
    __syncthreads();
#pragma unroll
    for (int mt = 0; mt < 2; mt++) {
#pragma unroll
        for (int h = 0; h < 2; h++) {
            int row = wm + mt * 16 + h * 8 + g;
            float S = lnS[row * 4] + lnS[row * 4 + 1] + lnS[row * 4 + 2] + lnS[row * 4 + 3];
            float Q = lnQ[row * 4] + lnQ[row * 4 + 1] + lnQ[row * 4 + 2] + lnQ[row * 4 + 3];
            float m = S * (1.f / H), v = Q * (1.f / H) - m * m, rs = rsqrtf(v + 1e-5f);
            if (bm + row < M) {
#pragma unroll
                for (int nf = 0; nf < 8; nf++) {
                    int col = wn + nf * 8 + 2 * t;
                    float o0 = f2tf32f((acc[mt][nf][2 * h]     - m) * rs * gs[col]     + bt[col]);
                    float o1 = f2tf32f((acc[mt][nf][2 * h + 1] - m) * rs * gs[col + 1] + bt[col + 1]);
                    *(float2*)(out + (size_t)(bm + row) * H + col) = make_float2(o0, o1);
                }
            }
        }
    }
}

// ================= fused FFN + LN2 =================
#define F_XSTR 260
#define F_HSTR 132
#define F_B1ST 4096
#define F_B2ST 8192
#define F_SMEM_FLOATS (64 * F_XSTR + 64 * F_HSTR + 2 * F_B2ST + 3 * 256 + 128 + 2 * 256)
#define F_SMEM_BYTES (F_SMEM_FLOATS * 4)

struct FArgs {
    const float* w1;    // packed
    const float* b1;
    const float* w2;    // packed
    const float* b2;
    const float* gamma;
    const float* beta;
};

__global__ void __launch_bounds__(512, 1)
ffn_kernel(FArgs args, int M, const float* __restrict__ in1,
           float* __restrict__ out, int out_cvt) {
    extern __shared__ float sm[];
    float* xs  = sm;
    float* hb  = xs + 64 * F_XSTR;
    float* Bst = hb + 64 * F_HSTR;
    float* b2s = Bst + 2 * F_B2ST;
    float* gs  = b2s + 256;
    float* bt  = gs + 256;
    float* b1c = bt + 256;
    float* lnS = b1c + 128;
    float* lnQ = lnS + 256;

    int tid = threadIdx.x;
    int bm = blockIdx.x * 64;

    if (tid < 256) {
        b2s[tid] = __ldg(args.b2 + tid);
        gs[tid]  = __ldg(args.gamma + tid);
        bt[tid]  = __ldg(args.beta + tid);
    }
#pragma unroll
    for (int i = 0; i < 8; i++) {
        int idx = tid + i * 512;
        int r = idx >> 6, cv = (idx & 63) << 2;
        int row = bm + r;
        float4 v = make_float4(0.f, 0.f, 0.f, 0.f);
        if (row < M) v = *(const float4*)(in1 + (size_t)row * H + cv);
        *(float4*)(xs + r * F_XSTR + cv) = v;
    }

    uint32_t bst_base = (uint32_t)__cvta_generic_to_shared(Bst);
    int warp = tid >> 5, lane = tid & 31, g = lane >> 2, t = lane & 3;
    int wm = (warp >> 2) * 16;
    int wN = warp & 3;
    int wn1 = wN * 32;
    int wn2 = wN * 64;

    float acc2[8][4];
#pragma unroll
    for (int nf = 0; nf < 8; nf++)
#pragma unroll
        for (int i = 0; i < 4; i++) acc2[nf][i] = 0.f;

    __syncthreads();

    for (int c = 0; c < 8; c++) {
        if (tid < 128) b1c[tid] = __ldg(args.b1 + c * 128 + tid);

        float acc1[4][4];
#pragma unroll
        for (int nf = 0; nf < 4; nf++)
#pragma unroll
            for (int i = 0; i < 4; i++) acc1[nf][i] = 0.f;

        const float4* W1p = (const float4*)args.w1 + (size_t)c * 8192;
        auto issue1 = [&](int kt, int buf) {
#pragma unroll
            for (int i = 0; i < 2; i++) {
                int idx = tid + i * 512;
                uint32_t dst = bst_base + (uint32_t)((buf * F_B1ST + idx * 4) * 4);
                asm volatile("cp.async.cg.shared.global [%0], [%1], 16;\n"
                             :: "r"(dst), "l"(W1p + kt * 1024 + idx));
            }
            asm volatile("cp.async.commit_group;\n");
        };

        issue1(0, 0);
        for (int kt = 0; kt < 8; kt++) {
            if (kt + 1 < 8) {
                issue1(kt + 1, (kt + 1) & 1);
                asm volatile("cp.async.wait_group 1;\n");
            } else {
                asm volatile("cp.async.wait_group 0;\n");
            }
            __syncthreads();
            const float4* Bb4 = (const float4*)(Bst + (kt & 1) * F_B1ST) + wN * 64 + lane;
            int kk = kt * 32;
#pragma unroll
            for (int ks = 0; ks < 4; ks++) {
                int kg = kk + ks * 8;
                uint32_t a[4];
                a[0] = __float_as_uint(xs[(wm + g) * F_XSTR + kg + t]);
                a[1] = __float_as_uint(xs[(wm + 8 + g) * F_XSTR + kg + t]);
                a[2] = __float_as_uint(xs[(wm + g) * F_XSTR + kg + t + 4]);
                a[3] = __float_as_uint(xs[(wm + 8 + g) * F_XSTR + kg + t + 4]);
#pragma unroll
                for (int nf2 = 0; nf2 < 2; nf2++) {
                    float4 bv = Bb4[ks * 256 + nf2 * 32];
                    uint32_t b0[2] = {__float_as_uint(bv.x), __float_as_uint(bv.y)};
                    mma_tf32(acc1[2 * nf2], a, b0);
                    uint32_t b1[2] = {__float_as_uint(bv.z), __float_as_uint(bv.w)};
                    mma_tf32(acc1[2 * nf2 + 1], a, b1);
                }
            }
            __syncthreads();
        }

#pragma unroll
        for (int nf = 0; nf < 4; nf++) {
            int col = wn1 + nf * 8 + 2 * t;
            float h0 = f2tf32f(gelu_exact(acc1[nf][0] + b1c[col]));
            float h1 = f2tf32f(gelu_exact(acc1[nf][1] + b1c[col + 1]));
            float h2 = f2tf32f(gelu_exact(acc1[nf][2] + b1c[col]));
            float h3 = f2tf32f(gelu_exact(acc1[nf][3] + b1c[col + 1]));
            *(float2*)(hb + (wm + g) * F_HSTR + col)     = make_float2(h0, h1);
            *(float2*)(hb + (wm + 8 + g) * F_HSTR + col) = make_float2(h2, h3);
        }
        __syncthreads();

        const float4* W2p = (const float4*)args.w2 + (size_t)c * 8192;
        auto issue2 = [&](int kt, int buf) {
#pragma unroll
            for (int i = 0; i < 4; i++) {
                int idx = tid + i * 512;
                uint32_t dst = bst_base + (uint32_t)((buf * F_B2ST + idx * 4) * 4);
                asm volatile("cp.async.cg.shared.global [%0], [%1], 16;\n"
                             :: "r"(dst), "l"(W2p + kt * 2048 + idx));
            }
            asm volatile("cp.async.commit_group;\n");
        };

        issue2(0, 0);
        for (int kt = 0; kt < 4; kt++) {
            if (kt + 1 < 4) {
                issue2(kt + 1, (kt + 1) & 1);
                asm volatile("cp.async.wait_group 1;\n");
            } else {
                asm volatile("cp.async.wait_group 0;\n");
            }
            __syncthreads();
            const float4* Bb4 = (const float4*)(Bst + (kt & 1) * F_B2ST) + wN * 128 + lane;
            int kk = kt * 32;
#pragma unroll
            for (int ks = 0; ks < 4; ks++) {
                int kg = kk + ks * 8;
                uint32_t a[4];
                a[0] = __float_as_uint(hb[(wm + g) * F_HSTR + kg + t]);
                a[1] = __float_as_uint(hb[(wm + 8 + g) * F_HSTR + kg + t]);
                a[2] = __float_as_uint(hb[(wm + g) * F_HSTR + kg + t + 4]);
                a[3] = __float_as_uint(hb[(wm + 8 + g) * F_HSTR + kg + t + 4]);
#pragma unroll
                for (int nf2 = 0; nf2 < 4; nf2++) {
                    float4 bv = Bb4[ks * 512 + nf2 * 32];
                    uint32_t b0[2] = {__float_as_uint(bv.x), __float_as_uint(bv.y)};
                    mma_tf32(acc2[2 * nf2], a, b0);
                    uint32_t b1[2] = {__float_as_uint(bv.z), __float_as_uint(bv.w)};
                    mma_tf32(acc2[2 * nf2 + 1], a, b1);
                }
            }
            __syncthreads();
        }
    }

    // LN2 epilogue
    int row0 = wm + g, row1 = wm + 8 + g;
    float s0 = 0.f, q0 = 0.f, s1 = 0.f, q1 = 0.f;
#pragma unroll
    for (int nf = 0; nf < 8; nf++) {
        int col = wn2 + nf * 8 + 2 * t;
        float t0 = xs[row0 * F_XSTR + col]     + acc2[nf][0] + b2s[col];
        float t1 = xs[row0 * F_XSTR + col + 1] + acc2[nf][1] + b2s[col + 1];
        float t2 = xs[row1 * F_XSTR + col]     + acc2[nf][2] + b2s[col];
        float t3 = xs[row1 * F_XSTR + col + 1] + acc2[nf][3] + b2s[col + 1];
        acc2[nf][0] = t0; acc2[nf][1] = t1; acc2[nf][2] = t2; acc2[nf][3] = t3;
        s0 += t0 + t1; q0 += t0 * t0 + t1 * t1;
        s1 += t2 + t3; q1 += t2 * t2 + t3 * t3;
    }
#pragma unroll
    for (int o = 1; o <= 2; o <<= 1) {
        s0 += __shfl_xor_sync(0xffffffffu, s0, o);
        q0 += __shfl_xor_sync(0xffffffffu, q0, o);
        s1 += __shfl_xor_sync(0xffffffffu, s1, o);
        q1 += __shfl_xor_sync(0xffffffffu, q1, o);
    }
    if (t == 0) {
        lnS[row0 * 4 + wN] = s0; lnQ[row0 * 4 + wN] = q0;
        lnS[row1 * 4 + wN] = s1; lnQ[row1 * 4 + wN] = q1;
    }
    __syncthreads();
    float S0 = lnS[row0 * 4] + lnS[row0 * 4 + 1] + lnS[row0 * 4 + 2] + lnS[row0 * 4 + 3];
    float Q0 = lnQ[row0 * 4] + lnQ[row0 * 4 + 1] + lnQ[row0 * 4 + 2] + lnQ[row0 * 4 + 3];
    float S1 = lnS[row1 * 4] + lnS[row1 * 4 + 1] + lnS[row1 * 4 + 2] + lnS[row1 * 4 + 3];
    float Q1 = lnQ[row1 * 4] + lnQ[row1 * 4 + 1] + lnQ[row1 * 4 + 2] + lnQ[row1 * 4 + 3];
    float m0 = S0 * (1.f / H), v0 = Q0 * (1.f / H) - m0 * m0, r0 = rsqrtf(v0 + 1e-5f);
    float m1 = S1 * (1.f / H), v1 = Q1 * (1.f / H) - m1 * m1, r1 = rsqrtf(v1 + 1e-5f);
    bool ok0 = (bm + row0) < M, ok1 = (bm + row1) < M;
#pragma unroll
    for (int nf = 0; nf < 8; nf++) {
        int col = wn2 + nf * 8 + 2 * t;
        float o0 = (acc2[nf][0] - m0) * r0 * gs[col]     + bt[col];
        float o1 = (acc2[nf][1] - m0) * r0 * gs[col + 1] + bt[col + 1];
        float o2 = (acc2[nf][2] - m1) * r1 * gs[col]     + bt[col];
        float o3 = (acc2[nf][3] - m1) * r1 * gs[col + 1] + bt[col + 1];
        if (out_cvt) {
            o0 = f2tf32f(o0); o1 = f2tf32f(o1);
            o2 = f2tf32f(o2); o3 = f2tf32f(o3);
        }
        if (ok0) *(float2*)(out + (size_t)(bm + row0) * H + col) = make_float2(o0, o1);
        if (ok1) *(float2*)(out + (size_t)(bm + row1) * H + col) = make_float2(o2, o3);
    }
}

// ---------------- host orchestration ----------------

struct Net {
    const float *b_self, *b_khop, *b_fuse, *b_ff1, *b_ff2;
    const float *ln1g, *ln1b, *ln2g, *ln2b;
    float* wbuf;
};

static void run_core(const Net& n, int l, int c, int M, float* const* z,
                     const float* xin, const float* fused, float* out1buf,
                     float* outp, int cvt_final, cudaStream_t st) {
    size_t lc = (size_t)(l * 2 + c);
    G1Args ga;
    ga.A[0] = xin;
    ga.W[0] = n.wbuf + OFF_WSELF + lc * H * H;
    ga.Bias[0] = n.b_self + lc * H;
    for (int i = 0; i < 4; i++) {
        ga.A[1 + i] = z[i];
        ga.W[1 + i] = n.wbuf + OFF_WKHOP + (lc * 4 + i) * (size_t)H * H;
        ga.Bias[1 + i] = n.b_khop + (lc * 4 + i) * (size_t)H;
    }
    ga.A[5] = fused;
    ga.W[5] = n.wbuf + OFF_WFUSE + lc * H * H;
    ga.Bias[5] = n.b_fuse + lc * H;
    ga.xres = xin;
    ga.gamma = n.ln1g + lc * H;
    ga.beta  = n.ln1b + lc * H;

    int grid = (M + 63) / 64;
    gemm1_ln_kernel<<<grid, 256, G1_SMEM_BYTES, st>>>(ga, M, out1buf);

    FArgs fa;
    fa.w1 = n.wbuf + OFF_WFF1 + lc * (size_t)H * FH;
    fa.b1 = n.b_ff1 + lc * FH;
    fa.w2 = n.wbuf + OFF_WFF2 + lc * (size_t)FH * H;
    fa.b2 = n.b_ff2 + lc * H;
    fa.gamma = n.ln2g + lc * H;
    fa.beta  = n.ln2b + lc * H;
    ffn_kernel<<<grid, 512, F_SMEM_BYTES, st>>>(fa, M, out1buf, outp, cvt_final);
}

static void exclusive_scan(int* cnt, int* rp, int* bsums, int n) {
    int nb = (n + 1023) / 1024;
    scan1_kernel<<<nb, 1024>>>(cnt, rp, bsums, n);
    scan2_kernel<<<1, 1024>>>(bsums, nb);
    scan3_kernel<<<nb, 1024>>>(rp, bsums, cnt, n);
}

extern "C" void kernel_launch(void* const* d_in, const int* in_sizes, int n_in,
                              void* d_out, int out_size) {
    const float* x_in = (const float*)d_in[0];
    const int* feat   = (const int*)d_in[1];
    const int* eig    = (const int*)d_in[2];
    const int* eil    = (const int*)d_in[3];
    const float* rel  = (const float*)d_in[4];

    const float* w_self = (const float*)d_in[5];
    const float* w_khop = (const float*)d_in[7];
    const float* w_fuse = (const float*)d_in[9];
    const float* w_ff1  = (const float*)d_in[11];
    const float* w_ff2  = (const float*)d_in[13];

    Net n;
    n.b_self = (const float*)d_in[6];
    n.b_khop = (const float*)d_in[8];
    n.b_fuse = (const float*)d_in[10];
    n.b_ff1  = (const float*)d_in[12];
    n.b_ff2  = (const float*)d_in[14];
    n.ln1g   = (const float*)d_in[15]; n.ln1b = (const float*)d_in[16];
    n.ln2g   = (const float*)d_in[17]; n.ln2b = (const float*)d_in[18];

    cudaFuncSetAttribute(gemm1_ln_kernel,
                         cudaFuncAttributeMaxDynamicSharedMemorySize, G1_SMEM_BYTES);
    cudaFuncSetAttribute(ffn_kernel,
                         cudaFuncAttributeMaxDynamicSharedMemorySize, F_SMEM_BYTES);

    // side stream + events (created once, outside capture on the first call)
    static cudaStream_t s2 = nullptr;
    static cudaEvent_t ev_init, ev_x0, ev_lg0, ev_fin;
    if (!s2) {
        cudaStreamCreateWithFlags(&s2, cudaStreamNonBlocking);
        cudaEventCreateWithFlags(&ev_init, cudaEventDisableTiming);
        cudaEventCreateWithFlags(&ev_x0,   cudaEventDisableTiming);
        cudaEventCreateWithFlags(&ev_lg0,  cudaEventDisableTiming);
        cudaEventCreateWithFlags(&ev_fin,  cudaEventDisableTiming);
    }

    float *px0, *plg0, *pfn, *pfe, *pzbase, *pznb, *pout1, *pout1n, *pwbuf;
    int *rp_nd, *ci_nd, *rp_fn, *ci_fn, *rp_lg, *ci_lg, *pcnt, *pcur, *pbs;
    cudaGetSymbolAddress((void**)&px0,   g_x);
    cudaGetSymbolAddress((void**)&plg0,  g_lg);
    cudaGetSymbolAddress((void**)&pfn,   g_fn);
    cudaGetSymbolAddress((void**)&pfe,   g_fe);
    cudaGetSymbolAddress((void**)&pzbase,g_z);
    cudaGetSymbolAddress((void**)&pznb,  g_zn);
    cudaGetSymbolAddress((void**)&pout1, g_out1);
    cudaGetSymbolAddress((void**)&pout1n,g_out1n);
    cudaGetSymbolAddress((void**)&pwbuf, g_wbuf);
    cudaGetSymbolAddress((void**)&rp_nd, g_rp_nd);
    cudaGetSymbolAddress((void**)&ci_nd, g_ci_nd);
    cudaGetSymbolAddress((void**)&rp_fn, g_rp_fn);
    cudaGetSymbolAddress((void**)&ci_fn, g_ci_fn);
    cudaGetSymbolAddress((void**)&rp_lg, g_rp_lg);
    cudaGetSymbolAddress((void**)&ci_lg, g_ci_lg);
    cudaGetSymbolAddress((void**)&pcnt,  g_cnt);
    cudaGetSymbolAddress((void**)&pcur,  g_cur);
    cudaGetSymbolAddress((void**)&pbs,   g_bs);

    n.wbuf = pwbuf;
    float* px[2]  = {px0,  px0  + (size_t)NNODE * H};
    float* plg[2] = {plg0, plg0 + (size_t)NEDGE * H};
    float* ze[4], * zn[4];
    for (int i = 0; i < 4; i++) {
        ze[i] = pzbase + (size_t)i * NEDGE * H;
        zn[i] = pznb + (size_t)i * NNODE * H;
    }

    const int* src_g = eig;  const int* dst_g = eig + NEDGE;
    const int* src_l = eil;  const int* dst_l = eil + NLG;

    // ===== stream 0: lg CSR + layer-0 edge khops + packs + init + node CSRs =====
    cudaMemsetAsync(pcnt, 0, NEDGE * sizeof(int), 0);
    hist_kernel<<<(NLG + 255) / 256, 256>>>(dst_l, pcnt, NLG);
    exclusive_scan(pcnt, rp_lg, pbs, NEDGE);
    cudaMemcpyAsync(pcur, rp_lg, NEDGE * sizeof(int), cudaMemcpyDeviceToDevice, 0);
    fill_kernel<<<(NLG + 255) / 256, 256>>>(dst_l, src_l, pcur, ci_lg, NLG);

    segsum_rel_kernel<<<(NEDGE + 7) / 8, 256>>>(rel, feat, rp_lg, ci_lg, ze[0], NEDGE);
    segsum_kernel<<<(NEDGE + 7) / 8, 256>>>(ze[0], rp_lg, ci_lg, ze[1], NEDGE);
    segsum_kernel<<<(NEDGE + 7) / 8, 256>>>(ze[1], rp_lg, ci_lg, ze[2], NEDGE);
    segsum_kernel<<<(NEDGE + 7) / 8, 256>>>(ze[2], rp_lg, ci_lg, ze[3], NEDGE);

    pack256_kernel<<<(4 * 16384 + 255) / 256, 256>>>(w_self, pwbuf + OFF_WSELF, 4);
    pack256_kernel<<<(16 * 16384 + 255) / 256, 256>>>(w_khop, pwbuf + OFF_WKHOP, 16);
    pack256_kernel<<<(4 * 16384 + 255) / 256, 256>>>(w_fuse, pwbuf + OFF_WFUSE, 4);
    packff1_kernel<<<(4 * 65536 + 255) / 256, 256>>>(w_ff1, pwbuf + OFF_WFF1, 4);
    packff2_kernel<<<(4 * 65536 + 255) / 256, 256>>>(w_ff2, pwbuf + OFF_WFF2, 4);

    cvt_kernel<<<(NNODE * H / 4 + 255) / 256, 256>>>(x_in, px[0], NNODE * H / 4);
    embed_kernel<<<NEDGE * 64 / 256, 256>>>(rel, feat, plg[0]);

    cudaMemsetAsync(pcnt, 0, NNODE * sizeof(int), 0);
    hist_kernel<<<(NEDGE + 255) / 256, 256>>>(dst_g, pcnt, NEDGE);
    exclusive_scan(pcnt, rp_nd, pbs, NNODE);
    cudaMemcpyAsync(pcur, rp_nd, NNODE * sizeof(int), cudaMemcpyDeviceToDevice, 0);
    fill_kernel<<<(NEDGE + 255) / 256, 256>>>(dst_g, src_g, pcur, ci_nd, NEDGE);

    cudaMemsetAsync(pcnt, 0, NNODE * sizeof(int), 0);
    hist_kernel<<<(NEDGE + 255) / 256, 256>>>(src_g, pcnt, NEDGE);
    hist_kernel<<<(NEDGE + 255) / 256, 256>>>(dst_g, pcnt, NEDGE);
    exclusive_scan(pcnt, rp_fn, pbs, NNODE);
    cudaMemcpyAsync(pcur, rp_fn, NNODE * sizeof(int), cudaMemcpyDeviceToDevice, 0);
    fill_kernel<<<(NEDGE + 255) / 256, 256>>>(src_g, nullptr, pcur, ci_fn, NEDGE);
    fill_kernel<<<(NEDGE + 255) / 256, 256>>>(dst_g, nullptr, pcur, ci_fn, NEDGE);

    cudaEventRecord(ev_init, 0);

    // ===== stream s2: node core, layer 0 =====
    cudaStreamWaitEvent(s2, ev_init, 0);
    segsum_kernel<<<(NNODE + 7) / 8, 256, 0, s2>>>(plg[0], rp_fn, ci_fn, pfn, NNODE);
    {
        const float* prev = px[0];
        for (int i = 0; i < 4; i++) {
            segsum_kernel<<<(NNODE + 7) / 8, 256, 0, s2>>>(prev, rp_nd, ci_nd, zn[i], NNODE);
            prev = zn[i];
        }
    }
    run_core(n, 0, 0, NNODE, zn, px[0], pfn, pout1n, px[1], 1, s2);
    cudaEventRecord(ev_x0, s2);

    // ===== stream 0: edge core, layer 0 =====
    gather2_kernel<<<NEDGE * 64 / 256, 256>>>(px[0], src_g, dst_g, pfe, NEDGE);
    run_core(n, 0, 1, NEDGE, ze, plg[0], pfe, pout1, plg[1], 1, (cudaStream_t)0);
    cudaEventRecord(ev_lg0, 0);

    // ===== stream s2: node core, layer 1 =====
    cudaStreamWaitEvent(s2, ev_lg0, 0);
    segsum_kernel<<<(NNODE + 7) / 8, 256, 0, s2>>>(plg[1], rp_fn, ci_fn, pfn, NNODE);
    {
        const float* prev = px[1];
        for (int i = 0; i < 4; i++) {
            segsum_kernel<<<(NNODE + 7) / 8, 256, 0, s2>>>(prev, rp_nd, ci_nd, zn[i], NNODE);
            prev = zn[i];
        }
    }
    run_core(n, 1, 0, NNODE, zn, px[1], pfn, pout1n, (float*)d_out, 0, s2);
    cudaEventRecord(ev_fin, s2);

    // ===== stream 0: edge core, layer 1 =====
    cudaStreamWaitEvent(0, ev_x0, 0);
    gather2_kernel<<<NEDGE * 64 / 256, 256>>>(px[1], src_g, dst_g, pfe, NEDGE);
    {
        const float* prev = plg[1];
        for (int i = 0; i < 4; i++) {
            segsum_kernel<<<(NEDGE + 7) / 8, 256>>>(prev, rp_lg, ci_lg, ze[i], NEDGE);
            prev = ze[i];
        }
    }
    run_core(n, 1, 1, NEDGE, ze, plg[1], pfe, pout1,
             (float*)d_out + (size_t)NNODE * H, 0, (cudaStream_t)0);

    cudaStreamWaitEvent(0, ev_fin, 0);
    (void)in_sizes; (void)n_in; (void)out_size;
}

// round 9
// speedup vs baseline: 1.0027x; 1.0027x over previous
#include <cuda_runtime.h>
#include <cstdint>
#include <math.h>

#define H       256
#define FH      1024
#define NNODE   20000
#define NEDGE   160000
#define NLG     640000

// ---------------- scratch (static device memory; no allocations) ----------------
__device__ float g_x[2][(size_t)NNODE * H];
__device__ float g_lg[2][(size_t)NEDGE * H];
__device__ float g_fn[(size_t)NNODE * H];
__device__ float g_fe[(size_t)NEDGE * H];
__device__ float g_z[4][(size_t)NEDGE * H];    // edge-core khop scratch
__device__ float g_zn[4][(size_t)NNODE * H];   // node-core khop scratch
__device__ float g_out1[(size_t)NEDGE * H];    // edge-core out1
__device__ float g_out1n[(size_t)NNODE * H];   // node-core out1 (stream overlap)

// packed (tf32-rounded, fragment-order) weights
#define OFF_WSELF 0
#define OFF_WKHOP (OFF_WSELF + 4 * H * H)
#define OFF_WFUSE (OFF_WKHOP + 16 * H * H)
#define OFF_WFF1  (OFF_WFUSE + 4 * H * H)
#define OFF_WFF2  (OFF_WFF1 + 4 * H * FH)
#define WBUF_TOT  (OFF_WFF2 + 4 * FH * H)
__device__ float g_wbuf[WBUF_TOT];

// CSR structures
__device__ int g_rp_nd[NNODE + 1];
__device__ int g_ci_nd[NEDGE];
__device__ int g_rp_fn[NNODE + 1];
__device__ int g_ci_fn[2 * NEDGE];
__device__ int g_rp_lg[NEDGE + 1];
__device__ int g_ci_lg[NLG];
__device__ int g_cnt[NEDGE];
__device__ int g_cur[NEDGE];
__device__ int g_bs[1024];

__device__ __forceinline__ float gelu_exact(float v) {
    return 0.5f * v * (1.0f + erff(v * 0.70710678118654752f));
}

__device__ __forceinline__ float f2tf32f(float f) {
    uint32_t r;
    asm("cvt.rna.tf32.f32 %0, %1;" : "=r"(r) : "f"(f));
    return __uint_as_float(r);
}

__device__ __forceinline__ void mma_tf32(float* c, const uint32_t* a, const uint32_t* b) {
    asm volatile(
        "mma.sync.aligned.m16n8k8.row.col.f32.tf32.tf32.f32 "
        "{%0,%1,%2,%3}, {%4,%5,%6,%7}, {%8,%9}, {%0,%1,%2,%3};"
        : "+f"(c[0]), "+f"(c[1]), "+f"(c[2]), "+f"(c[3])
        : "r"(a[0]), "r"(a[1]), "r"(a[2]), "r"(a[3]), "r"(b[0]), "r"(b[1]));
}

// ---------------- CSR build kernels ----------------

__global__ void hist_kernel(const int* __restrict__ key, int* cnt, int n) {
    int i = blockIdx.x * 256 + threadIdx.x;
    if (i < n) atomicAdd(&cnt[__ldg(key + i)], 1);
}

__global__ void scan1_kernel(const int* __restrict__ in, int* __restrict__ out,
                             int* __restrict__ bsums, int n) {
    __shared__ int sh[1024];
    int i = blockIdx.x * 1024 + threadIdx.x;
    int v = (i < n) ? in[i] : 0;
    sh[threadIdx.x] = v;
    __syncthreads();
#pragma unroll
    for (int o = 1; o < 1024; o <<= 1) {
        int t = (threadIdx.x >= o) ? sh[threadIdx.x - o] : 0;
        __syncthreads();
        sh[threadIdx.x] += t;
        __syncthreads();
    }
    if (i < n) out[i] = sh[threadIdx.x] - v;     // exclusive
    if (threadIdx.x == 1023) bsums[blockIdx.x] = sh[1023];
}

__global__ void scan2_kernel(int* bsums, int nb) {
    __shared__ int sh[1024];
    int v = (threadIdx.x < nb) ? bsums[threadIdx.x] : 0;
    sh[threadIdx.x] = v;
    __syncthreads();
#pragma unroll
    for (int o = 1; o < 1024; o <<= 1) {
        int t = (threadIdx.x >= o) ? sh[threadIdx.x - o] : 0;
        __syncthreads();
        sh[threadIdx.x] += t;
        __syncthreads();
    }
    if (threadIdx.x < nb) bsums[threadIdx.x] = sh[threadIdx.x] - v;  // exclusive
}

__global__ void scan3_kernel(int* __restrict__ out, const int* __restrict__ bsums,
                             const int* __restrict__ cnt, int n) {
    int i = blockIdx.x * 1024 + threadIdx.x;
    if (i < n) {
        int v = out[i] + bsums[i >> 10];
        out[i] = v;
        if (i == n - 1) out[n] = v + cnt[i];
    }
}

__global__ void fill_kernel(const int* __restrict__ key, const int* __restrict__ val,
                            int* cursor, int* __restrict__ ci, int n) {
    int i = blockIdx.x * 256 + threadIdx.x;
    if (i >= n) return;
    int pos = atomicAdd(&cursor[__ldg(key + i)], 1);
    ci[pos] = val ? __ldg(val + i) : i;
}

// ---------------- weight pack kernels (tf32 round + fragment permutation) ----------------
// float4 = { W[k][n], W[k+4][n], W[k][n+8], W[k+4][n+8] }, k = kt*32+ks*8+t

// H x H (gemm1 weights), m32n64 warp tile: [kt(8)][ks(4)][wN(4)][nf2(4)][lane(32)]
__global__ void pack256_kernel(const float* __restrict__ W, float* __restrict__ out, int nmat) {
    int gid = blockIdx.x * 256 + threadIdx.x;
    if (gid >= nmat * 16384) return;
    int m = gid >> 14, o = gid & 16383;
    int kt = o >> 11, i4 = o & 2047;
    int ks = i4 >> 9, r = i4 & 511;
    int wN = r >> 7, r2 = r & 127;
    int nf2 = r2 >> 5, lane = r2 & 31;
    int t = lane & 3, g = lane >> 2;
    int k = kt * 32 + ks * 8 + t;
    int n = wN * 64 + nf2 * 16 + g;
    const float* Wm = W + (size_t)m * 65536;
    float4 v;
    v.x = f2tf32f(Wm[k * 256 + n]);
    v.y = f2tf32f(Wm[(k + 4) * 256 + n]);
    v.z = f2tf32f(Wm[k * 256 + n + 8]);
    v.w = f2tf32f(Wm[(k + 4) * 256 + n + 8]);
    ((float4*)out)[gid] = v;
}

// w_ff1 [256, 1024]: [c(8)][kt(8)][ks(4)][wN(4)][nf2(2)][lane] float4
__global__ void packff1_kernel(const float* __restrict__ W, float* __restrict__ out, int nmat) {
    int gid = blockIdx.x * 256 + threadIdx.x;
    if (gid >= nmat * 65536) return;
    int m = gid >> 16, o = gid & 65535;
    int c = o >> 13, r = o & 8191;
    int kt = r >> 10, i4 = r & 1023;
    int ks = i4 >> 8, r2 = i4 & 255;
    int wN = r2 >> 6, r3 = r2 & 63;
    int nf2 = r3 >> 5, lane = r3 & 31;
    int t = lane & 3, g = lane >> 2;
    int k = kt * 32 + ks * 8 + t;
    int n = c * 128 + wN * 32 + nf2 * 16 + g;
    const float* Wm = W + (size_t)m * 262144;
    float4 v;
    v.x = f2tf32f(Wm[k * 1024 + n]);
    v.y = f2tf32f(Wm[(k + 4) * 1024 + n]);
    v.z = f2tf32f(Wm[k * 1024 + n + 8]);
    v.w = f2tf32f(Wm[(k + 4) * 1024 + n + 8]);
    ((float4*)out)[gid] = v;
}

// w_ff2 [1024, 256]: [c(8)][kt(4)][ks(4)][wN(4)][nf2(4)][lane] float4
__global__ void packff2_kernel(const float* __restrict__ W, float* __restrict__ out, int nmat) {
    int gid = blockIdx.x * 256 + threadIdx.x;
    if (gid >= nmat * 65536) return;
    int m = gid >> 16, o = gid & 65535;
    int c = o >> 13, r = o & 8191;
    int kt = r >> 11, i4 = r & 2047;
    int ks = i4 >> 9, r2 = i4 & 511;
    int wN = r2 >> 7, r3 = r2 & 127;
    int nf2 = r3 >> 5, lane = r3 & 31;
    int t = lane & 3, g = lane >> 2;
    int k = c * 128 + kt * 32 + ks * 8 + t;
    int n = wN * 64 + nf2 * 16 + g;
    const float* Wm = W + (size_t)m * 262144;
    float4 v;
    v.x = f2tf32f(Wm[k * 256 + n]);
    v.y = f2tf32f(Wm[(k + 4) * 256 + n]);
    v.z = f2tf32f(Wm[k * 256 + n + 8]);
    v.w = f2tf32f(Wm[(k + 4) * 256 + n + 8]);
    ((float4*)out)[gid] = v;
}

// ---------------- small kernels ----------------

__global__ void cvt_kernel(const float* __restrict__ in, float* __restrict__ out, int n4) {
    int i = blockIdx.x * 256 + threadIdx.x;
    if (i >= n4) return;
    float4 v = ((const float4*)in)[i];
    v.x = f2tf32f(v.x); v.y = f2tf32f(v.y); v.z = f2tf32f(v.z); v.w = f2tf32f(v.w);
    ((float4*)out)[i] = v;
}

__global__ void embed_kernel(const float* __restrict__ rel, const int* __restrict__ feat,
                             float* __restrict__ out) {
    int gid = blockIdx.x * blockDim.x + threadIdx.x;
    int e = gid >> 6;
    if (e >= NEDGE) return;
    int c = (gid & 63) << 2;
    int r = __ldg(feat + e);
    float4 v = *(const float4*)(rel + (size_t)r * H + c);
    v.x = f2tf32f(v.x); v.y = f2tf32f(v.y); v.z = f2tf32f(v.z); v.w = f2tf32f(v.w);
    *(float4*)(out + (size_t)e * H + c) = v;
}

__global__ void gather2_kernel(const float* __restrict__ x, const int* __restrict__ s,
                               const int* __restrict__ d, float* __restrict__ out, int n) {
    int gid = blockIdx.x * blockDim.x + threadIdx.x;
    int e = gid >> 6;
    if (e >= n) return;
    int c = (gid & 63) << 2;
    int si = __ldg(s + e), di = __ldg(d + e);
    float4 a = *(const float4*)(x + (size_t)si * H + c);
    float4 b = *(const float4*)(x + (size_t)di * H + c);
    a.x = f2tf32f(a.x + b.x); a.y = f2tf32f(a.y + b.y);
    a.z = f2tf32f(a.z + b.z); a.w = f2tf32f(a.w + b.w);
    *(float4*)(out + (size_t)e * H + c) = a;
}

// CSR gather segment-sum (2-way unrolled)
__global__ void segsum_kernel(const float* __restrict__ rows, const int* __restrict__ rp,
                              const int* __restrict__ ci, float* __restrict__ out, int nseg) {
    int row = blockIdx.x * 8 + (threadIdx.x >> 5);
    if (row >= nseg) return;
    int lane = threadIdx.x & 31;
    int beg = __ldg(rp + row), end = __ldg(rp + row + 1);
    float a[8] = {0.f, 0.f, 0.f, 0.f, 0.f, 0.f, 0.f, 0.f};
    float b[8] = {0.f, 0.f, 0.f, 0.f, 0.f, 0.f, 0.f, 0.f};
    int j = beg;
    for (; j + 1 < end; j += 2) {
        const float* p0 = rows + (size_t)__ldg(ci + j) * H + lane * 8;
        const float* p1 = rows + (size_t)__ldg(ci + j + 1) * H + lane * 8;
        float4 u0 = ((const float4*)p0)[0], u1 = ((const float4*)p0)[1];
        float4 w0 = ((const float4*)p1)[0], w1 = ((const float4*)p1)[1];
        a[0] += u0.x; a[1] += u0.y; a[2] += u0.z; a[3] += u0.w;
        a[4] += u1.x; a[5] += u1.y; a[6] += u1.z; a[7] += u1.w;
        b[0] += w0.x; b[1] += w0.y; b[2] += w0.z; b[3] += w0.w;
        b[4] += w1.x; b[5] += w1.y; b[6] += w1.z; b[7] += w1.w;
    }
    if (j < end) {
        const float* p0 = rows + (size_t)__ldg(ci + j) * H + lane * 8;
        float4 u0 = ((const float4*)p0)[0], u1 = ((const float4*)p0)[1];
        a[0] += u0.x; a[1] += u0.y; a[2] += u0.z; a[3] += u0.w;
        a[4] += u1.x; a[5] += u1.y; a[6] += u1.z; a[7] += u1.w;
    }
#pragma unroll
    for (int i = 0; i < 8; i++) a[i] = f2tf32f(a[i] + b[i]);
    float* po = out + (size_t)row * H + lane * 8;
    ((float4*)po)[0] = make_float4(a[0], a[1], a[2], a[3]);
    ((float4*)po)[1] = make_float4(a[4], a[5], a[6], a[7]);
}

// hop1 of layer-0 edge core: gather rel[feat[ci[j]]]
__global__ void segsum_rel_kernel(const float* __restrict__ rel, const int* __restrict__ feat,
                                  const int* __restrict__ rp, const int* __restrict__ ci,
                                  float* __restrict__ out, int nseg) {
    int row = blockIdx.x * 8 + (threadIdx.x >> 5);
    if (row >= nseg) return;
    int lane = threadIdx.x & 31;
    int beg = __ldg(rp + row), end = __ldg(rp + row + 1);
    float a[8] = {0.f, 0.f, 0.f, 0.f, 0.f, 0.f, 0.f, 0.f};
    for (int j = beg; j < end; j++) {
        int r = __ldg(feat + __ldg(ci + j));
        const float* p = rel + (size_t)r * H + lane * 8;
        float4 u0 = ((const float4*)p)[0], u1 = ((const float4*)p)[1];
        a[0] += f2tf32f(u0.x); a[1] += f2tf32f(u0.y);
        a[2] += f2tf32f(u0.z); a[3] += f2tf32f(u0.w);
        a[4] += f2tf32f(u1.x); a[5] += f2tf32f(u1.y);
        a[6] += f2tf32f(u1.z); a[7] += f2tf32f(u1.w);
    }
#pragma unroll
    for (int i = 0; i < 8; i++) a[i] = f2tf32f(a[i]);
    float* po = out + (size_t)row * H + lane * 8;
    ((float4*)po)[0] = make_float4(a[0], a[1], a[2], a[3]);
    ((float4*)po)[1] = make_float4(a[4], a[5], a[6], a[7]);
}

// ================= GEMM1 + LN1 fused, m32n64 warp tile =================
// out1 = tf32( LN( xres + gelu( sum_j A_j @ W_j + sum_j bias_j ) ) )
// BM=64, BN=256, 256 threads, warps: 2 along M (m32) x 4 along N (n64).

#define G_ASTR 36
#define G_AST (64 * G_ASTR)       // 2304
#define G_BST 8192
#define G1_SMEM_FLOATS (2 * G_AST + 2 * G_BST + 3 * 256 + 2 * 256)
#define G1_SMEM_BYTES (G1_SMEM_FLOATS * 4)

struct G1Args {
    const float* A[6];
    const float* W[6];       // packed
    const float* Bias[6];
    const float* xres;
    const float* gamma;
    const float* beta;
};

__global__ void __launch_bounds__(256, 2)
gemm1_ln_kernel(G1Args args, int M, float* __restrict__ out) {
    extern __shared__ float sm[];
    float* As = sm;
    float* Bs = sm + 2 * G_AST;
    float* bias_s = Bs + 2 * G_BST;
    float* gs = bias_s + 256;
    float* bt = gs + 256;
    float* lnS = bt + 256;
    float* lnQ = lnS + 256;
    float* xs = sm;                 // alias; reused after mainloop, stride 264

    int tid = threadIdx.x;
    int bm = blockIdx.x * 64;

    {
        float b = 0.f;
#pragma unroll
        for (int j = 0; j < 6; j++) b += __ldg(args.Bias[j] + tid);
        bias_s[tid] = b;
        gs[tid] = __ldg(args.gamma + tid);
        bt[tid] = __ldg(args.beta + tid);
    }

    uint32_t a_base = (uint32_t)__cvta_generic_to_shared(As);
    uint32_t b_base = (uint32_t)__cvta_generic_to_shared(Bs);

    int warp = tid >> 5, lane = tid & 31, g = lane >> 2, t = lane & 3;
    int wm = (warp >> 2) * 32;    // 2 warps along M, 32 rows each
    int wN = warp & 3;            // 4 warps along N, 64 cols each
    int wn = wN * 64;

    float acc[2][8][4];
#pragma unroll
    for (int mt = 0; mt < 2; mt++)
#pragma unroll
        for (int nf = 0; nf < 8; nf++)
#pragma unroll
            for (int i = 0; i < 4; i++) acc[mt][nf][i] = 0.f;

    auto issue = [&](int tt, int buf) {
        int j = tt >> 3;
        int kk = (tt & 7) * 32;
        const float* A = args.A[j];
        const float4* Wp = (const float4*)args.W[j] + (size_t)(tt & 7) * 2048;
#pragma unroll
        for (int i = 0; i < 2; i++) {
            int idx = tid + i * 256;
            int r = idx >> 3, kv = (idx & 7) << 2;
            int row = bm + r;
            uint32_t dst = a_base + (uint32_t)((buf * G_AST + r * G_ASTR + kv) * 4);
            const float* src = A + (size_t)row * H + kk + kv;
            int sz = (row < M) ? 16 : 0;
            asm volatile("cp.async.cg.shared.global [%0], [%1], 16, %2;\n"
                         :: "r"(dst), "l"(src), "r"(sz));
        }
#pragma unroll
        for (int i = 0; i < 8; i++) {
            int idx = tid + i * 256;
            uint32_t dst = b_base + (uint32_t)((buf * G_BST + idx * 4) * 4);
            asm volatile("cp.async.cg.shared.global [%0], [%1], 16;\n"
                         :: "r"(dst), "l"(Wp + idx));
        }
        asm volatile("cp.async.commit_group;\n");
    };

    issue(0, 0);
    for (int tt = 0; tt < 48; tt++) {
        if (tt + 1 < 48) {
            issue(tt + 1, (tt + 1) & 1);
            asm volatile("cp.async.wait_group 1;\n");
        } else {
            asm volatile("cp.async.wait_group 0;\n");
        }
        __syncthreads();
        const float* Ab = As + (tt & 1) * G_AST;
        const float4* Bb4 = (const float4*)(Bs + (tt & 1) * G_BST) + wN * 128 + lane;
#pragma unroll
        for (int ks = 0; ks < 4; ks++) {
            int k0 = ks * 8;
            uint32_t a0[4], a1[4];
            a0[0] = __float_as_uint(Ab[(wm + g) * G_ASTR + k0 + t]);
            a0[1] = __float_as_uint(Ab[(wm + 8 + g) * G_ASTR + k0 + t]);
            a0[2] = __float_as_uint(Ab[(wm + g) * G_ASTR + k0 + t + 4]);
            a0[3] = __float_as_uint(Ab[(wm + 8 + g) * G_ASTR + k0 + t + 4]);
            a1[0] = __float_as_uint(Ab[(wm + 16 + g) * G_ASTR + k0 + t]);
            a1[1] = __float_as_uint(Ab[(wm + 24 + g) * G_ASTR + k0 + t]);
            a1[2] = __float_as_uint(Ab[(wm + 16 + g) * G_ASTR + k0 + t + 4]);
            a1[3] = __float_as_uint(Ab[(wm + 24 + g) * G_ASTR + k0 + t + 4]);
#pragma unroll
            for (int nf2 = 0; nf2 < 4; nf2++) {
                float4 bv = Bb4[ks * 512 + nf2 * 32];
                uint32_t b0[2] = {__float_as_uint(bv.x), __float_as_uint(bv.y)};
                mma_tf32(acc[0][2 * nf2], a0, b0);
                mma_tf32(acc[1][2 * nf2], a1, b0);
                uint32_t b1[2] = {__float_as_uint(bv.z), __float_as_uint(bv.w)};
                mma_tf32(acc[0][2 * nf2 + 1], a0, b1);
                mma_tf32(acc[1][2 * nf2 + 1], a1, b1);
            }
        }
        __syncthreads();
    }

    // cooperative residual tile load into xs (stride 264)
#pragma unroll
    for (int i = 0; i < 16; i++) {
        int idx = tid + i * 256;
        int r = idx >> 6, cv = (idx & 63) << 2;
        int row = bm + r;
        float4 v = make_float4(0.f, 0.f, 0.f, 0.f);
        if (row < M) v = *(const float4*)(args.xres + (size_t)row * H + cv);
        *(float4*)(xs + r * 264 + cv) = v;
    }
    __syncthreads();

    // bias+gelu+residual, per-row partial sums
#pragma unroll
    for (int mt = 0; mt < 2; mt++) {
#pragma unroll
        for (int h = 0; h < 2; h++) {
            int row = wm + mt * 16 + h * 8 + g;
            float s = 0.f, q = 0.f;
#pragma unroll
            for (int nf = 0; nf < 8; nf++) {
                int col = wn + nf * 8 + 2 * t;
                float v0 = xs[row * 264 + col]     + gelu_exact(acc[mt][nf][2 * h]     + bias_s[col]);
                float v1 = xs[row * 264 + col + 1] + gelu_exact(acc[mt][nf][2 * h + 1] + bias_s[col + 1]);
                acc[mt][nf][2 * h] = v0; acc[mt][nf][2 * h + 1] = v1;
                s += v0 + v1; q += v0 * v0 + v1 * v1;
            }
#pragma unroll
            for (int o = 1; o <= 2; o <<= 1) {
                s += __shfl_xor_sync(0xffffffffu, s, o);
                q += __shfl_xor_sync(0xffffffffu, q, o);
            }
            if (t == 0) { lnS[row * 4 + wN] = s; lnQ[row * 4 + wN] = q; }
        }
    }
    __syncthreads();
#pragma unroll
    for (int mt = 0; mt < 2; mt++) {
#pragma unroll
        for (int h = 0; h < 2; h++) {
            int row = wm + mt * 16 + h * 8 + g;
            float S = lnS[row * 4] + lnS[row * 4 + 1] + lnS[row * 4 + 2] + lnS[row * 4 + 3];
            float Q = lnQ[row * 4] + lnQ[row * 4 + 1] + lnQ[row * 4 + 2] + lnQ[row * 4 + 3];
            float m = S * (1.f / H), v = Q * (1.f / H) - m * m, rs = rsqrtf(v + 1e-5f);
            if (bm + row < M) {
#pragma unroll
                for (int nf = 0; nf < 8; nf++) {
                    int col = wn + nf * 8 + 2 * t;
                    float o0 = f2tf32f((acc[mt][nf][2 * h]     - m) * rs * gs[col]     + bt[col]);
                    float o1 = f2tf32f((acc[mt][nf][2 * h + 1] - m) * rs * gs[col + 1] + bt[col + 1]);
                    *(float2*)(out + (size_t)(bm + row) * H + col) = make_float2(o0, o1);
                }
            }
        }
    }
}

// ================= fused FFN + LN2 =================
#define F_XSTR 260
#define F_HSTR 132
#define F_B1ST 4096
#define F_B2ST 8192
#define F_SMEM_FLOATS (64 * F_XSTR + 64 * F_HSTR + 2 * F_B2ST + 3 * 256 + 128 + 2 * 256)
#define F_SMEM_BYTES (F_SMEM_FLOATS * 4)

struct FArgs {
    const float* w1;    // packed
    const float* b1;
    const float* w2;    // packed
    const float* b2;
    const float* gamma;
    const float* beta;
};

__global__ void __launch_bounds__(512, 1)
ffn_kernel(FArgs args, int M, const float* __restrict__ in1,
           float* __restrict__ out, int out_cvt) {
    extern __shared__ float sm[];
    float* xs  = sm;
    float* hb  = xs + 64 * F_XSTR;
    float* Bst = hb + 64 * F_HSTR;
    float* b2s = Bst + 2 * F_B2ST;
    float* gs  = b2s + 256;
    float* bt  = gs + 256;
    float* b1c = bt + 256;
    float* lnS = b1c + 128;
    float* lnQ = lnS + 256;

    int tid = threadIdx.x;
    int bm = blockIdx.x * 64;

    if (tid < 256) {
        b2s[tid] = __ldg(args.b2 + tid);
        gs[tid]  = __ldg(args.gamma + tid);
        bt[tid]  = __ldg(args.beta + tid);
    }
#pragma unroll
    for (int i = 0; i < 8; i++) {
        int idx = tid + i * 512;
        int r = idx >> 6, cv = (idx & 63) << 2;
        int row = bm + r;
        float4 v = make_float4(0.f, 0.f, 0.f, 0.f);
        if (row < M) v = *(const float4*)(in1 + (size_t)row * H + cv);
        *(float4*)(xs + r * F_XSTR + cv) = v;
    }

    uint32_t bst_base = (uint32_t)__cvta_generic_to_shared(Bst);
    int warp = tid >> 5, lane = tid & 31, g = lane >> 2, t = lane & 3;
    int wm = (warp >> 2) * 16;
    int wN = warp & 3;
    int wn1 = wN * 32;
    int wn2 = wN * 64;

    float acc2[8][4];
#pragma unroll
    for (int nf = 0; nf < 8; nf++)
#pragma unroll
        for (int i = 0; i < 4; i++) acc2[nf][i] = 0.f;

    __syncthreads();

    for (int c = 0; c < 8; c++) {
        if (tid < 128) b1c[tid] = __ldg(args.b1 + c * 128 + tid);

        float acc1[4][4];
#pragma unroll
        for (int nf = 0; nf < 4; nf++)
#pragma unroll
            for (int i = 0; i < 4; i++) acc1[nf][i] = 0.f;

        const float4* W1p = (const float4*)args.w1 + (size_t)c * 8192;
        auto issue1 = [&](int kt, int buf) {
#pragma unroll
            for (int i = 0; i < 2; i++) {
                int idx = tid + i * 512;
                uint32_t dst = bst_base + (uint32_t)((buf * F_B1ST + idx * 4) * 4);
                asm volatile("cp.async.cg.shared.global [%0], [%1], 16;\n"
                             :: "r"(dst), "l"(W1p + kt * 1024 + idx));
            }
            asm volatile("cp.async.commit_group;\n");
        };

        issue1(0, 0);
        for (int kt = 0; kt < 8; kt++) {
            if (kt + 1 < 8) {
                issue1(kt + 1, (kt + 1) & 1);
                asm volatile("cp.async.wait_group 1;\n");
            } else {
                asm volatile("cp.async.wait_group 0;\n");
            }
            __syncthreads();
            const float4* Bb4 = (const float4*)(Bst + (kt & 1) * F_B1ST) + wN * 64 + lane;
            int kk = kt * 32;
#pragma unroll
            for (int ks = 0; ks < 4; ks++) {
                int kg = kk + ks * 8;
                uint32_t a[4];
                a[0] = __float_as_uint(xs[(wm + g) * F_XSTR + kg + t]);
                a[1] = __float_as_uint(xs[(wm + 8 + g) * F_XSTR + kg + t]);
                a[2] = __float_as_uint(xs[(wm + g) * F_XSTR + kg + t + 4]);
                a[3] = __float_as_uint(xs[(wm + 8 + g) * F_XSTR + kg + t + 4]);
#pragma unroll
                for (int nf2 = 0; nf2 < 2; nf2++) {
                    float4 bv = Bb4[ks * 256 + nf2 * 32];
                    uint32_t b0[2] = {__float_as_uint(bv.x), __float_as_uint(bv.y)};
                    mma_tf32(acc1[2 * nf2], a, b0);
                    uint32_t b1[2] = {__float_as_uint(bv.z), __float_as_uint(bv.w)};
                    mma_tf32(acc1[2 * nf2 + 1], a, b1);
                }
            }
            __syncthreads();
        }

#pragma unroll
        for (int nf = 0; nf < 4; nf++) {
            int col = wn1 + nf * 8 + 2 * t;
            float h0 = f2tf32f(gelu_exact(acc1[nf][0] + b1c[col]));
            float h1 = f2tf32f(gelu_exact(acc1[nf][1] + b1c[col + 1]));
            float h2 = f2tf32f(gelu_exact(acc1[nf][2] + b1c[col]));
            float h3 = f2tf32f(gelu_exact(acc1[nf][3] + b1c[col + 1]));
            *(float2*)(hb + (wm + g) * F_HSTR + col)     = make_float2(h0, h1);
            *(float2*)(hb + (wm + 8 + g) * F_HSTR + col) = make_float2(h2, h3);
        }
        __syncthreads();

        const float4* W2p = (const float4*)args.w2 + (size_t)c * 8192;
        auto issue2 = [&](int kt, int buf) {
#pragma unroll
            for (int i = 0; i < 4; i++) {
                int idx = tid + i * 512;
                uint32_t dst = bst_base + (uint32_t)((buf * F_B2ST + idx * 4) * 4);
                asm volatile("cp.async.cg.shared.global [%0], [%1], 16;\n"
                             :: "r"(dst), "l"(W2p + kt * 2048 + idx));
            }
            asm volatile("cp.async.commit_group;\n");
        };

        issue2(0, 0);
        for (int kt = 0; kt < 4; kt++) {
            if (kt + 1 < 4) {
                issue2(kt + 1, (kt + 1) & 1);
                asm volatile("cp.async.wait_group 1;\n");
            } else {
                asm volatile("cp.async.wait_group 0;\n");
            }
            __syncthreads();
            const float4* Bb4 = (const float4*)(Bst + (kt & 1) * F_B2ST) + wN * 128 + lane;
            int kk = kt * 32;
#pragma unroll
            for (int ks = 0; ks < 4; ks++) {
                int kg = kk + ks * 8;
                uint32_t a[4];
                a[0] = __float_as_uint(hb[(wm + g) * F_HSTR + kg + t]);
                a[1] = __float_as_uint(hb[(wm + 8 + g) * F_HSTR + kg + t]);
                a[2] = __float_as_uint(hb[(wm + g) * F_HSTR + kg + t + 4]);
                a[3] = __float_as_uint(hb[(wm + 8 + g) * F_HSTR + kg + t + 4]);
#pragma unroll
                for (int nf2 = 0; nf2 < 4; nf2++) {
                    float4 bv = Bb4[ks * 512 + nf2 * 32];
                    uint32_t b0[2] = {__float_as_uint(bv.x), __float_as_uint(bv.y)};
                    mma_tf32(acc2[2 * nf2], a, b0);
                    uint32_t b1[2] = {__float_as_uint(bv.z), __float_as_uint(bv.w)};
                    mma_tf32(acc2[2 * nf2 + 1], a, b1);
                }
            }
            __syncthreads();
        }
    }

    // LN2 epilogue
    int row0 = wm + g, row1 = wm + 8 + g;
    float s0 = 0.f, q0 = 0.f, s1 = 0.f, q1 = 0.f;
#pragma unroll
    for (int nf = 0; nf < 8; nf++) {
        int col = wn2 + nf * 8 + 2 * t;
        float t0 = xs[row0 * F_XSTR + col]     + acc2[nf][0] + b2s[col];
        float t1 = xs[row0 * F_XSTR + col + 1] + acc2[nf][1] + b2s[col + 1];
        float t2 = xs[row1 * F_XSTR + col]     + acc2[nf][2] + b2s[col];
        float t3 = xs[row1 * F_XSTR + col + 1] + acc2[nf][3] + b2s[col + 1];
        acc2[nf][0] = t0; acc2[nf][1] = t1; acc2[nf][2] = t2; acc2[nf][3] = t3;
        s0 += t0 + t1; q0 += t0 * t0 + t1 * t1;
        s1 += t2 + t3; q1 += t2 * t2 + t3 * t3;
    }
#pragma unroll
    for (int o = 1; o <= 2; o <<= 1) {
        s0 += __shfl_xor_sync(0xffffffffu, s0, o);
        q0 += __shfl_xor_sync(0xffffffffu, q0, o);
        s1 += __shfl_xor_sync(0xffffffffu, s1, o);
        q1 += __shfl_xor_sync(0xffffffffu, q1, o);
    }
    if (t == 0) {
        lnS[row0 * 4 + wN] = s0; lnQ[row0 * 4 + wN] = q0;
        lnS[row1 * 4 + wN] = s1; lnQ[row1 * 4 + wN] = q1;
    }
    __syncthreads();
    float S0 = lnS[row0 * 4] + lnS[row0 * 4 + 1] + lnS[row0 * 4 + 2] + lnS[row0 * 4 + 3];
    float Q0 = lnQ[row0 * 4] + lnQ[row0 * 4 + 1] + lnQ[row0 * 4 + 2] + lnQ[row0 * 4 + 3];
    float S1 = lnS[row1 * 4] + lnS[row1 * 4 + 1] + lnS[row1 * 4 + 2] + lnS[row1 * 4 + 3];
    float Q1 = lnQ[row1 * 4] + lnQ[row1 * 4 + 1] + lnQ[row1 * 4 + 2] + lnQ[row1 * 4 + 3];
    float m0 = S0 * (1.f / H), v0 = Q0 * (1.f / H) - m0 * m0, r0 = rsqrtf(v0 + 1e-5f);
    float m1 = S1 * (1.f / H), v1 = Q1 * (1.f / H) - m1 * m1, r1 = rsqrtf(v1 + 1e-5f);
    bool ok0 = (bm + row0) < M, ok1 = (bm + row1) < M;
#pragma unroll
    for (int nf = 0; nf < 8; nf++) {
        int col = wn2 + nf * 8 + 2 * t;
        float o0 = (acc2[nf][0] - m0) * r0 * gs[col]     + bt[col];
        float o1 = (acc2[nf][1] - m0) * r0 * gs[col + 1] + bt[col + 1];
        float o2 = (acc2[nf][2] - m1) * r1 * gs[col]     + bt[col];
        float o3 = (acc2[nf][3] - m1) * r1 * gs[col + 1] + bt[col + 1];
        if (out_cvt) {
            o0 = f2tf32f(o0); o1 = f2tf32f(o1);
            o2 = f2tf32f(o2); o3 = f2tf32f(o3);
        }
        if (ok0) *(float2*)(out + (size_t)(bm + row0) * H + col) = make_float2(o0, o1);
        if (ok1) *(float2*)(out + (size_t)(bm + row1) * H + col) = make_float2(o2, o3);
    }
}

// ---------------- host orchestration ----------------

struct Net {
    const float *b_self, *b_khop, *b_fuse, *b_ff1, *b_ff2;
    const float *ln1g, *ln1b, *ln2g, *ln2b;
    float* wbuf;
};

static void run_core(const Net& n, int l, int c, int M, float* const* z,
                     const float* xin, const float* fused, float* out1buf,
                     float* outp, int cvt_final, cudaStream_t st) {
    size_t lc = (size_t)(l * 2 + c);
    G1Args ga;
    ga.A[0] = xin;
    ga.W[0] = n.wbuf + OFF_WSELF + lc * H * H;
    ga.Bias[0] = n.b_self + lc * H;
    for (int i = 0; i < 4; i++) {
        ga.A[1 + i] = z[i];
        ga.W[1 + i] = n.wbuf + OFF_WKHOP + (lc * 4 + i) * (size_t)H * H;
        ga.Bias[1 + i] = n.b_khop + (lc * 4 + i) * (size_t)H;
    }
    ga.A[5] = fused;
    ga.W[5] = n.wbuf + OFF_WFUSE + lc * H * H;
    ga.Bias[5] = n.b_fuse + lc * H;
    ga.xres = xin;
    ga.gamma = n.ln1g + lc * H;
    ga.beta  = n.ln1b + lc * H;

    int grid = (M + 63) / 64;
    gemm1_ln_kernel<<<grid, 256, G1_SMEM_BYTES, st>>>(ga, M, out1buf);

    FArgs fa;
    fa.w1 = n.wbuf + OFF_WFF1 + lc * (size_t)H * FH;
    fa.b1 = n.b_ff1 + lc * FH;
    fa.w2 = n.wbuf + OFF_WFF2 + lc * (size_t)FH * H;
    fa.b2 = n.b_ff2 + lc * H;
    fa.gamma = n.ln2g + lc * H;
    fa.beta  = n.ln2b + lc * H;
    ffn_kernel<<<grid, 512, F_SMEM_BYTES, st>>>(fa, M, out1buf, outp, cvt_final);
}

static void exclusive_scan(int* cnt, int* rp, int* bsums, int n) {
    int nb = (n + 1023) / 1024;
    scan1_kernel<<<nb, 1024>>>(cnt, rp, bsums, n);
    scan2_kernel<<<1, 1024>>>(bsums, nb);
    scan3_kernel<<<nb, 1024>>>(rp, bsums, cnt, n);
}

extern "C" void kernel_launch(void* const* d_in, const int* in_sizes, int n_in,
                              void* d_out, int out_size) {
    const float* x_in = (const float*)d_in[0];
    const int* feat   = (const int*)d_in[1];
    const int* eig    = (const int*)d_in[2];
    const int* eil    = (const int*)d_in[3];
    const float* rel  = (const float*)d_in[4];

    const float* w_self = (const float*)d_in[5];
    const float* w_khop = (const float*)d_in[7];
    const float* w_fuse = (const float*)d_in[9];
    const float* w_ff1  = (const float*)d_in[11];
    const float* w_ff2  = (const float*)d_in[13];

    Net n;
    n.b_self = (const float*)d_in[6];
    n.b_khop = (const float*)d_in[8];
    n.b_fuse = (const float*)d_in[10];
    n.b_ff1  = (const float*)d_in[12];
    n.b_ff2  = (const float*)d_in[14];
    n.ln1g   = (const float*)d_in[15]; n.ln1b = (const float*)d_in[16];
    n.ln2g   = (const float*)d_in[17]; n.ln2b = (const float*)d_in[18];

    cudaFuncSetAttribute(gemm1_ln_kernel,
                         cudaFuncAttributeMaxDynamicSharedMemorySize, G1_SMEM_BYTES);
    cudaFuncSetAttribute(ffn_kernel,
                         cudaFuncAttributeMaxDynamicSharedMemorySize, F_SMEM_BYTES);

    // side stream + events (created once, outside capture on the first call)
    static cudaStream_t s2 = nullptr;
    static cudaEvent_t ev_init, ev_x0, ev_lg0, ev_fin;
    if (!s2) {
        cudaStreamCreateWithFlags(&s2, cudaStreamNonBlocking);
        cudaEventCreateWithFlags(&ev_init, cudaEventDisableTiming);
        cudaEventCreateWithFlags(&ev_x0,   cudaEventDisableTiming);
        cudaEventCreateWithFlags(&ev_lg0,  cudaEventDisableTiming);
        cudaEventCreateWithFlags(&ev_fin,  cudaEventDisableTiming);
    }

    float *px0, *plg0, *pfn, *pfe, *pzbase, *pznb, *pout1, *pout1n, *pwbuf;
    int *rp_nd, *ci_nd, *rp_fn, *ci_fn, *rp_lg, *ci_lg, *pcnt, *pcur, *pbs;
    cudaGetSymbolAddress((void**)&px0,   g_x);
    cudaGetSymbolAddress((void**)&plg0,  g_lg);
    cudaGetSymbolAddress((void**)&pfn,   g_fn);
    cudaGetSymbolAddress((void**)&pfe,   g_fe);
    cudaGetSymbolAddress((void**)&pzbase,g_z);
    cudaGetSymbolAddress((void**)&pznb,  g_zn);
    cudaGetSymbolAddress((void**)&pout1, g_out1);
    cudaGetSymbolAddress((void**)&pout1n,g_out1n);
    cudaGetSymbolAddress((void**)&pwbuf, g_wbuf);
    cudaGetSymbolAddress((void**)&rp_nd, g_rp_nd);
    cudaGetSymbolAddress((void**)&ci_nd, g_ci_nd);
    cudaGetSymbolAddress((void**)&rp_fn, g_rp_fn);
    cudaGetSymbolAddress((void**)&ci_fn, g_ci_fn);
    cudaGetSymbolAddress((void**)&rp_lg, g_rp_lg);
    cudaGetSymbolAddress((void**)&ci_lg, g_ci_lg);
    cudaGetSymbolAddress((void**)&pcnt,  g_cnt);
    cudaGetSymbolAddress((void**)&pcur,  g_cur);
    cudaGetSymbolAddress((void**)&pbs,   g_bs);

    n.wbuf = pwbuf;
    float* px[2]  = {px0,  px0  + (size_t)NNODE * H};
    float* plg[2] = {plg0, plg0 + (size_t)NEDGE * H};
    float* ze[4], * zn[4];
    for (int i = 0; i < 4; i++) {
        ze[i] = pzbase + (size_t)i * NEDGE * H;
        zn[i] = pznb + (size_t)i * NNODE * H;
    }

    const int* src_g = eig;  const int* dst_g = eig + NEDGE;
    const int* src_l = eil;  const int* dst_l = eil + NLG;

    // ===== stream 0: lg CSR + layer-0 edge khops + packs + init + node CSRs =====
    cudaMemsetAsync(pcnt, 0, NEDGE * sizeof(int), 0);
    hist_kernel<<<(NLG + 255) / 256, 256>>>(dst_l, pcnt, NLG);
    exclusive_scan(pcnt, rp_lg, pbs, NEDGE);
    cudaMemcpyAsync(pcur, rp_lg, NEDGE * sizeof(int), cudaMemcpyDeviceToDevice, 0);
    fill_kernel<<<(NLG + 255) / 256, 256>>>(dst_l, src_l, pcur, ci_lg, NLG);

    segsum_rel_kernel<<<(NEDGE + 7) / 8, 256>>>(rel, feat, rp_lg, ci_lg, ze[0], NEDGE);
    segsum_kernel<<<(NEDGE + 7) / 8, 256>>>(ze[0], rp_lg, ci_lg, ze[1], NEDGE);
    segsum_kernel<<<(NEDGE + 7) / 8, 256>>>(ze[1], rp_lg, ci_lg, ze[2], NEDGE);
    segsum_kernel<<<(NEDGE + 7) / 8, 256>>>(ze[2], rp_lg, ci_lg, ze[3], NEDGE);

    pack256_kernel<<<(4 * 16384 + 255) / 256, 256>>>(w_self, pwbuf + OFF_WSELF, 4);
    pack256_kernel<<<(16 * 16384 + 255) / 256, 256>>>(w_khop, pwbuf + OFF_WKHOP, 16);
    pack256_kernel<<<(4 * 16384 + 255) / 256, 256>>>(w_fuse, pwbuf + OFF_WFUSE, 4);
    packff1_kernel<<<(4 * 65536 + 255) / 256, 256>>>(w_ff1, pwbuf + OFF_WFF1, 4);
    packff2_kernel<<<(4 * 65536 + 255) / 256, 256>>>(w_ff2, pwbuf + OFF_WFF2, 4);

    cvt_kernel<<<(NNODE * H / 4 + 255) / 256, 256>>>(x_in, px[0], NNODE * H / 4);
    embed_kernel<<<NEDGE * 64 / 256, 256>>>(rel, feat, plg[0]);

    cudaMemsetAsync(pcnt, 0, NNODE * sizeof(int), 0);
    hist_kernel<<<(NEDGE + 255) / 256, 256>>>(dst_g, pcnt, NEDGE);
    exclusive_scan(pcnt, rp_nd, pbs, NNODE);
    cudaMemcpyAsync(pcur, rp_nd, NNODE * sizeof(int), cudaMemcpyDeviceToDevice, 0);
    fill_kernel<<<(NEDGE + 255) / 256, 256>>>(dst_g, src_g, pcur, ci_nd, NEDGE);

    cudaMemsetAsync(pcnt, 0, NNODE * sizeof(int), 0);
    hist_kernel<<<(NEDGE + 255) / 256, 256>>>(src_g, pcnt, NEDGE);
    hist_kernel<<<(NEDGE + 255) / 256, 256>>>(dst_g, pcnt, NEDGE);
    exclusive_scan(pcnt, rp_fn, pbs, NNODE);
    cudaMemcpyAsync(pcur, rp_fn, NNODE * sizeof(int), cudaMemcpyDeviceToDevice, 0);
    fill_kernel<<<(NEDGE + 255) / 256, 256>>>(src_g, nullptr, pcur, ci_fn, NEDGE);
    fill_kernel<<<(NEDGE + 255) / 256, 256>>>(dst_g, nullptr, pcur, ci_fn, NEDGE);

    cudaEventRecord(ev_init, 0);

    // ===== stream s2: node core, layer 0 =====
    cudaStreamWaitEvent(s2, ev_init, 0);
    segsum_kernel<<<(NNODE + 7) / 8, 256, 0, s2>>>(plg[0], rp_fn, ci_fn, pfn, NNODE);
    {
        const float* prev = px[0];
        for (int i = 0; i < 4; i++) {
            segsum_kernel<<<(NNODE + 7) / 8, 256, 0, s2>>>(prev, rp_nd, ci_nd, zn[i], NNODE);
            prev = zn[i];
        }
    }
    run_core(n, 0, 0, NNODE, zn, px[0], pfn, pout1n, px[1], 1, s2);
    cudaEventRecord(ev_x0, s2);

    // ===== stream 0: edge core, layer 0 =====
    gather2_kernel<<<NEDGE * 64 / 256, 256>>>(px[0], src_g, dst_g, pfe, NEDGE);
    run_core(n, 0, 1, NEDGE, ze, plg[0], pfe, pout1, plg[1], 1, (cudaStream_t)0);
    cudaEventRecord(ev_lg0, 0);

    // ===== stream s2: node core, layer 1 =====
    cudaStreamWaitEvent(s2, ev_lg0, 0);
    segsum_kernel<<<(NNODE + 7) / 8, 256, 0, s2>>>(plg[1], rp_fn, ci_fn, pfn, NNODE);
    {
        const float* prev = px[1];
        for (int i = 0; i < 4; i++) {
            segsum_kernel<<<(NNODE + 7) / 8, 256, 0, s2>>>(prev, rp_nd, ci_nd, zn[i], NNODE);
            prev = zn[i];
        }
    }
    run_core(n, 1, 0, NNODE, zn, px[1], pfn, pout1n, (float*)d_out, 0, s2);
    cudaEventRecord(ev_fin, s2);

    // ===== stream 0: edge core, layer 1 =====
    cudaStreamWaitEvent(0, ev_x0, 0);
    gather2_kernel<<<NEDGE * 64 / 256, 256>>>(px[1], src_g, dst_g, pfe, NEDGE);
    {
        const float* prev = plg[1];
        for (int i = 0; i < 4; i++) {
            segsum_kernel<<<(NEDGE + 7) / 8, 256>>>(prev, rp_lg, ci_lg, ze[i], NEDGE);
            prev = ze[i];
        }
    }
    run_core(n, 1, 1, NEDGE, ze, plg[1], pfe, pout1,
             (float*)d_out + (size_t)NNODE * H, 0, (cudaStream_t)0);

    cudaStreamWaitEvent(0, ev_fin, 0);
    (void)in_sizes; (void)n_in; (void)out_size;
}

// round 10
// speedup vs baseline: 1.0398x; 1.0369x over previous
#include <cuda_runtime.h>
#include <cstdint>
#include <math.h>

#define H       256
#define FH      1024
#define NNODE   20000
#define NEDGE   160000
#define NLG     640000

// ---------------- scratch (static device memory; no allocations) ----------------
__device__ float g_x[2][(size_t)NNODE * H];
__device__ float g_lg[2][(size_t)NEDGE * H];
__device__ float g_fn[(size_t)NNODE * H];
__device__ float g_fe[(size_t)NEDGE * H];
__device__ float g_z[4][(size_t)NEDGE * H];    // edge-core khop scratch
__device__ float g_zn[4][(size_t)NNODE * H];   // node-core khop scratch
__device__ float g_out1[(size_t)NEDGE * H];    // edge-core out1
__device__ float g_out1n[(size_t)NNODE * H];   // node-core out1 (stream overlap)

// packed (tf32-rounded, fragment-order) weights
#define OFF_WSELF 0
#define OFF_WKHOP (OFF_WSELF + 4 * H * H)
#define OFF_WFUSE (OFF_WKHOP + 16 * H * H)
#define OFF_WFF1  (OFF_WFUSE + 4 * H * H)
#define OFF_WFF2  (OFF_WFF1 + 4 * H * FH)
#define WBUF_TOT  (OFF_WFF2 + 4 * FH * H)
__device__ float g_wbuf[WBUF_TOT];

// CSR structures (stream-0 set)
__device__ int g_rp_nd[NNODE + 1];
__device__ int g_ci_nd[NEDGE];
__device__ int g_rp_fn[NNODE + 1];
__device__ int g_ci_fn[2 * NEDGE];
__device__ int g_rp_lg[NEDGE + 1];
__device__ int g_ci_lg[NLG];
__device__ int g_cnt[NEDGE];
__device__ int g_cur[NEDGE];
__device__ int g_bs[1024];
// stream-2 private CSR scratch (node-side builds)
__device__ int g_cnt2[NNODE];
__device__ int g_cur2[NNODE];
__device__ int g_bs2[1024];

__device__ __forceinline__ float gelu_exact(float v) {
    return 0.5f * v * (1.0f + erff(v * 0.70710678118654752f));
}

__device__ __forceinline__ float f2tf32f(float f) {
    uint32_t r;
    asm("cvt.rna.tf32.f32 %0, %1;" : "=r"(r) : "f"(f));
    return __uint_as_float(r);
}

__device__ __forceinline__ void mma_tf32(float* c, const uint32_t* a, const uint32_t* b) {
    asm volatile(
        "mma.sync.aligned.m16n8k8.row.col.f32.tf32.tf32.f32 "
        "{%0,%1,%2,%3}, {%4,%5,%6,%7}, {%8,%9}, {%0,%1,%2,%3};"
        : "+f"(c[0]), "+f"(c[1]), "+f"(c[2]), "+f"(c[3])
        : "r"(a[0]), "r"(a[1]), "r"(a[2]), "r"(a[3]), "r"(b[0]), "r"(b[1]));
}

// ---------------- CSR build kernels ----------------

__global__ void hist_kernel(const int* __restrict__ key, int* cnt, int n) {
    int i = blockIdx.x * 256 + threadIdx.x;
    if (i < n) atomicAdd(&cnt[__ldg(key + i)], 1);
}

__global__ void scan1_kernel(const int* __restrict__ in, int* __restrict__ out,
                             int* __restrict__ bsums, int n) {
    __shared__ int sh[1024];
    int i = blockIdx.x * 1024 + threadIdx.x;
    int v = (i < n) ? in[i] : 0;
    sh[threadIdx.x] = v;
    __syncthreads();
#pragma unroll
    for (int o = 1; o < 1024; o <<= 1) {
        int t = (threadIdx.x >= o) ? sh[threadIdx.x - o] : 0;
        __syncthreads();
        sh[threadIdx.x] += t;
        __syncthreads();
    }
    if (i < n) out[i] = sh[threadIdx.x] - v;     // exclusive
    if (threadIdx.x == 1023) bsums[blockIdx.x] = sh[1023];
}

__global__ void scan2_kernel(int* bsums, int nb) {
    __shared__ int sh[1024];
    int v = (threadIdx.x < nb) ? bsums[threadIdx.x] : 0;
    sh[threadIdx.x] = v;
    __syncthreads();
#pragma unroll
    for (int o = 1; o < 1024; o <<= 1) {
        int t = (threadIdx.x >= o) ? sh[threadIdx.x - o] : 0;
        __syncthreads();
        sh[threadIdx.x] += t;
        __syncthreads();
    }
    if (threadIdx.x < nb) bsums[threadIdx.x] = sh[threadIdx.x] - v;  // exclusive
}

__global__ void scan3_kernel(int* __restrict__ out, const int* __restrict__ bsums,
                             const int* __restrict__ cnt, int n) {
    int i = blockIdx.x * 1024 + threadIdx.x;
    if (i < n) {
        int v = out[i] + bsums[i >> 10];
        out[i] = v;
        if (i == n - 1) out[n] = v + cnt[i];
    }
}

__global__ void fill_kernel(const int* __restrict__ key, const int* __restrict__ val,
                            int* cursor, int* __restrict__ ci, int n) {
    int i = blockIdx.x * 256 + threadIdx.x;
    if (i >= n) return;
    int pos = atomicAdd(&cursor[__ldg(key + i)], 1);
    ci[pos] = val ? __ldg(val + i) : i;
}

// ---------------- weight pack kernels (tf32 round + fragment permutation) ----------------
// float4 = { W[k][n], W[k+4][n], W[k][n+8], W[k+4][n+8] }, k = kt*32+ks*8+t

// H x H (gemm1 weights), m32n64 warp tile: [kt(8)][ks(4)][wN(4)][nf2(4)][lane(32)]
__global__ void pack256_kernel(const float* __restrict__ W, float* __restrict__ out, int nmat) {
    int gid = blockIdx.x * 256 + threadIdx.x;
    if (gid >= nmat * 16384) return;
    int m = gid >> 14, o = gid & 16383;
    int kt = o >> 11, i4 = o & 2047;
    int ks = i4 >> 9, r = i4 & 511;
    int wN = r >> 7, r2 = r & 127;
    int nf2 = r2 >> 5, lane = r2 & 31;
    int t = lane & 3, g = lane >> 2;
    int k = kt * 32 + ks * 8 + t;
    int n = wN * 64 + nf2 * 16 + g;
    const float* Wm = W + (size_t)m * 65536;
    float4 v;
    v.x = f2tf32f(Wm[k * 256 + n]);
    v.y = f2tf32f(Wm[(k + 4) * 256 + n]);
    v.z = f2tf32f(Wm[k * 256 + n + 8]);
    v.w = f2tf32f(Wm[(k + 4) * 256 + n + 8]);
    ((float4*)out)[gid] = v;
}

// w_ff1 [256, 1024]: [c(8)][kt(8)][ks(4)][wN(4)][nf2(2)][lane] float4
__global__ void packff1_kernel(const float* __restrict__ W, float* __restrict__ out, int nmat) {
    int gid = blockIdx.x * 256 + threadIdx.x;
    if (gid >= nmat * 65536) return;
    int m = gid >> 16, o = gid & 65535;
    int c = o >> 13, r = o & 8191;
    int kt = r >> 10, i4 = r & 1023;
    int ks = i4 >> 8, r2 = i4 & 255;
    int wN = r2 >> 6, r3 = r2 & 63;
    int nf2 = r3 >> 5, lane = r3 & 31;
    int t = lane & 3, g = lane >> 2;
    int k = kt * 32 + ks * 8 + t;
    int n = c * 128 + wN * 32 + nf2 * 16 + g;
    const float* Wm = W + (size_t)m * 262144;
    float4 v;
    v.x = f2tf32f(Wm[k * 1024 + n]);
    v.y = f2tf32f(Wm[(k + 4) * 1024 + n]);
    v.z = f2tf32f(Wm[k * 1024 + n + 8]);
    v.w = f2tf32f(Wm[(k + 4) * 1024 + n + 8]);
    ((float4*)out)[gid] = v;
}

// w_ff2 [1024, 256]: [c(8)][kt(4)][ks(4)][wN(4)][nf2(4)][lane] float4
__global__ void packff2_kernel(const float* __restrict__ W, float* __restrict__ out, int nmat) {
    int gid = blockIdx.x * 256 + threadIdx.x;
    if (gid >= nmat * 65536) return;
    int m = gid >> 16, o = gid & 65535;
    int c = o >> 13, r = o & 8191;
    int kt = r >> 11, i4 = r & 2047;
    int ks = i4 >> 9, r2 = i4 & 511;
    int wN = r2 >> 7, r3 = r2 & 127;
    int nf2 = r3 >> 5, lane = r3 & 31;
    int t = lane & 3, g = lane >> 2;
    int k = c * 128 + kt * 32 + ks * 8 + t;
    int n = wN * 64 + nf2 * 16 + g;
    const float* Wm = W + (size_t)m * 262144;
    float4 v;
    v.x = f2tf32f(Wm[k * 256 + n]);
    v.y = f2tf32f(Wm[(k + 4) * 256 + n]);
    v.z = f2tf32f(Wm[k * 256 + n + 8]);
    v.w = f2tf32f(Wm[(k + 4) * 256 + n + 8]);
    ((float4*)out)[gid] = v;
}

// ---------------- small kernels ----------------

__global__ void cvt_kernel(const float* __restrict__ in, float* __restrict__ out, int n4) {
    int i = blockIdx.x * 256 + threadIdx.x;
    if (i >= n4) return;
    float4 v = ((const float4*)in)[i];
    v.x = f2tf32f(v.x); v.y = f2tf32f(v.y); v.z = f2tf32f(v.z); v.w = f2tf32f(v.w);
    ((float4*)out)[i] = v;
}

__global__ void embed_kernel(const float* __restrict__ rel, const int* __restrict__ feat,
                             float* __restrict__ out) {
    int gid = blockIdx.x * blockDim.x + threadIdx.x;
    int e = gid >> 6;
    if (e >= NEDGE) return;
    int c = (gid & 63) << 2;
    int r = __ldg(feat + e);
    float4 v = *(const float4*)(rel + (size_t)r * H + c);
    v.x = f2tf32f(v.x); v.y = f2tf32f(v.y); v.z = f2tf32f(v.z); v.w = f2tf32f(v.w);
    *(float4*)(out + (size_t)e * H + c) = v;
}

__global__ void gather2_kernel(const float* __restrict__ x, const int* __restrict__ s,
                               const int* __restrict__ d, float* __restrict__ out, int n) {
    int gid = blockIdx.x * blockDim.x + threadIdx.x;
    int e = gid >> 6;
    if (e >= n) return;
    int c = (gid & 63) << 2;
    int si = __ldg(s + e), di = __ldg(d + e);
    float4 a = *(const float4*)(x + (size_t)si * H + c);
    float4 b = *(const float4*)(x + (size_t)di * H + c);
    a.x = f2tf32f(a.x + b.x); a.y = f2tf32f(a.y + b.y);
    a.z = f2tf32f(a.z + b.z); a.w = f2tf32f(a.w + b.w);
    *(float4*)(out + (size_t)e * H + c) = a;
}

// CSR gather segment-sum (2-way unrolled)
__global__ void segsum_kernel(const float* __restrict__ rows, const int* __restrict__ rp,
                              const int* __restrict__ ci, float* __restrict__ out, int nseg) {
    int row = blockIdx.x * 8 + (threadIdx.x >> 5);
    if (row >= nseg) return;
    int lane = threadIdx.x & 31;
    int beg = __ldg(rp + row), end = __ldg(rp + row + 1);
    float a[8] = {0.f, 0.f, 0.f, 0.f, 0.f, 0.f, 0.f, 0.f};
    float b[8] = {0.f, 0.f, 0.f, 0.f, 0.f, 0.f, 0.f, 0.f};
    int j = beg;
    for (; j + 1 < end; j += 2) {
        const float* p0 = rows + (size_t)__ldg(ci + j) * H + lane * 8;
        const float* p1 = rows + (size_t)__ldg(ci + j + 1) * H + lane * 8;
        float4 u0 = ((const float4*)p0)[0], u1 = ((const float4*)p0)[1];
        float4 w0 = ((const float4*)p1)[0], w1 = ((const float4*)p1)[1];
        a[0] += u0.x; a[1] += u0.y; a[2] += u0.z; a[3] += u0.w;
        a[4] += u1.x; a[5] += u1.y; a[6] += u1.z; a[7] += u1.w;
        b[0] += w0.x; b[1] += w0.y; b[2] += w0.z; b[3] += w0.w;
        b[4] += w1.x; b[5] += w1.y; b[6] += w1.z; b[7] += w1.w;
    }
    if (j < end) {
        const float* p0 = rows + (size_t)__ldg(ci + j) * H + lane * 8;
        float4 u0 = ((const float4*)p0)[0], u1 = ((const float4*)p0)[1];
        a[0] += u0.x; a[1] += u0.y; a[2] += u0.z; a[3] += u0.w;
        a[4] += u1.x; a[5] += u1.y; a[6] += u1.z; a[7] += u1.w;
    }
#pragma unroll
    for (int i = 0; i < 8; i++) a[i] = f2tf32f(a[i] + b[i]);
    float* po = out + (size_t)row * H + lane * 8;
    ((float4*)po)[0] = make_float4(a[0], a[1], a[2], a[3]);
    ((float4*)po)[1] = make_float4(a[4], a[5], a[6], a[7]);
}

// hop1 of layer-0 edge core: gather rel[feat[ci[j]]]
__global__ void segsum_rel_kernel(const float* __restrict__ rel, const int* __restrict__ feat,
                                  const int* __restrict__ rp, const int* __restrict__ ci,
                                  float* __restrict__ out, int nseg) {
    int row = blockIdx.x * 8 + (threadIdx.x >> 5);
    if (row >= nseg) return;
    int lane = threadIdx.x & 31;
    int beg = __ldg(rp + row), end = __ldg(rp + row + 1);
    float a[8] = {0.f, 0.f, 0.f, 0.f, 0.f, 0.f, 0.f, 0.f};
    for (int j = beg; j < end; j++) {
        int r = __ldg(feat + __ldg(ci + j));
        const float* p = rel + (size_t)r * H + lane * 8;
        float4 u0 = ((const float4*)p)[0], u1 = ((const float4*)p)[1];
        a[0] += f2tf32f(u0.x); a[1] += f2tf32f(u0.y);
        a[2] += f2tf32f(u0.z); a[3] += f2tf32f(u0.w);
        a[4] += f2tf32f(u1.x); a[5] += f2tf32f(u1.y);
        a[6] += f2tf32f(u1.z); a[7] += f2tf32f(u1.w);
    }
#pragma unroll
    for (int i = 0; i < 8; i++) a[i] = f2tf32f(a[i]);
    float* po = out + (size_t)row * H + lane * 8;
    ((float4*)po)[0] = make_float4(a[0], a[1], a[2], a[3]);
    ((float4*)po)[1] = make_float4(a[4], a[5], a[6], a[7]);
}

// ================= GEMM1 + LN1 fused, m32n64 warp tile, 1 sync/k-tile =================
#define G_ASTR 36
#define G_AST (64 * G_ASTR)       // 2304
#define G_BST 8192
#define G1_SMEM_FLOATS (2 * G_AST + 2 * G_BST + 3 * 256 + 2 * 256)
#define G1_SMEM_BYTES (G1_SMEM_FLOATS * 4)

struct G1Args {
    const float* A[6];
    const float* W[6];       // packed
    const float* Bias[6];
    const float* xres;
    const float* gamma;
    const float* beta;
};

__global__ void __launch_bounds__(256, 2)
gemm1_ln_kernel(G1Args args, int M, float* __restrict__ out) {
    extern __shared__ float sm[];
    float* As = sm;
    float* Bs = sm + 2 * G_AST;
    float* bias_s = Bs + 2 * G_BST;
    float* gs = bias_s + 256;
    float* bt = gs + 256;
    float* lnS = bt + 256;
    float* lnQ = lnS + 256;
    float* xs = sm;                 // alias; reused after mainloop, stride 264

    int tid = threadIdx.x;
    int bm = blockIdx.x * 64;

    {
        float b = 0.f;
#pragma unroll
        for (int j = 0; j < 6; j++) b += __ldg(args.Bias[j] + tid);
        bias_s[tid] = b;
        gs[tid] = __ldg(args.gamma + tid);
        bt[tid] = __ldg(args.beta + tid);
    }

    uint32_t a_base = (uint32_t)__cvta_generic_to_shared(As);
    uint32_t b_base = (uint32_t)__cvta_generic_to_shared(Bs);

    int warp = tid >> 5, lane = tid & 31, g = lane >> 2, t = lane & 3;
    int wm = (warp >> 2) * 32;    // 2 warps along M, 32 rows each
    int wN = warp & 3;            // 4 warps along N, 64 cols each
    int wn = wN * 64;

    float acc[2][8][4];
#pragma unroll
    for (int mt = 0; mt < 2; mt++)
#pragma unroll
        for (int nf = 0; nf < 8; nf++)
#pragma unroll
            for (int i = 0; i < 4; i++) acc[mt][nf][i] = 0.f;

    auto issue = [&](int tt, int buf) {
        int j = tt >> 3;
        int kk = (tt & 7) * 32;
        const float* A = args.A[j];
        const float4* Wp = (const float4*)args.W[j] + (size_t)(tt & 7) * 2048;
#pragma unroll
        for (int i = 0; i < 2; i++) {
            int idx = tid + i * 256;
            int r = idx >> 3, kv = (idx & 7) << 2;
            int row = bm + r;
            uint32_t dst = a_base + (uint32_t)((buf * G_AST + r * G_ASTR + kv) * 4);
            const float* src = A + (size_t)row * H + kk + kv;
            int sz = (row < M) ? 16 : 0;
            asm volatile("cp.async.cg.shared.global [%0], [%1], 16, %2;\n"
                         :: "r"(dst), "l"(src), "r"(sz));
        }
#pragma unroll
        for (int i = 0; i < 8; i++) {
            int idx = tid + i * 256;
            uint32_t dst = b_base + (uint32_t)((buf * G_BST + idx * 4) * 4);
            asm volatile("cp.async.cg.shared.global [%0], [%1], 16;\n"
                         :: "r"(dst), "l"(Wp + idx));
        }
        asm volatile("cp.async.commit_group;\n");
    };

    issue(0, 0);
    for (int tt = 0; tt < 48; tt++) {
        asm volatile("cp.async.wait_group 0;\n");
        __syncthreads();
        if (tt + 1 < 48) issue(tt + 1, (tt + 1) & 1);
        const float* Ab = As + (tt & 1) * G_AST;
        const float4* Bb4 = (const float4*)(Bs + (tt & 1) * G_BST) + wN * 128 + lane;
#pragma unroll
        for (int ks = 0; ks < 4; ks++) {
            int k0 = ks * 8;
            uint32_t a0[4], a1[4];
            a0[0] = __float_as_uint(Ab[(wm + g) * G_ASTR + k0 + t]);
            a0[1] = __float_as_uint(Ab[(wm + 8 + g) * G_ASTR + k0 + t]);
            a0[2] = __float_as_uint(Ab[(wm + g) * G_ASTR + k0 + t + 4]);
            a0[3] = __float_as_uint(Ab[(wm + 8 + g) * G_ASTR + k0 + t + 4]);
            a1[0] = __float_as_uint(Ab[(wm + 16 + g) * G_ASTR + k0 + t]);
            a1[1] = __float_as_uint(Ab[(wm + 24 + g) * G_ASTR + k0 + t]);
            a1[2] = __float_as_uint(Ab[(wm + 16 + g) * G_ASTR + k0 + t + 4]);
            a1[3] = __float_as_uint(Ab[(wm + 24 + g) * G_ASTR + k0 + t + 4]);
#pragma unroll
            for (int nf2 = 0; nf2 < 4; nf2++) {
                float4 bv = Bb4[ks * 512 + nf2 * 32];
                uint32_t b0[2] = {__float_as_uint(bv.x), __float_as_uint(bv.y)};
                mma_tf32(acc[0][2 * nf2], a0, b0);
                mma_tf32(acc[1][2 * nf2], a1, b0);
                uint32_t b1[2] = {__float_as_uint(bv.z), __float_as_uint(bv.w)};
                mma_tf32(acc[0][2 * nf2 + 1], a0, b1);
                mma_tf32(acc[1][2 * nf2 + 1], a1, b1);
            }
        }
    }
    __syncthreads();   // mainloop reads done before xs alias reuse

    // cooperative residual tile load into xs (stride 264)
#pragma unroll
    for (int i = 0; i < 16; i++) {
        int idx = tid + i * 256;
        int r = idx >> 6, cv = (idx & 63) << 2;
        int row = bm + r;
        float4 v = make_float4(0.f, 0.f, 0.f, 0.f);
        if (row < M) v = *(const float4*)(args.xres + (size_t)row * H + cv);
        *(float4*)(xs + r * 264 + cv) = v;
    }
    __syncthreads();

    // bias+gelu+residual, per-row partial sums
#pragma unroll
    for (int mt = 0; mt < 2; mt++) {
#pragma unroll
        for (int h = 0; h < 2; h++) {
            int row = wm + mt * 16 + h * 8 + g;
            float s = 0.f, q = 0.f;
#pragma unroll
            for (int nf = 0; nf < 8; nf++) {
                int col = wn + nf * 8 + 2 * t;
                float v0 = xs[row * 264 + col]     + gelu_exact(acc[mt][nf][2 * h]     + bias_s[col]);
                float v1 = xs[row * 264 + col + 1] + gelu_exact(acc[mt][nf][2 * h + 1] + bias_s[col + 1]);
                acc[mt][nf][2 * h] = v0; acc[mt][nf][2 * h + 1] = v1;
                s += v0 + v1; q += v0 * v0 + v1 * v1;
            }
#pragma unroll
            for (int o = 1; o <= 2; o <<= 1) {
                s += __shfl_xor_sync(0xffffffffu, s, o);
                q += __shfl_xor_sync(0xffffffffu, q, o);
            }
            if (t == 0) { lnS[row * 4 + wN] = s; lnQ[row * 4 + wN] = q; }
        }
    }
    __syncthreads();
#pragma unroll
    for (int mt = 0; mt < 2; mt++) {
#pragma unroll
        for (int h = 0; h < 2; h++) {
            int row = wm + mt * 16 + h * 8 + g;
            float S = lnS[row * 4] + lnS[row * 4 + 1] + lnS[row * 4 + 2] + lnS[row * 4 + 3];
            float Q = lnQ[row * 4] + lnQ[row * 4 + 1] + lnQ[row * 4 + 2] + lnQ[row * 4 + 3];
            float m = S * (1.f / H), v = Q * (1.f / H) - m * m, rs = rsqrtf(v + 1e-5f);
            if (bm + row < M) {
#pragma unroll
                for (int nf = 0; nf < 8; nf++) {
                    int col = wn + nf * 8 + 2 * t;
                    float o0 = f2tf32f((acc[mt][nf][2 * h]     - m) * rs * gs[col]     + bt[col]);
                    float o1 = f2tf32f((acc[mt][nf][2 * h + 1] - m) * rs * gs[col + 1] + bt[col + 1]);
                    *(float2*)(out + (size_t)(bm + row) * H + col) = make_float2(o0, o1);
                }
            }
        }
    }
}

// ================= fused FFN + LN2, 1 sync/k-tile =================
#define F_XSTR 260
#define F_HSTR 132
#define F_B1ST 4096
#define F_B2ST 8192
#define F_SMEM_FLOATS (64 * F_XSTR + 64 * F_HSTR + 2 * F_B2ST + 3 * 256 + 128 + 2 * 256)
#define F_SMEM_BYTES (F_SMEM_FLOATS * 4)

struct FArgs {
    const float* w1;    // packed
    const float* b1;
    const float* w2;    // packed
    const float* b2;
    const float* gamma;
    const float* beta;
};

__global__ void __launch_bounds__(512, 1)
ffn_kernel(FArgs args, int M, const float* __restrict__ in1,
           float* __restrict__ out, int out_cvt) {
    extern __shared__ float sm[];
    float* xs  = sm;
    float* hb  = xs + 64 * F_XSTR;
    float* Bst = hb + 64 * F_HSTR;
    float* b2s = Bst + 2 * F_B2ST;
    float* gs  = b2s + 256;
    float* bt  = gs + 256;
    float* b1c = bt + 256;
    float* lnS = b1c + 128;
    float* lnQ = lnS + 256;

    int tid = threadIdx.x;
    int bm = blockIdx.x * 64;

    if (tid < 256) {
        b2s[tid] = __ldg(args.b2 + tid);
        gs[tid]  = __ldg(args.gamma + tid);
        bt[tid]  = __ldg(args.beta + tid);
    }
#pragma unroll
    for (int i = 0; i < 8; i++) {
        int idx = tid + i * 512;
        int r = idx >> 6, cv = (idx & 63) << 2;
        int row = bm + r;
        float4 v = make_float4(0.f, 0.f, 0.f, 0.f);
        if (row < M) v = *(const float4*)(in1 + (size_t)row * H + cv);
        *(float4*)(xs + r * F_XSTR + cv) = v;
    }

    uint32_t bst_base = (uint32_t)__cvta_generic_to_shared(Bst);
    int warp = tid >> 5, lane = tid & 31, g = lane >> 2, t = lane & 3;
    int wm = (warp >> 2) * 16;
    int wN = warp & 3;
    int wn1 = wN * 32;
    int wn2 = wN * 64;

    float acc2[8][4];
#pragma unroll
    for (int nf = 0; nf < 8; nf++)
#pragma unroll
        for (int i = 0; i < 4; i++) acc2[nf][i] = 0.f;

    __syncthreads();

    for (int c = 0; c < 8; c++) {
        // protect Bst (read by prior chunk's stage2) and b1c before overwrite
        if (c > 0) __syncthreads();
        if (tid < 128) b1c[tid] = __ldg(args.b1 + c * 128 + tid);

        float acc1[4][4];
#pragma unroll
        for (int nf = 0; nf < 4; nf++)
#pragma unroll
            for (int i = 0; i < 4; i++) acc1[nf][i] = 0.f;

        const float4* W1p = (const float4*)args.w1 + (size_t)c * 8192;
        auto issue1 = [&](int kt, int buf) {
#pragma unroll
            for (int i = 0; i < 2; i++) {
                int idx = tid + i * 512;
                uint32_t dst = bst_base + (uint32_t)((buf * F_B1ST + idx * 4) * 4);
                asm volatile("cp.async.cg.shared.global [%0], [%1], 16;\n"
                             :: "r"(dst), "l"(W1p + kt * 1024 + idx));
            }
            asm volatile("cp.async.commit_group;\n");
        };

        issue1(0, 0);
        for (int kt = 0; kt < 8; kt++) {
            asm volatile("cp.async.wait_group 0;\n");
            __syncthreads();
            if (kt + 1 < 8) issue1(kt + 1, (kt + 1) & 1);
            const float4* Bb4 = (const float4*)(Bst + (kt & 1) * F_B1ST) + wN * 64 + lane;
            int kk = kt * 32;
#pragma unroll
            for (int ks = 0; ks < 4; ks++) {
                int kg = kk + ks * 8;
                uint32_t a[4];
                a[0] = __float_as_uint(xs[(wm + g) * F_XSTR + kg + t]);
                a[1] = __float_as_uint(xs[(wm + 8 + g) * F_XSTR + kg + t]);
                a[2] = __float_as_uint(xs[(wm + g) * F_XSTR + kg + t + 4]);
                a[3] = __float_as_uint(xs[(wm + 8 + g) * F_XSTR + kg + t + 4]);
#pragma unroll
                for (int nf2 = 0; nf2 < 2; nf2++) {
                    float4 bv = Bb4[ks * 256 + nf2 * 32];
                    uint32_t b0[2] = {__float_as_uint(bv.x), __float_as_uint(bv.y)};
                    mma_tf32(acc1[2 * nf2], a, b0);
                    uint32_t b1[2] = {__float_as_uint(bv.z), __float_as_uint(bv.w)};
                    mma_tf32(acc1[2 * nf2 + 1], a, b1);
                }
            }
        }

        // h = tf32(gelu(acc1 + b1)) -> hb (each warp writes its own region)
#pragma unroll
        for (int nf = 0; nf < 4; nf++) {
            int col = wn1 + nf * 8 + 2 * t;
            float h0 = f2tf32f(gelu_exact(acc1[nf][0] + b1c[col]));
            float h1 = f2tf32f(gelu_exact(acc1[nf][1] + b1c[col + 1]));
            float h2 = f2tf32f(gelu_exact(acc1[nf][2] + b1c[col]));
            float h3 = f2tf32f(gelu_exact(acc1[nf][3] + b1c[col + 1]));
            *(float2*)(hb + (wm + g) * F_HSTR + col)     = make_float2(h0, h1);
            *(float2*)(hb + (wm + 8 + g) * F_HSTR + col) = make_float2(h2, h3);
        }
        __syncthreads();   // hb visible + stage1 Bst reads done

        const float4* W2p = (const float4*)args.w2 + (size_t)c * 8192;
        auto issue2 = [&](int kt, int buf) {
#pragma unroll
            for (int i = 0; i < 4; i++) {
                int idx = tid + i * 512;
                uint32_t dst = bst_base + (uint32_t)((buf * F_B2ST + idx * 4) * 4);
                asm volatile("cp.async.cg.shared.global [%0], [%1], 16;\n"
                             :: "r"(dst), "l"(W2p + kt * 2048 + idx));
            }
            asm volatile("cp.async.commit_group;\n");
        };

        issue2(0, 0);
        for (int kt = 0; kt < 4; kt++) {
            asm volatile("cp.async.wait_group 0;\n");
            __syncthreads();
            if (kt + 1 < 4) issue2(kt + 1, (kt + 1) & 1);
            const float4* Bb4 = (const float4*)(Bst + (kt & 1) * F_B2ST) + wN * 128 + lane;
            int kk = kt * 32;
#pragma unroll
            for (int ks = 0; ks < 4; ks++) {
                int kg = kk + ks * 8;
                uint32_t a[4];
                a[0] = __float_as_uint(hb[(wm + g) * F_HSTR + kg + t]);
                a[1] = __float_as_uint(hb[(wm + 8 + g) * F_HSTR + kg + t]);
                a[2] = __float_as_uint(hb[(wm + g) * F_HSTR + kg + t + 4]);
                a[3] = __float_as_uint(hb[(wm + 8 + g) * F_HSTR + kg + t + 4]);
#pragma unroll
                for (int nf2 = 0; nf2 < 4; nf2++) {
                    float4 bv = Bb4[ks * 512 + nf2 * 32];
                    uint32_t b0[2] = {__float_as_uint(bv.x), __float_as_uint(bv.y)};
                    mma_tf32(acc2[2 * nf2], a, b0);
                    uint32_t b1[2] = {__float_as_uint(bv.z), __float_as_uint(bv.w)};
                    mma_tf32(acc2[2 * nf2 + 1], a, b1);
                }
            }
        }
    }

    // LN2 epilogue
    int row0 = wm + g, row1 = wm + 8 + g;
    float s0 = 0.f, q0 = 0.f, s1 = 0.f, q1 = 0.f;
#pragma unroll
    for (int nf = 0; nf < 8; nf++) {
        int col = wn2 + nf * 8 + 2 * t;
        float t0 = xs[row0 * F_XSTR + col]     + acc2[nf][0] + b2s[col];
        float t1 = xs[row0 * F_XSTR + col + 1] + acc2[nf][1] + b2s[col + 1];
        float t2 = xs[row1 * F_XSTR + col]     + acc2[nf][2] + b2s[col];
        float t3 = xs[row1 * F_XSTR + col + 1] + acc2[nf][3] + b2s[col + 1];
        acc2[nf][0] = t0; acc2[nf][1] = t1; acc2[nf][2] = t2; acc2[nf][3] = t3;
        s0 += t0 + t1; q0 += t0 * t0 + t1 * t1;
        s1 += t2 + t3; q1 += t2 * t2 + t3 * t3;
    }
#pragma unroll
    for (int o = 1; o <= 2; o <<= 1) {
        s0 += __shfl_xor_sync(0xffffffffu, s0, o);
        q0 += __shfl_xor_sync(0xffffffffu, q0, o);
        s1 += __shfl_xor_sync(0xffffffffu, s1, o);
        q1 += __shfl_xor_sync(0xffffffffu, q1, o);
    }
    if (t == 0) {
        lnS[row0 * 4 + wN] = s0; lnQ[row0 * 4 + wN] = q0;
        lnS[row1 * 4 + wN] = s1; lnQ[row1 * 4 + wN] = q1;
    }
    __syncthreads();
    float S0 = lnS[row0 * 4] + lnS[row0 * 4 + 1] + lnS[row0 * 4 + 2] + lnS[row0 * 4 + 3];
    float Q0 = lnQ[row0 * 4] + lnQ[row0 * 4 + 1] + lnQ[row0 * 4 + 2] + lnQ[row0 * 4 + 3];
    float S1 = lnS[row1 * 4] + lnS[row1 * 4 + 1] + lnS[row1 * 4 + 2] + lnS[row1 * 4 + 3];
    float Q1 = lnQ[row1 * 4] + lnQ[row1 * 4 + 1] + lnQ[row1 * 4 + 2] + lnQ[row1 * 4 + 3];
    float m0 = S0 * (1.f / H), v0 = Q0 * (1.f / H) - m0 * m0, r0 = rsqrtf(v0 + 1e-5f);
    float m1 = S1 * (1.f / H), v1 = Q1 * (1.f / H) - m1 * m1, r1 = rsqrtf(v1 + 1e-5f);
    bool ok0 = (bm + row0) < M, ok1 = (bm + row1) < M;
#pragma unroll
    for (int nf = 0; nf < 8; nf++) {
        int col = wn2 + nf * 8 + 2 * t;
        float o0 = (acc2[nf][0] - m0) * r0 * gs[col]     + bt[col];
        float o1 = (acc2[nf][1] - m0) * r0 * gs[col + 1] + bt[col + 1];
        float o2 = (acc2[nf][2] - m1) * r1 * gs[col]     + bt[col];
        float o3 = (acc2[nf][3] - m1) * r1 * gs[col + 1] + bt[col + 1];
        if (out_cvt) {
            o0 = f2tf32f(o0); o1 = f2tf32f(o1);
            o2 = f2tf32f(o2); o3 = f2tf32f(o3);
        }
        if (ok0) *(float2*)(out + (size_t)(bm + row0) * H + col) = make_float2(o0, o1);
        if (ok1) *(float2*)(out + (size_t)(bm + row1) * H + col) = make_float2(o2, o3);
    }
}

// ---------------- host orchestration ----------------

struct Net {
    const float *b_self, *b_khop, *b_fuse, *b_ff1, *b_ff2;
    const float *ln1g, *ln1b, *ln2g, *ln2b;
    float* wbuf;
};

static void run_core(const Net& n, int l, int c, int M, float* const* z,
                     const float* xin, const float* fused, float* out1buf,
                     float* outp, int cvt_final, cudaStream_t st) {
    size_t lc = (size_t)(l * 2 + c);
    G1Args ga;
    ga.A[0] = xin;
    ga.W[0] = n.wbuf + OFF_WSELF + lc * H * H;
    ga.Bias[0] = n.b_self + lc * H;
    for (int i = 0; i < 4; i++) {
        ga.A[1 + i] = z[i];
        ga.W[1 + i] = n.wbuf + OFF_WKHOP + (lc * 4 + i) * (size_t)H * H;
        ga.Bias[1 + i] = n.b_khop + (lc * 4 + i) * (size_t)H;
    }
    ga.A[5] = fused;
    ga.W[5] = n.wbuf + OFF_WFUSE + lc * H * H;
    ga.Bias[5] = n.b_fuse + lc * H;
    ga.xres = xin;
    ga.gamma = n.ln1g + lc * H;
    ga.beta  = n.ln1b + lc * H;

    int grid = (M + 63) / 64;
    gemm1_ln_kernel<<<grid, 256, G1_SMEM_BYTES, st>>>(ga, M, out1buf);

    FArgs fa;
    fa.w1 = n.wbuf + OFF_WFF1 + lc * (size_t)H * FH;
    fa.b1 = n.b_ff1 + lc * FH;
    fa.w2 = n.wbuf + OFF_WFF2 + lc * (size_t)FH * H;
    fa.b2 = n.b_ff2 + lc * H;
    fa.gamma = n.ln2g + lc * H;
    fa.beta  = n.ln2b + lc * H;
    ffn_kernel<<<grid, 512, F_SMEM_BYTES, st>>>(fa, M, out1buf, outp, cvt_final);
}

static void exclusive_scan(int* cnt, int* rp, int* bsums, int n, cudaStream_t st) {
    int nb = (n + 1023) / 1024;
    scan1_kernel<<<nb, 1024, 0, st>>>(cnt, rp, bsums, n);
    scan2_kernel<<<1, 1024, 0, st>>>(bsums, nb);
    scan3_kernel<<<nb, 1024, 0, st>>>(rp, bsums, cnt, n);
}

extern "C" void kernel_launch(void* const* d_in, const int* in_sizes, int n_in,
                              void* d_out, int out_size) {
    const float* x_in = (const float*)d_in[0];
    const int* feat   = (const int*)d_in[1];
    const int* eig    = (const int*)d_in[2];
    const int* eil    = (const int*)d_in[3];
    const float* rel  = (const float*)d_in[4];

    const float* w_self = (const float*)d_in[5];
    const float* w_khop = (const float*)d_in[7];
    const float* w_fuse = (const float*)d_in[9];
    const float* w_ff1  = (const float*)d_in[11];
    const float* w_ff2  = (const float*)d_in[13];

    Net n;
    n.b_self = (const float*)d_in[6];
    n.b_khop = (const float*)d_in[8];
    n.b_fuse = (const float*)d_in[10];
    n.b_ff1  = (const float*)d_in[12];
    n.b_ff2  = (const float*)d_in[14];
    n.ln1g   = (const float*)d_in[15]; n.ln1b = (const float*)d_in[16];
    n.ln2g   = (const float*)d_in[17]; n.ln2b = (const float*)d_in[18];

    cudaFuncSetAttribute(gemm1_ln_kernel,
                         cudaFuncAttributeMaxDynamicSharedMemorySize, G1_SMEM_BYTES);
    cudaFuncSetAttribute(ffn_kernel,
                         cudaFuncAttributeMaxDynamicSharedMemorySize, F_SMEM_BYTES);

    // side stream + events (created once, outside capture on the first call)
    static cudaStream_t s2 = nullptr;
    static cudaEvent_t ev_start, ev_prep, ev_x0, ev_lg0, ev_fin;
    if (!s2) {
        cudaStreamCreateWithFlags(&s2, cudaStreamNonBlocking);
        cudaEventCreateWithFlags(&ev_start, cudaEventDisableTiming);
        cudaEventCreateWithFlags(&ev_prep,  cudaEventDisableTiming);
        cudaEventCreateWithFlags(&ev_x0,    cudaEventDisableTiming);
        cudaEventCreateWithFlags(&ev_lg0,   cudaEventDisableTiming);
        cudaEventCreateWithFlags(&ev_fin,   cudaEventDisableTiming);
    }

    float *px0, *plg0, *pfn, *pfe, *pzbase, *pznb, *pout1, *pout1n, *pwbuf;
    int *rp_nd, *ci_nd, *rp_fn, *ci_fn, *rp_lg, *ci_lg;
    int *pcnt, *pcur, *pbs, *pcnt2, *pcur2, *pbs2;
    cudaGetSymbolAddress((void**)&px0,   g_x);
    cudaGetSymbolAddress((void**)&plg0,  g_lg);
    cudaGetSymbolAddress((void**)&pfn,   g_fn);
    cudaGetSymbolAddress((void**)&pfe,   g_fe);
    cudaGetSymbolAddress((void**)&pzbase,g_z);
    cudaGetSymbolAddress((void**)&pznb,  g_zn);
    cudaGetSymbolAddress((void**)&pout1, g_out1);
    cudaGetSymbolAddress((void**)&pout1n,g_out1n);
    cudaGetSymbolAddress((void**)&pwbuf, g_wbuf);
    cudaGetSymbolAddress((void**)&rp_nd, g_rp_nd);
    cudaGetSymbolAddress((void**)&ci_nd, g_ci_nd);
    cudaGetSymbolAddress((void**)&rp_fn, g_rp_fn);
    cudaGetSymbolAddress((void**)&ci_fn, g_ci_fn);
    cudaGetSymbolAddress((void**)&rp_lg, g_rp_lg);
    cudaGetSymbolAddress((void**)&ci_lg, g_ci_lg);
    cudaGetSymbolAddress((void**)&pcnt,  g_cnt);
    cudaGetSymbolAddress((void**)&pcur,  g_cur);
    cudaGetSymbolAddress((void**)&pbs,   g_bs);
    cudaGetSymbolAddress((void**)&pcnt2, g_cnt2);
    cudaGetSymbolAddress((void**)&pcur2, g_cur2);
    cudaGetSymbolAddress((void**)&pbs2,  g_bs2);

    n.wbuf = pwbuf;
    float* px[2]  = {px0,  px0  + (size_t)NNODE * H};
    float* plg[2] = {plg0, plg0 + (size_t)NEDGE * H};
    float* ze[4], * zn[4];
    for (int i = 0; i < 4; i++) {
        ze[i] = pzbase + (size_t)i * NEDGE * H;
        zn[i] = pznb + (size_t)i * NNODE * H;
    }

    const int* src_g = eig;  const int* dst_g = eig + NEDGE;
    const int* src_l = eil;  const int* dst_l = eil + NLG;

    // fork point for capture
    cudaEventRecord(ev_start, 0);
    cudaStreamWaitEvent(s2, ev_start, 0);

    // ===== stream s2: packs + init + gather2-l0 (prereqs for edge core l0) =====
    cvt_kernel<<<(NNODE * H / 4 + 255) / 256, 256, 0, s2>>>(x_in, px[0], NNODE * H / 4);
    embed_kernel<<<NEDGE * 64 / 256, 256, 0, s2>>>(rel, feat, plg[0]);
    pack256_kernel<<<(4 * 16384 + 255) / 256, 256, 0, s2>>>(w_self, pwbuf + OFF_WSELF, 4);
    pack256_kernel<<<(16 * 16384 + 255) / 256, 256, 0, s2>>>(w_khop, pwbuf + OFF_WKHOP, 16);
    pack256_kernel<<<(4 * 16384 + 255) / 256, 256, 0, s2>>>(w_fuse, pwbuf + OFF_WFUSE, 4);
    packff1_kernel<<<(4 * 65536 + 255) / 256, 256, 0, s2>>>(w_ff1, pwbuf + OFF_WFF1, 4);
    packff2_kernel<<<(4 * 65536 + 255) / 256, 256, 0, s2>>>(w_ff2, pwbuf + OFF_WFF2, 4);
    gather2_kernel<<<NEDGE * 64 / 256, 256, 0, s2>>>(px[0], src_g, dst_g, pfe, NEDGE);
    cudaEventRecord(ev_prep, s2);

    // ===== stream s2 (continued): node CSRs + node core layer 0 =====
    cudaMemsetAsync(pcnt2, 0, NNODE * sizeof(int), s2);
    hist_kernel<<<(NEDGE + 255) / 256, 256, 0, s2>>>(dst_g, pcnt2, NEDGE);
    exclusive_scan(pcnt2, rp_nd, pbs2, NNODE, s2);
    cudaMemcpyAsync(pcur2, rp_nd, NNODE * sizeof(int), cudaMemcpyDeviceToDevice, s2);
    fill_kernel<<<(NEDGE + 255) / 256, 256, 0, s2>>>(dst_g, src_g, pcur2, ci_nd, NEDGE);

    cudaMemsetAsync(pcnt2, 0, NNODE * sizeof(int), s2);
    hist_kernel<<<(NEDGE + 255) / 256, 256, 0, s2>>>(src_g, pcnt2, NEDGE);
    hist_kernel<<<(NEDGE + 255) / 256, 256, 0, s2>>>(dst_g, pcnt2, NEDGE);
    exclusive_scan(pcnt2, rp_fn, pbs2, NNODE, s2);
    cudaMemcpyAsync(pcur2, rp_fn, NNODE * sizeof(int), cudaMemcpyDeviceToDevice, s2);
    fill_kernel<<<(NEDGE + 255) / 256, 256, 0, s2>>>(src_g, nullptr, pcur2, ci_fn, NEDGE);
    fill_kernel<<<(NEDGE + 255) / 256, 256, 0, s2>>>(dst_g, nullptr, pcur2, ci_fn, NEDGE);

    segsum_kernel<<<(NNODE + 7) / 8, 256, 0, s2>>>(plg[0], rp_fn, ci_fn, pfn, NNODE);
    {
        const float* prev = px[0];
        for (int i = 0; i < 4; i++) {
            segsum_kernel<<<(NNODE + 7) / 8, 256, 0, s2>>>(prev, rp_nd, ci_nd, zn[i], NNODE);
            prev = zn[i];
        }
    }
    run_core(n, 0, 0, NNODE, zn, px[0], pfn, pout1n, px[1], 1, s2);
    cudaEventRecord(ev_x0, s2);

    // ===== stream 0: lg CSR + layer-0 edge khops =====
    cudaMemsetAsync(pcnt, 0, NEDGE * sizeof(int), 0);
    hist_kernel<<<(NLG + 255) / 256, 256>>>(dst_l, pcnt, NLG);
    exclusive_scan(pcnt, rp_lg, pbs, NEDGE, 0);
    cudaMemcpyAsync(pcur, rp_lg, NEDGE * sizeof(int), cudaMemcpyDeviceToDevice, 0);
    fill_kernel<<<(NLG + 255) / 256, 256>>>(dst_l, src_l, pcur, ci_lg, NLG);

    segsum_rel_kernel<<<(NEDGE + 7) / 8, 256>>>(rel, feat, rp_lg, ci_lg, ze[0], NEDGE);
    segsum_kernel<<<(NEDGE + 7) / 8, 256>>>(ze[0], rp_lg, ci_lg, ze[1], NEDGE);
    segsum_kernel<<<(NEDGE + 7) / 8, 256>>>(ze[1], rp_lg, ci_lg, ze[2], NEDGE);
    segsum_kernel<<<(NEDGE + 7) / 8, 256>>>(ze[2], rp_lg, ci_lg, ze[3], NEDGE);

    // ===== stream 0: edge core, layer 0 (needs packs/embed/gather2 from s2) =====
    cudaStreamWaitEvent(0, ev_prep, 0);
    run_core(n, 0, 1, NEDGE, ze, plg[0], pfe, pout1, plg[1], 1, (cudaStream_t)0);
    cudaEventRecord(ev_lg0, 0);

    // ===== stream s2: node core, layer 1 =====
    cudaStreamWaitEvent(s2, ev_lg0, 0);
    segsum_kernel<<<(NNODE + 7) / 8, 256, 0, s2>>>(plg[1], rp_fn, ci_fn, pfn, NNODE);
    {
        const float* prev = px[1];
        for (int i = 0; i < 4; i++) {
            segsum_kernel<<<(NNODE + 7) / 8, 256, 0, s2>>>(prev, rp_nd, ci_nd, zn[i], NNODE);
            prev = zn[i];
        }
    }
    run_core(n, 1, 0, NNODE, zn, px[1], pfn, pout1n, (float*)d_out, 0, s2);
    cudaEventRecord(ev_fin, s2);

    // ===== stream 0: edge core, layer 1 =====
    cudaStreamWaitEvent(0, ev_x0, 0);
    gather2_kernel<<<NEDGE * 64 / 256, 256>>>(px[1], src_g, dst_g, pfe, NEDGE);
    {
        const float* prev = plg[1];
        for (int i = 0; i < 4; i++) {
            segsum_kernel<<<(NEDGE + 7) / 8, 256>>>(prev, rp_lg, ci_lg, ze[i], NEDGE);
            prev = ze[i];
        }
    }
    run_core(n, 1, 1, NEDGE, ze, plg[1], pfe, pout1,
             (float*)d_out + (size_t)NNODE * H, 0, (cudaStream_t)0);

    cudaStreamWaitEvent(0, ev_fin, 0);
    (void)in_sizes; (void)n_in; (void)out_size;
}

// round 11
// speedup vs baseline: 1.6256x; 1.5634x over previous
#include <cuda_runtime.h>
#include <cuda_fp16.h>
#include <cstdint>
#include <math.h>

#define H       256
#define FH      1024
#define NNODE   20000
#define NEDGE   160000
#define NLG     640000

// ---------------- scratch (static device memory; no allocations) ----------------
__device__ __half h_x[2][(size_t)NNODE * H];
__device__ __half h_lg[2][(size_t)NEDGE * H];
__device__ __half h_fn[(size_t)NNODE * H];
__device__ __half h_fe[(size_t)NEDGE * H];
__device__ __half h_z[4][(size_t)NEDGE * H];
__device__ __half h_zn[4][(size_t)NNODE * H];
__device__ __half h_out1[(size_t)NEDGE * H];
__device__ __half h_out1n[(size_t)NNODE * H];

// packed fp16 weights (fragment order for mma.m16n8k16)
#define OFFH_WSELF 0
#define OFFH_WKHOP (OFFH_WSELF + 4 * 65536)
#define OFFH_WFUSE (OFFH_WKHOP + 16 * 65536)
#define OFFH_WFF1  (OFFH_WFUSE + 4 * 65536)
#define OFFH_WFF2  (OFFH_WFF1 + 4 * 262144)
#define WBUFH_TOT  (OFFH_WFF2 + 4 * 262144)
__device__ __half g_wbufh[WBUFH_TOT];

// CSR structures
__device__ int g_rp_nd[NNODE + 1];
__device__ int g_ci_nd[NEDGE];
__device__ int g_rp_fn[NNODE + 1];
__device__ int g_ci_fn[2 * NEDGE];
__device__ int g_rp_lg[NEDGE + 1];
__device__ int g_ci_lg[NLG];
__device__ int g_cnt[NEDGE];
__device__ int g_cur[NEDGE];
__device__ int g_bs[1024];
__device__ int g_cnt2[NNODE];
__device__ int g_cur2[NNODE];
__device__ int g_bs2[1024];

__device__ __forceinline__ float gelu_exact(float v) {
    return 0.5f * v * (1.0f + erff(v * 0.70710678118654752f));
}

__device__ __forceinline__ uint32_t pkh2(float a, float b) {
    __half2 h = __floats2half2_rn(a, b);
    return *(uint32_t*)&h;
}
__device__ __forceinline__ float2 uph2(uint32_t u) {
    __half2 h = *(__half2*)&u;
    return __half22float2(h);
}
__device__ __forceinline__ uint32_t pk2(float a, float b) { return pkh2(a, b); }

__device__ __forceinline__ void mma_f16(float* c, const uint32_t* a, const uint32_t* b) {
    asm volatile(
        "mma.sync.aligned.m16n8k16.row.col.f32.f16.f16.f32 "
        "{%0,%1,%2,%3}, {%4,%5,%6,%7}, {%8,%9}, {%0,%1,%2,%3};"
        : "+f"(c[0]), "+f"(c[1]), "+f"(c[2]), "+f"(c[3])
        : "r"(a[0]), "r"(a[1]), "r"(a[2]), "r"(a[3]), "r"(b[0]), "r"(b[1]));
}

// ---------------- CSR build kernels ----------------

__global__ void hist_kernel(const int* __restrict__ key, int* cnt, int n) {
    int i = blockIdx.x * 256 + threadIdx.x;
    if (i < n) atomicAdd(&cnt[__ldg(key + i)], 1);
}

__global__ void scan1_kernel(const int* __restrict__ in, int* __restrict__ out,
                             int* __restrict__ bsums, int n) {
    __shared__ int sh[1024];
    int i = blockIdx.x * 1024 + threadIdx.x;
    int v = (i < n) ? in[i] : 0;
    sh[threadIdx.x] = v;
    __syncthreads();
#pragma unroll
    for (int o = 1; o < 1024; o <<= 1) {
        int t = (threadIdx.x >= o) ? sh[threadIdx.x - o] : 0;
        __syncthreads();
        sh[threadIdx.x] += t;
        __syncthreads();
    }
    if (i < n) out[i] = sh[threadIdx.x] - v;
    if (threadIdx.x == 1023) bsums[blockIdx.x] = sh[1023];
}

__global__ void scan2_kernel(int* bsums, int nb) {
    __shared__ int sh[1024];
    int v = (threadIdx.x < nb) ? bsums[threadIdx.x] : 0;
    sh[threadIdx.x] = v;
    __syncthreads();
#pragma unroll
    for (int o = 1; o < 1024; o <<= 1) {
        int t = (threadIdx.x >= o) ? sh[threadIdx.x - o] : 0;
        __syncthreads();
        sh[threadIdx.x] += t;
        __syncthreads();
    }
    if (threadIdx.x < nb) bsums[threadIdx.x] = sh[threadIdx.x] - v;
}

__global__ void scan3_kernel(int* __restrict__ out, const int* __restrict__ bsums,
                             const int* __restrict__ cnt, int n) {
    int i = blockIdx.x * 1024 + threadIdx.x;
    if (i < n) {
        int v = out[i] + bsums[i >> 10];
        out[i] = v;
        if (i == n - 1) out[n] = v + cnt[i];
    }
}

__global__ void fill_kernel(const int* __restrict__ key, const int* __restrict__ val,
                            int* cursor, int* __restrict__ ci, int n) {
    int i = blockIdx.x * 256 + threadIdx.x;
    if (i >= n) return;
    int pos = atomicAdd(&cursor[__ldg(key + i)], 1);
    ci[pos] = val ? __ldg(val + i) : i;
}

// ---------------- weight pack kernels (f32 -> fp16, m16n8k16 B-fragment order) --------
// Per (kstep s of 16, n8-pair) a lane's uint4 = {b0(n0), b1(n0), b0(n1), b1(n1)} where
// b0 = h2(W[k+2t][n], W[k+2t+1][n]), b1 = h2(W[k+2t+8][n], W[k+2t+9][n]), n1 = n0+8.

// H x H (gemm1): per matrix [kt(8)][s(2)][wN(4)][nf4(4)][lane(32)] uint4
__global__ void pack256_kernel(const float* __restrict__ W, __half* __restrict__ out, int nmat) {
    int gid = blockIdx.x * 256 + threadIdx.x;
    if (gid >= nmat * 8192) return;
    int m = gid >> 13, o = gid & 8191;
    int kt = o >> 10, s = (o >> 9) & 1, wN = (o >> 7) & 3, nf4 = (o >> 5) & 3, lane = o & 31;
    int t = lane & 3, g = lane >> 2;
    int k = kt * 32 + s * 16 + 2 * t;
    int n0 = wN * 64 + nf4 * 16 + g, n1 = n0 + 8;
    const float* Wm = W + (size_t)m * 65536;
    uint4 v;
    v.x = pk2(Wm[k * 256 + n0], Wm[(k + 1) * 256 + n0]);
    v.y = pk2(Wm[(k + 8) * 256 + n0], Wm[(k + 9) * 256 + n0]);
    v.z = pk2(Wm[k * 256 + n1], Wm[(k + 1) * 256 + n1]);
    v.w = pk2(Wm[(k + 8) * 256 + n1], Wm[(k + 9) * 256 + n1]);
    ((uint4*)out)[gid] = v;
}

// w_ff1 [256,1024]: per matrix [c(8)][kt(8)][s(2)][wN(4)][nf4(2)][lane] uint4
__global__ void packff1_kernel(const float* __restrict__ W, __half* __restrict__ out, int nmat) {
    int gid = blockIdx.x * 256 + threadIdx.x;
    if (gid >= nmat * 32768) return;
    int m = gid >> 15, o = gid & 32767;
    int c = o >> 12, r = o & 4095;
    int kt = r >> 9, s = (r >> 8) & 1, wN = (r >> 6) & 3, nf4 = (r >> 5) & 1, lane = r & 31;
    int t = lane & 3, g = lane >> 2;
    int k = kt * 32 + s * 16 + 2 * t;
    int n0 = c * 128 + wN * 32 + nf4 * 16 + g, n1 = n0 + 8;
    const float* Wm = W + (size_t)m * 262144;
    uint4 v;
    v.x = pk2(Wm[k * 1024 + n0], Wm[(k + 1) * 1024 + n0]);
    v.y = pk2(Wm[(k + 8) * 1024 + n0], Wm[(k + 9) * 1024 + n0]);
    v.z = pk2(Wm[k * 1024 + n1], Wm[(k + 1) * 1024 + n1]);
    v.w = pk2(Wm[(k + 8) * 1024 + n1], Wm[(k + 9) * 1024 + n1]);
    ((uint4*)out)[gid] = v;
}

// w_ff2 [1024,256]: per matrix [c(8)][kt(4)][s(2)][wN(4)][nf4(4)][lane] uint4
__global__ void packff2_kernel(const float* __restrict__ W, __half* __restrict__ out, int nmat) {
    int gid = blockIdx.x * 256 + threadIdx.x;
    if (gid >= nmat * 32768) return;
    int m = gid >> 15, o = gid & 32767;
    int c = o >> 12, r = o & 4095;
    int kt = r >> 10, s = (r >> 9) & 1, wN = (r >> 7) & 3, nf4 = (r >> 5) & 3, lane = r & 31;
    int t = lane & 3, g = lane >> 2;
    int k = c * 128 + kt * 32 + s * 16 + 2 * t;
    int n0 = wN * 64 + nf4 * 16 + g, n1 = n0 + 8;
    const float* Wm = W + (size_t)m * 262144;
    uint4 v;
    v.x = pk2(Wm[k * 256 + n0], Wm[(k + 1) * 256 + n0]);
    v.y = pk2(Wm[(k + 8) * 256 + n0], Wm[(k + 9) * 256 + n0]);
    v.z = pk2(Wm[k * 256 + n1], Wm[(k + 1) * 256 + n1]);
    v.w = pk2(Wm[(k + 8) * 256 + n1], Wm[(k + 9) * 256 + n1]);
    ((uint4*)out)[gid] = v;
}

// ---------------- small kernels (fp16 activations) ----------------

// f32 -> fp16, 8 elems per thread (rows of H)
__global__ void cvth_kernel(const float* __restrict__ in, __half* __restrict__ out, int n8) {
    int i = blockIdx.x * 256 + threadIdx.x;
    if (i >= n8) return;
    const float* p = in + (size_t)i * 8;
    float4 v0 = ((const float4*)p)[0], v1 = ((const float4*)p)[1];
    uint4 o;
    o.x = pk2(v0.x, v0.y); o.y = pk2(v0.z, v0.w);
    o.z = pk2(v1.x, v1.y); o.w = pk2(v1.z, v1.w);
    ((uint4*)out)[i] = o;
}

__global__ void embed_kernel(const float* __restrict__ rel, const int* __restrict__ feat,
                             __half* __restrict__ out) {
    int gid = blockIdx.x * 256 + threadIdx.x;   // NEDGE*32 threads
    int e = gid >> 5;
    if (e >= NEDGE) return;
    int c8 = (gid & 31) * 8;
    int r = __ldg(feat + e);
    const float* p = rel + (size_t)r * H + c8;
    float4 v0 = ((const float4*)p)[0], v1 = ((const float4*)p)[1];
    uint4 o;
    o.x = pk2(v0.x, v0.y); o.y = pk2(v0.z, v0.w);
    o.z = pk2(v1.x, v1.y); o.w = pk2(v1.z, v1.w);
    *(uint4*)(out + (size_t)e * H + c8) = o;
}

__global__ void gather2_kernel(const __half* __restrict__ x, const int* __restrict__ s,
                               const int* __restrict__ d, __half* __restrict__ out, int n) {
    int gid = blockIdx.x * 256 + threadIdx.x;   // n*32 threads
    int e = gid >> 5;
    if (e >= n) return;
    int c8 = (gid & 31) * 8;
    int si = __ldg(s + e), di = __ldg(d + e);
    uint4 ua = *(const uint4*)(x + (size_t)si * H + c8);
    uint4 ub = *(const uint4*)(x + (size_t)di * H + c8);
    const uint32_t* ap = (const uint32_t*)&ua;
    const uint32_t* bp = (const uint32_t*)&ub;
    uint4 o; uint32_t* op = (uint32_t*)&o;
#pragma unroll
    for (int i = 0; i < 4; i++) {
        float2 fa = uph2(ap[i]), fb = uph2(bp[i]);
        op[i] = pkh2(fa.x + fb.x, fa.y + fb.y);
    }
    *(uint4*)(out + (size_t)e * H + c8) = o;
}

// CSR gather segment-sum, fp16 in/out, f32 accumulate, 2-way unrolled
__global__ void segsum_kernel(const __half* __restrict__ rows, const int* __restrict__ rp,
                              const int* __restrict__ ci, __half* __restrict__ out, int nseg) {
    int row = blockIdx.x * 8 + (threadIdx.x >> 5);
    if (row >= nseg) return;
    int lane = threadIdx.x & 31;
    int beg = __ldg(rp + row), end = __ldg(rp + row + 1);
    float a[8] = {0.f,0.f,0.f,0.f,0.f,0.f,0.f,0.f};
    float b[8] = {0.f,0.f,0.f,0.f,0.f,0.f,0.f,0.f};
    int j = beg;
    for (; j + 1 < end; j += 2) {
        uint4 u = *(const uint4*)(rows + (size_t)__ldg(ci + j) * H + lane * 8);
        uint4 v = *(const uint4*)(rows + (size_t)__ldg(ci + j + 1) * H + lane * 8);
        const uint32_t* up = (const uint32_t*)&u;
        const uint32_t* vp = (const uint32_t*)&v;
#pragma unroll
        for (int i = 0; i < 4; i++) {
            float2 f = uph2(up[i]); a[2*i] += f.x; a[2*i+1] += f.y;
            float2 q = uph2(vp[i]); b[2*i] += q.x; b[2*i+1] += q.y;
        }
    }
    if (j < end) {
        uint4 u = *(const uint4*)(rows + (size_t)__ldg(ci + j) * H + lane * 8);
        const uint32_t* up = (const uint32_t*)&u;
#pragma unroll
        for (int i = 0; i < 4; i++) {
            float2 f = uph2(up[i]); a[2*i] += f.x; a[2*i+1] += f.y;
        }
    }
    uint4 o; uint32_t* op = (uint32_t*)&o;
#pragma unroll
    for (int i = 0; i < 4; i++) op[i] = pkh2(a[2*i] + b[2*i], a[2*i+1] + b[2*i+1]);
    *(uint4*)(out + (size_t)row * H + lane * 8) = o;
}

// hop1 of layer-0 edge core: gather rel[feat[ci[j]]] (f32 table), fp16 out
__global__ void segsum_rel_kernel(const float* __restrict__ rel, const int* __restrict__ feat,
                                  const int* __restrict__ rp, const int* __restrict__ ci,
                                  __half* __restrict__ out, int nseg) {
    int row = blockIdx.x * 8 + (threadIdx.x >> 5);
    if (row >= nseg) return;
    int lane = threadIdx.x & 31;
    int beg = __ldg(rp + row), end = __ldg(rp + row + 1);
    float a[8] = {0.f,0.f,0.f,0.f,0.f,0.f,0.f,0.f};
    for (int j = beg; j < end; j++) {
        int r = __ldg(feat + __ldg(ci + j));
        const float* p = rel + (size_t)r * H + lane * 8;
        float4 v0 = ((const float4*)p)[0], v1 = ((const float4*)p)[1];
        // quantize each source to fp16 precision first (matches embed storage)
        float2 q;
        q = uph2(pk2(v0.x, v0.y)); a[0] += q.x; a[1] += q.y;
        q = uph2(pk2(v0.z, v0.w)); a[2] += q.x; a[3] += q.y;
        q = uph2(pk2(v1.x, v1.y)); a[4] += q.x; a[5] += q.y;
        q = uph2(pk2(v1.z, v1.w)); a[6] += q.x; a[7] += q.y;
    }
    uint4 o; uint32_t* op = (uint32_t*)&o;
#pragma unroll
    for (int i = 0; i < 4; i++) op[i] = pkh2(a[2*i], a[2*i+1]);
    *(uint4*)(out + (size_t)row * H + lane * 8) = o;
}

// ================= GEMM1 + LN1 fused (fp16), m32n64 warp tile =================
// out1 = h( LN( xres + gelu( sum_j A_j @ W_j + bias ) ) ); BM=64, BN=256, BK=32.
#define G1_SMEM_BYTES (10240 + 32768 + 5 * 1024)    // As 2x2560h, Bs 2x8192h, 5x256 f32

struct G1Args {
    const __half* A[6];
    const __half* W[6];       // packed
    const float* Bias[6];
    const __half* xres;
    const float* gamma;
    const float* beta;
};

__global__ void __launch_bounds__(256, 2)
gemm1_ln_kernel(G1Args args, int M, __half* __restrict__ out) {
    extern __shared__ char smraw[];
    __half* As = (__half*)smraw;                // 2 x 2560 halves (stride 40)
    __half* Bs = As + 2 * 2560;                 // 2 x 8192 halves
    float* bias_s = (float*)(Bs + 2 * 8192);
    float* gs  = bias_s + 256;
    float* bt  = gs + 256;
    float* lnS = bt + 256;
    float* lnQ = lnS + 256;
    __half* xs = (__half*)smraw;                // alias after mainloop, stride 264

    int tid = threadIdx.x;
    int bm = blockIdx.x * 64;
    {
        float b = 0.f;
#pragma unroll
        for (int j = 0; j < 6; j++) b += __ldg(args.Bias[j] + tid);
        bias_s[tid] = b;
        gs[tid] = __ldg(args.gamma + tid);
        bt[tid] = __ldg(args.beta + tid);
    }

    uint32_t sbase = (uint32_t)__cvta_generic_to_shared(smraw);
    uint32_t a_base = sbase;
    uint32_t b_base = sbase + 10240;

    int warp = tid >> 5, lane = tid & 31, g = lane >> 2, t = lane & 3;
    int wm = (warp >> 2) * 32;
    int wN = warp & 3;
    int wn = wN * 64;

    float acc[2][8][4];
#pragma unroll
    for (int mt = 0; mt < 2; mt++)
#pragma unroll
        for (int nf = 0; nf < 8; nf++)
#pragma unroll
            for (int i = 0; i < 4; i++) acc[mt][nf][i] = 0.f;

    auto issue = [&](int tt, int buf) {
        int j = tt >> 3, kt = tt & 7;
        const __half* A = args.A[j];
        const uint4* Wp = (const uint4*)args.W[j] + (size_t)kt * 1024;
        {
            int r = tid >> 2, cp = tid & 3;
            int row = bm + r;
            uint32_t dst = a_base + (uint32_t)(buf * 5120 + r * 80 + cp * 16);
            const __half* src = A + (size_t)row * H + kt * 32 + cp * 8;
            int sz = (row < M) ? 16 : 0;
            asm volatile("cp.async.cg.shared.global [%0], [%1], 16, %2;\n"
                         :: "r"(dst), "l"(src), "r"(sz));
        }
#pragma unroll
        for (int i = 0; i < 4; i++) {
            int idx = tid + i * 256;
            uint32_t dst = b_base + (uint32_t)(buf * 16384 + idx * 16);
            asm volatile("cp.async.cg.shared.global [%0], [%1], 16;\n"
                         :: "r"(dst), "l"(Wp + idx));
        }
        asm volatile("cp.async.commit_group;\n");
    };

    issue(0, 0);
    for (int tt = 0; tt < 48; tt++) {
        asm volatile("cp.async.wait_group 0;\n");
        __syncthreads();
        if (tt + 1 < 48) issue(tt + 1, (tt + 1) & 1);
        const __half* Ab = As + (tt & 1) * 2560;
        const uint4* Bb4 = (const uint4*)(Bs + (tt & 1) * 8192) + wN * 128 + lane;
#pragma unroll
        for (int s = 0; s < 2; s++) {
            int k0 = s * 16 + 2 * t;
            const __half* Ar0 = Ab + (wm + g) * 40 + k0;
            const __half* Ar1 = Ab + (wm + 8 + g) * 40 + k0;
            const __half* Ar2 = Ab + (wm + 16 + g) * 40 + k0;
            const __half* Ar3 = Ab + (wm + 24 + g) * 40 + k0;
            uint32_t a0[4], a1[4];
            a0[0] = *(const uint32_t*)Ar0;
            a0[1] = *(const uint32_t*)Ar1;
            a0[2] = *(const uint32_t*)(Ar0 + 8);
            a0[3] = *(const uint32_t*)(Ar1 + 8);
            a1[0] = *(const uint32_t*)Ar2;
            a1[1] = *(const uint32_t*)Ar3;
            a1[2] = *(const uint32_t*)(Ar2 + 8);
            a1[3] = *(const uint32_t*)(Ar3 + 8);
#pragma unroll
            for (int nf4 = 0; nf4 < 4; nf4++) {
                uint4 bv = Bb4[s * 512 + nf4 * 32];
                uint32_t b0[2] = {bv.x, bv.y};
                uint32_t b1[2] = {bv.z, bv.w};
                mma_f16(acc[0][2 * nf4], a0, b0);
                mma_f16(acc[1][2 * nf4], a1, b0);
                mma_f16(acc[0][2 * nf4 + 1], a0, b1);
                mma_f16(acc[1][2 * nf4 + 1], a1, b1);
            }
        }
    }
    __syncthreads();

    // residual tile into xs (half, stride 264)
#pragma unroll
    for (int i = 0; i < 8; i++) {
        int idx = tid + i * 256;
        int r = idx >> 5, c8 = (idx & 31) * 8;
        int row = bm + r;
        uint4 v = make_uint4(0, 0, 0, 0);
        if (row < M) v = *(const uint4*)(args.xres + (size_t)row * H + c8);
        *(uint4*)(xs + r * 264 + c8) = v;
    }
    __syncthreads();

#pragma unroll
    for (int mt = 0; mt < 2; mt++) {
#pragma unroll
        for (int h = 0; h < 2; h++) {
            int row = wm + mt * 16 + h * 8 + g;
            float s = 0.f, q = 0.f;
#pragma unroll
            for (int nf = 0; nf < 8; nf++) {
                int col = wn + nf * 8 + 2 * t;
                float2 xv = uph2(*(const uint32_t*)(xs + row * 264 + col));
                float v0 = xv.x + gelu_exact(acc[mt][nf][2 * h]     + bias_s[col]);
                float v1 = xv.y + gelu_exact(acc[mt][nf][2 * h + 1] + bias_s[col + 1]);
                acc[mt][nf][2 * h] = v0; acc[mt][nf][2 * h + 1] = v1;
                s += v0 + v1; q += v0 * v0 + v1 * v1;
            }
#pragma unroll
            for (int o = 1; o <= 2; o <<= 1) {
                s += __shfl_xor_sync(0xffffffffu, s, o);
                q += __shfl_xor_sync(0xffffffffu, q, o);
            }
            if (t == 0) { lnS[row * 4 + wN] = s; lnQ[row * 4 + wN] = q; }
        }
    }
    __syncthreads();
#pragma unroll
    for (int mt = 0; mt < 2; mt++) {
#pragma unroll
        for (int h = 0; h < 2; h++) {
            int row = wm + mt * 16 + h * 8 + g;
            float S = lnS[row * 4] + lnS[row * 4 + 1] + lnS[row * 4 + 2] + lnS[row * 4 + 3];
            float Q = lnQ[row * 4] + lnQ[row * 4 + 1] + lnQ[row * 4 + 2] + lnQ[row * 4 + 3];
            float m = S * (1.f / H), v = Q * (1.f / H) - m * m, rs = rsqrtf(v + 1e-5f);
            if (bm + row < M) {
#pragma unroll
                for (int nf = 0; nf < 8; nf++) {
                    int col = wn + nf * 8 + 2 * t;
                    float o0 = (acc[mt][nf][2 * h]     - m) * rs * gs[col]     + bt[col];
                    float o1 = (acc[mt][nf][2 * h + 1] - m) * rs * gs[col + 1] + bt[col + 1];
                    *(uint32_t*)(out + (size_t)(bm + row) * H + col) = pkh2(o0, o1);
                }
            }
        }
    }
}

// ================= fused FFN + LN2 (fp16) =================
// out = LN( out1 + gelu(out1@w1+b1)@w2 + b2 ); 512 threads, FH chunked by 128.
#define F_SMEM_BYTES (33792 + 17408 + 32768 + 5632)   // 89600

struct FArgs {
    const __half* w1;    // packed
    const float* b1;
    const __half* w2;    // packed
    const float* b2;
    const float* gamma;
    const float* beta;
};

__global__ void __launch_bounds__(512, 1)
ffn_kernel(FArgs args, int M, const __half* __restrict__ in1,
           void* __restrict__ outv, int out_half) {
    extern __shared__ char smraw[];
    __half* xs  = (__half*)smraw;            // 64 x 264 halves
    __half* hb  = xs + 64 * 264;             // 64 x 136 halves
    __half* Bst = hb + 64 * 136;             // 2 x 8192 halves
    float* b2s = (float*)(Bst + 2 * 8192);
    float* gs  = b2s + 256;
    float* bt  = gs + 256;
    float* b1c = bt + 256;                   // 128
    float* lnS = b1c + 128;                  // 256
    float* lnQ = lnS + 256;                  // 256

    int tid = threadIdx.x;
    int bm = blockIdx.x * 64;

    if (tid < 256) {
        b2s[tid] = __ldg(args.b2 + tid);
        gs[tid]  = __ldg(args.gamma + tid);
        bt[tid]  = __ldg(args.beta + tid);
    }
#pragma unroll
    for (int i = 0; i < 4; i++) {
        int idx = tid + i * 512;
        int r = idx >> 5, c8 = (idx & 31) * 8;
        int row = bm + r;
        uint4 v = make_uint4(0, 0, 0, 0);
        if (row < M) v = *(const uint4*)(in1 + (size_t)row * H + c8);
        *(uint4*)(xs + r * 264 + c8) = v;
    }

    uint32_t bst_base = (uint32_t)__cvta_generic_to_shared(Bst);
    int warp = tid >> 5, lane = tid & 31, g = lane >> 2, t = lane & 3;
    int wm = (warp >> 2) * 16;
    int wN = warp & 3;
    int wn1 = wN * 32;
    int wn2 = wN * 64;

    float acc2[8][4];
#pragma unroll
    for (int nf = 0; nf < 8; nf++)
#pragma unroll
        for (int i = 0; i < 4; i++) acc2[nf][i] = 0.f;

    __syncthreads();

    for (int c = 0; c < 8; c++) {
        if (c > 0) __syncthreads();
        if (tid < 128) b1c[tid] = __ldg(args.b1 + c * 128 + tid);

        float acc1[4][4];
#pragma unroll
        for (int nf = 0; nf < 4; nf++)
#pragma unroll
            for (int i = 0; i < 4; i++) acc1[nf][i] = 0.f;

        const uint4* W1p = (const uint4*)args.w1 + (size_t)(c * 8) * 512;
        auto issue1 = [&](int kt, int buf) {
            uint32_t dst = bst_base + (uint32_t)(buf * 8192 + tid * 16);
            asm volatile("cp.async.cg.shared.global [%0], [%1], 16;\n"
                         :: "r"(dst), "l"(W1p + kt * 512 + tid));
            asm volatile("cp.async.commit_group;\n");
        };

        issue1(0, 0);
        for (int kt = 0; kt < 8; kt++) {
            asm volatile("cp.async.wait_group 0;\n");
            __syncthreads();
            if (kt + 1 < 8) issue1(kt + 1, (kt + 1) & 1);
            const uint4* Bb4 = (const uint4*)(Bst + (kt & 1) * 4096) + wN * 64 + lane;
#pragma unroll
            for (int s = 0; s < 2; s++) {
                int kg = kt * 32 + s * 16 + 2 * t;
                const __half* Ar0 = xs + (wm + g) * 264 + kg;
                const __half* Ar1 = xs + (wm + 8 + g) * 264 + kg;
                uint32_t a[4];
                a[0] = *(const uint32_t*)Ar0;
                a[1] = *(const uint32_t*)Ar1;
                a[2] = *(const uint32_t*)(Ar0 + 8);
                a[3] = *(const uint32_t*)(Ar1 + 8);
#pragma unroll
                for (int nf4 = 0; nf4 < 2; nf4++) {
                    uint4 bv = Bb4[s * 256 + nf4 * 32];
                    uint32_t b0[2] = {bv.x, bv.y};
                    uint32_t b1[2] = {bv.z, bv.w};
                    mma_f16(acc1[2 * nf4], a, b0);
                    mma_f16(acc1[2 * nf4 + 1], a, b1);
                }
            }
        }

        // h = h16(gelu(acc1 + b1)) -> hb
#pragma unroll
        for (int nf = 0; nf < 4; nf++) {
            int col = wn1 + nf * 8 + 2 * t;
            float h0 = gelu_exact(acc1[nf][0] + b1c[col]);
            float h1 = gelu_exact(acc1[nf][1] + b1c[col + 1]);
            float h2v = gelu_exact(acc1[nf][2] + b1c[col]);
            float h3v = gelu_exact(acc1[nf][3] + b1c[col + 1]);
            *(uint32_t*)(hb + (wm + g) * 136 + col)     = pkh2(h0, h1);
            *(uint32_t*)(hb + (wm + 8 + g) * 136 + col) = pkh2(h2v, h3v);
        }
        __syncthreads();

        const uint4* W2p = (const uint4*)args.w2 + (size_t)(c * 4) * 1024;
        auto issue2 = [&](int kt, int buf) {
#pragma unroll
            for (int i = 0; i < 2; i++) {
                int idx = tid + i * 512;
                uint32_t dst = bst_base + (uint32_t)(buf * 16384 + idx * 16);
                asm volatile("cp.async.cg.shared.global [%0], [%1], 16;\n"
                             :: "r"(dst), "l"(W2p + kt * 1024 + idx));
            }
            asm volatile("cp.async.commit_group;\n");
        };

        issue2(0, 0);
        for (int kt = 0; kt < 4; kt++) {
            asm volatile("cp.async.wait_group 0;\n");
            __syncthreads();
            if (kt + 1 < 4) issue2(kt + 1, (kt + 1) & 1);
            const uint4* Bb4 = (const uint4*)(Bst + (kt & 1) * 8192) + wN * 128 + lane;
#pragma unroll
            for (int s = 0; s < 2; s++) {
                int kg = kt * 32 + s * 16 + 2 * t;
                const __half* Ar0 = hb + (wm + g) * 136 + kg;
                const __half* Ar1 = hb + (wm + 8 + g) * 136 + kg;
                uint32_t a[4];
                a[0] = *(const uint32_t*)Ar0;
                a[1] = *(const uint32_t*)Ar1;
                a[2] = *(const uint32_t*)(Ar0 + 8);
                a[3] = *(const uint32_t*)(Ar1 + 8);
#pragma unroll
                for (int nf4 = 0; nf4 < 4; nf4++) {
                    uint4 bv = Bb4[s * 512 + nf4 * 32];
                    uint32_t b0[2] = {bv.x, bv.y};
                    uint32_t b1[2] = {bv.z, bv.w};
                    mma_f16(acc2[2 * nf4], a, b0);
                    mma_f16(acc2[2 * nf4 + 1], a, b1);
                }
            }
        }
    }

    // LN2 epilogue
    int row0 = wm + g, row1 = wm + 8 + g;
    float s0 = 0.f, q0 = 0.f, s1 = 0.f, q1 = 0.f;
#pragma unroll
    for (int nf = 0; nf < 8; nf++) {
        int col = wn2 + nf * 8 + 2 * t;
        float2 x0 = uph2(*(const uint32_t*)(xs + row0 * 264 + col));
        float2 x1 = uph2(*(const uint32_t*)(xs + row1 * 264 + col));
        float t0 = x0.x + acc2[nf][0] + b2s[col];
        float t1 = x0.y + acc2[nf][1] + b2s[col + 1];
        float t2 = x1.x + acc2[nf][2] + b2s[col];
        float t3 = x1.y + acc2[nf][3] + b2s[col + 1];
        acc2[nf][0] = t0; acc2[nf][1] = t1; acc2[nf][2] = t2; acc2[nf][3] = t3;
        s0 += t0 + t1; q0 += t0 * t0 + t1 * t1;
        s1 += t2 + t3; q1 += t2 * t2 + t3 * t3;
    }
#pragma unroll
    for (int o = 1; o <= 2; o <<= 1) {
        s0 += __shfl_xor_sync(0xffffffffu, s0, o);
        q0 += __shfl_xor_sync(0xffffffffu, q0, o);
        s1 += __shfl_xor_sync(0xffffffffu, s1, o);
        q1 += __shfl_xor_sync(0xffffffffu, q1, o);
    }
    if (t == 0) {
        lnS[row0 * 4 + wN] = s0; lnQ[row0 * 4 + wN] = q0;
        lnS[row1 * 4 + wN] = s1; lnQ[row1 * 4 + wN] = q1;
    }
    __syncthreads();
    float S0 = lnS[row0 * 4] + lnS[row0 * 4 + 1] + lnS[row0 * 4 + 2] + lnS[row0 * 4 + 3];
    float Q0 = lnQ[row0 * 4] + lnQ[row0 * 4 + 1] + lnQ[row0 * 4 + 2] + lnQ[row0 * 4 + 3];
    float S1 = lnS[row1 * 4] + lnS[row1 * 4 + 1] + lnS[row1 * 4 + 2] + lnS[row1 * 4 + 3];
    float Q1 = lnQ[row1 * 4] + lnQ[row1 * 4 + 1] + lnQ[row1 * 4 + 2] + lnQ[row1 * 4 + 3];
    float m0 = S0 * (1.f / H), v0 = Q0 * (1.f / H) - m0 * m0, r0 = rsqrtf(v0 + 1e-5f);
    float m1 = S1 * (1.f / H), v1 = Q1 * (1.f / H) - m1 * m1, r1 = rsqrtf(v1 + 1e-5f);
    bool ok0 = (bm + row0) < M, ok1 = (bm + row1) < M;
#pragma unroll
    for (int nf = 0; nf < 8; nf++) {
        int col = wn2 + nf * 8 + 2 * t;
        float o0 = (acc2[nf][0] - m0) * r0 * gs[col]     + bt[col];
        float o1 = (acc2[nf][1] - m0) * r0 * gs[col + 1] + bt[col + 1];
        float o2 = (acc2[nf][2] - m1) * r1 * gs[col]     + bt[col];
        float o3 = (acc2[nf][3] - m1) * r1 * gs[col + 1] + bt[col + 1];
        if (out_half) {
            __half* out = (__half*)outv;
            if (ok0) *(uint32_t*)(out + (size_t)(bm + row0) * H + col) = pkh2(o0, o1);
            if (ok1) *(uint32_t*)(out + (size_t)(bm + row1) * H + col) = pkh2(o2, o3);
        } else {
            float* out = (float*)outv;
            if (ok0) *(float2*)(out + (size_t)(bm + row0) * H + col) = make_float2(o0, o1);
            if (ok1) *(float2*)(out + (size_t)(bm + row1) * H + col) = make_float2(o2, o3);
        }
    }
}

// ---------------- host orchestration ----------------

struct Net {
    const float *b_self, *b_khop, *b_fuse, *b_ff1, *b_ff2;
    const float *ln1g, *ln1b, *ln2g, *ln2b;
    __half* wbuf;
};

static void run_core(const Net& n, int l, int c, int M, __half* const* z,
                     const __half* xin, const __half* fused, __half* out1buf,
                     void* outp, int out_half, cudaStream_t st) {
    size_t lc = (size_t)(l * 2 + c);
    G1Args ga;
    ga.A[0] = xin;
    ga.W[0] = n.wbuf + OFFH_WSELF + lc * 65536;
    ga.Bias[0] = n.b_self + lc * H;
    for (int i = 0; i < 4; i++) {
        ga.A[1 + i] = z[i];
        ga.W[1 + i] = n.wbuf + OFFH_WKHOP + (lc * 4 + i) * (size_t)65536;
        ga.Bias[1 + i] = n.b_khop + (lc * 4 + i) * (size_t)H;
    }
    ga.A[5] = fused;
    ga.W[5] = n.wbuf + OFFH_WFUSE + lc * 65536;
    ga.Bias[5] = n.b_fuse + lc * H;
    ga.xres = xin;
    ga.gamma = n.ln1g + lc * H;
    ga.beta  = n.ln1b + lc * H;

    int grid = (M + 63) / 64;
    gemm1_ln_kernel<<<grid, 256, G1_SMEM_BYTES, st>>>(ga, M, out1buf);

    FArgs fa;
    fa.w1 = n.wbuf + OFFH_WFF1 + lc * (size_t)262144;
    fa.b1 = n.b_ff1 + lc * FH;
    fa.w2 = n.wbuf + OFFH_WFF2 + lc * (size_t)262144;
    fa.b2 = n.b_ff2 + lc * H;
    fa.gamma = n.ln2g + lc * H;
    fa.beta  = n.ln2b + lc * H;
    ffn_kernel<<<grid, 512, F_SMEM_BYTES, st>>>(fa, M, out1buf, outp, out_half);
}

static void exclusive_scan(int* cnt, int* rp, int* bsums, int n, cudaStream_t st) {
    int nb = (n + 1023) / 1024;
    scan1_kernel<<<nb, 1024, 0, st>>>(cnt, rp, bsums, n);
    scan2_kernel<<<1, 1024, 0, st>>>(bsums, nb);
    scan3_kernel<<<nb, 1024, 0, st>>>(rp, bsums, cnt, n);
}

extern "C" void kernel_launch(void* const* d_in, const int* in_sizes, int n_in,
                              void* d_out, int out_size) {
    const float* x_in = (const float*)d_in[0];
    const int* feat   = (const int*)d_in[1];
    const int* eig    = (const int*)d_in[2];
    const int* eil    = (const int*)d_in[3];
    const float* rel  = (const float*)d_in[4];

    const float* w_self = (const float*)d_in[5];
    const float* w_khop = (const float*)d_in[7];
    const float* w_fuse = (const float*)d_in[9];
    const float* w_ff1  = (const float*)d_in[11];
    const float* w_ff2  = (const float*)d_in[13];

    Net n;
    n.b_self = (const float*)d_in[6];
    n.b_khop = (const float*)d_in[8];
    n.b_fuse = (const float*)d_in[10];
    n.b_ff1  = (const float*)d_in[12];
    n.b_ff2  = (const float*)d_in[14];
    n.ln1g   = (const float*)d_in[15]; n.ln1b = (const float*)d_in[16];
    n.ln2g   = (const float*)d_in[17]; n.ln2b = (const float*)d_in[18];

    cudaFuncSetAttribute(gemm1_ln_kernel,
                         cudaFuncAttributeMaxDynamicSharedMemorySize, G1_SMEM_BYTES);
    cudaFuncSetAttribute(ffn_kernel,
                         cudaFuncAttributeMaxDynamicSharedMemorySize, F_SMEM_BYTES);

    static cudaStream_t s2 = nullptr;
    static cudaEvent_t ev_start, ev_prep, ev_x0, ev_lg0, ev_fin;
    if (!s2) {
        cudaStreamCreateWithFlags(&s2, cudaStreamNonBlocking);
        cudaEventCreateWithFlags(&ev_start, cudaEventDisableTiming);
        cudaEventCreateWithFlags(&ev_prep,  cudaEventDisableTiming);
        cudaEventCreateWithFlags(&ev_x0,    cudaEventDisableTiming);
        cudaEventCreateWithFlags(&ev_lg0,   cudaEventDisableTiming);
        cudaEventCreateWithFlags(&ev_fin,   cudaEventDisableTiming);
    }

    __half *px0, *plg0, *pfn, *pfe, *pzbase, *pznb, *pout1, *pout1n, *pwbuf;
    int *rp_nd, *ci_nd, *rp_fn, *ci_fn, *rp_lg, *ci_lg;
    int *pcnt, *pcur, *pbs, *pcnt2, *pcur2, *pbs2;
    cudaGetSymbolAddress((void**)&px0,   h_x);
    cudaGetSymbolAddress((void**)&plg0,  h_lg);
    cudaGetSymbolAddress((void**)&pfn,   h_fn);
    cudaGetSymbolAddress((void**)&pfe,   h_fe);
    cudaGetSymbolAddress((void**)&pzbase,h_z);
    cudaGetSymbolAddress((void**)&pznb,  h_zn);
    cudaGetSymbolAddress((void**)&pout1, h_out1);
    cudaGetSymbolAddress((void**)&pout1n,h_out1n);
    cudaGetSymbolAddress((void**)&pwbuf, g_wbufh);
    cudaGetSymbolAddress((void**)&rp_nd, g_rp_nd);
    cudaGetSymbolAddress((void**)&ci_nd, g_ci_nd);
    cudaGetSymbolAddress((void**)&rp_fn, g_rp_fn);
    cudaGetSymbolAddress((void**)&ci_fn, g_ci_fn);
    cudaGetSymbolAddress((void**)&rp_lg, g_rp_lg);
    cudaGetSymbolAddress((void**)&ci_lg, g_ci_lg);
    cudaGetSymbolAddress((void**)&pcnt,  g_cnt);
    cudaGetSymbolAddress((void**)&pcur,  g_cur);
    cudaGetSymbolAddress((void**)&pbs,   g_bs);
    cudaGetSymbolAddress((void**)&pcnt2, g_cnt2);
    cudaGetSymbolAddress((void**)&pcur2, g_cur2);
    cudaGetSymbolAddress((void**)&pbs2,  g_bs2);

    n.wbuf = pwbuf;
    __half* px[2]  = {px0,  px0  + (size_t)NNODE * H};
    __half* plg[2] = {plg0, plg0 + (size_t)NEDGE * H};
    __half* ze[4]; __half* zn[4];
    for (int i = 0; i < 4; i++) {
        ze[i] = pzbase + (size_t)i * NEDGE * H;
        zn[i] = pznb + (size_t)i * NNODE * H;
    }

    const int* src_g = eig;  const int* dst_g = eig + NEDGE;
    const int* src_l = eil;  const int* dst_l = eil + NLG;

    // fork point for capture
    cudaEventRecord(ev_start, 0);
    cudaStreamWaitEvent(s2, ev_start, 0);

    // ===== stream s2: packs + init + gather2-l0 =====
    cvth_kernel<<<(NNODE * H / 8 + 255) / 256, 256, 0, s2>>>(x_in, px[0], NNODE * H / 8);
    embed_kernel<<<NEDGE * 32 / 256, 256, 0, s2>>>(rel, feat, plg[0]);
    pack256_kernel<<<(4 * 8192 + 255) / 256, 256, 0, s2>>>(w_self, pwbuf + OFFH_WSELF, 4);
    pack256_kernel<<<(16 * 8192 + 255) / 256, 256, 0, s2>>>(w_khop, pwbuf + OFFH_WKHOP, 16);
    pack256_kernel<<<(4 * 8192 + 255) / 256, 256, 0, s2>>>(w_fuse, pwbuf + OFFH_WFUSE, 4);
    packff1_kernel<<<(4 * 32768 + 255) / 256, 256, 0, s2>>>(w_ff1, pwbuf + OFFH_WFF1, 4);
    packff2_kernel<<<(4 * 32768 + 255) / 256, 256, 0, s2>>>(w_ff2, pwbuf + OFFH_WFF2, 4);
    gather2_kernel<<<NEDGE * 32 / 256, 256, 0, s2>>>(px[0], src_g, dst_g, pfe, NEDGE);
    cudaEventRecord(ev_prep, s2);

    // ===== stream s2: node CSRs + node core layer 0 =====
    cudaMemsetAsync(pcnt2, 0, NNODE * sizeof(int), s2);
    hist_kernel<<<(NEDGE + 255) / 256, 256, 0, s2>>>(dst_g, pcnt2, NEDGE);
    exclusive_scan(pcnt2, rp_nd, pbs2, NNODE, s2);
    cudaMemcpyAsync(pcur2, rp_nd, NNODE * sizeof(int), cudaMemcpyDeviceToDevice, s2);
    fill_kernel<<<(NEDGE + 255) / 256, 256, 0, s2>>>(dst_g, src_g, pcur2, ci_nd, NEDGE);

    cudaMemsetAsync(pcnt2, 0, NNODE * sizeof(int), s2);
    hist_kernel<<<(NEDGE + 255) / 256, 256, 0, s2>>>(src_g, pcnt2, NEDGE);
    hist_kernel<<<(NEDGE + 255) / 256, 256, 0, s2>>>(dst_g, pcnt2, NEDGE);
    exclusive_scan(pcnt2, rp_fn, pbs2, NNODE, s2);
    cudaMemcpyAsync(pcur2, rp_fn, NNODE * sizeof(int), cudaMemcpyDeviceToDevice, s2);
    fill_kernel<<<(NEDGE + 255) / 256, 256, 0, s2>>>(src_g, nullptr, pcur2, ci_fn, NEDGE);
    fill_kernel<<<(NEDGE + 255) / 256, 256, 0, s2>>>(dst_g, nullptr, pcur2, ci_fn, NEDGE);

    segsum_kernel<<<(NNODE + 7) / 8, 256, 0, s2>>>(plg[0], rp_fn, ci_fn, pfn, NNODE);
    {
        const __half* prev = px[0];
        for (int i = 0; i < 4; i++) {
            segsum_kernel<<<(NNODE + 7) / 8, 256, 0, s2>>>(prev, rp_nd, ci_nd, zn[i], NNODE);
            prev = zn[i];
        }
    }
    run_core(n, 0, 0, NNODE, zn, px[0], pfn, pout1n, px[1], 1, s2);
    cudaEventRecord(ev_x0, s2);

    // ===== stream 0: lg CSR + layer-0 edge khops =====
    cudaMemsetAsync(pcnt, 0, NEDGE * sizeof(int), 0);
    hist_kernel<<<(NLG + 255) / 256, 256>>>(dst_l, pcnt, NLG);
    exclusive_scan(pcnt, rp_lg, pbs, NEDGE, 0);
    cudaMemcpyAsync(pcur, rp_lg, NEDGE * sizeof(int), cudaMemcpyDeviceToDevice, 0);
    fill_kernel<<<(NLG + 255) / 256, 256>>>(dst_l, src_l, pcur, ci_lg, NLG);

    segsum_rel_kernel<<<(NEDGE + 7) / 8, 256>>>(rel, feat, rp_lg, ci_lg, ze[0], NEDGE);
    segsum_kernel<<<(NEDGE + 7) / 8, 256>>>(ze[0], rp_lg, ci_lg, ze[1], NEDGE);
    segsum_kernel<<<(NEDGE + 7) / 8, 256>>>(ze[1], rp_lg, ci_lg, ze[2], NEDGE);
    segsum_kernel<<<(NEDGE + 7) / 8, 256>>>(ze[2], rp_lg, ci_lg, ze[3], NEDGE);

    // ===== stream 0: edge core, layer 0 =====
    cudaStreamWaitEvent(0, ev_prep, 0);
    run_core(n, 0, 1, NEDGE, ze, plg[0], pfe, pout1, plg[1], 1, (cudaStream_t)0);
    cudaEventRecord(ev_lg0, 0);

    // ===== stream s2: node core, layer 1 =====
    cudaStreamWaitEvent(s2, ev_lg0, 0);
    segsum_kernel<<<(NNODE + 7) / 8, 256, 0, s2>>>(plg[1], rp_fn, ci_fn, pfn, NNODE);
    {
        const __half* prev = px[1];
        for (int i = 0; i < 4; i++) {
            segsum_kernel<<<(NNODE + 7) / 8, 256, 0, s2>>>(prev, rp_nd, ci_nd, zn[i], NNODE);
            prev = zn[i];
        }
    }
    run_core(n, 1, 0, NNODE, zn, px[1], pfn, pout1n, (float*)d_out, 0, s2);
    cudaEventRecord(ev_fin, s2);

    // ===== stream 0: edge core, layer 1 =====
    cudaStreamWaitEvent(0, ev_x0, 0);
    gather2_kernel<<<NEDGE * 32 / 256, 256>>>(px[1], src_g, dst_g, pfe, NEDGE);
    {
        const __half* prev = plg[1];
        for (int i = 0; i < 4; i++) {
            segsum_kernel<<<(NEDGE + 7) / 8, 256>>>(prev, rp_lg, ci_lg, ze[i], NEDGE);
            prev = ze[i];
        }
    }
    run_core(n, 1, 1, NEDGE, ze, plg[1], pfe, pout1,
             (float*)d_out + (size_t)NNODE * H, 0, (cudaStream_t)0);

    cudaStreamWaitEvent(0, ev_fin, 0);
    (void)in_sizes; (void)n_in; (void)out_size;
}

// round 12
// speedup vs baseline: 1.7835x; 1.0971x over previous
#include <cuda_runtime.h>
#include <cuda_fp16.h>
#include <cstdint>
#include <math.h>

#define H       256
#define FH      1024
#define NNODE   20000
#define NEDGE   160000
#define NLG     640000

// ---------------- scratch (static device memory; no allocations) ----------------
__device__ __half h_x[2][(size_t)NNODE * H];
__device__ __half h_lg[2][(size_t)NEDGE * H];
__device__ __half h_fn[(size_t)NNODE * H];
__device__ __half h_fe[(size_t)NEDGE * H];
__device__ __half h_fe2[(size_t)NEDGE * H];
__device__ __half h_z[4][(size_t)NEDGE * H];
__device__ __half h_zn[4][(size_t)NNODE * H];
__device__ __half h_out1[(size_t)NEDGE * H];
__device__ __half h_out1n[(size_t)NNODE * H];

// packed fp16 weights (fragment order for mma.m16n8k16)
#define OFFH_WSELF 0
#define OFFH_WKHOP (OFFH_WSELF + 4 * 65536)
#define OFFH_WFUSE (OFFH_WKHOP + 16 * 65536)
#define OFFH_WFF1  (OFFH_WFUSE + 4 * 65536)
#define OFFH_WFF2  (OFFH_WFF1 + 4 * 262144)
#define WBUFH_TOT  (OFFH_WFF2 + 4 * 262144)
__device__ __half g_wbufh[WBUFH_TOT];

// CSR structures
__device__ int g_rp_nd[NNODE + 1];
__device__ int g_ci_nd[NEDGE];
__device__ int g_rp_fn[NNODE + 1];
__device__ int g_ci_fn[2 * NEDGE];
__device__ int g_rp_lg[NEDGE + 1];
__device__ int g_ci_lg[NLG];
__device__ int g_cnt[NEDGE];
__device__ int g_cur[NEDGE];
__device__ int g_bs[1024];
__device__ int g_cnt2[NNODE];
__device__ int g_cur2[NNODE];
__device__ int g_bs2[1024];

__device__ __forceinline__ float gelu_exact(float v) {
    return 0.5f * v * (1.0f + erff(v * 0.70710678118654752f));
}

__device__ __forceinline__ uint32_t pkh2(float a, float b) {
    __half2 h = __floats2half2_rn(a, b);
    return *(uint32_t*)&h;
}
__device__ __forceinline__ float2 uph2(uint32_t u) {
    __half2 h = *(__half2*)&u;
    return __half22float2(h);
}
__device__ __forceinline__ uint32_t pk2(float a, float b) { return pkh2(a, b); }

__device__ __forceinline__ void mma_f16(float* c, const uint32_t* a, const uint32_t* b) {
    asm volatile(
        "mma.sync.aligned.m16n8k16.row.col.f32.f16.f16.f32 "
        "{%0,%1,%2,%3}, {%4,%5,%6,%7}, {%8,%9}, {%0,%1,%2,%3};"
        : "+f"(c[0]), "+f"(c[1]), "+f"(c[2]), "+f"(c[3])
        : "r"(a[0]), "r"(a[1]), "r"(a[2]), "r"(a[3]), "r"(b[0]), "r"(b[1]));
}

// ---------------- CSR build kernels ----------------

__global__ void hist_kernel(const int* __restrict__ key, int* cnt, int n) {
    int i = blockIdx.x * 256 + threadIdx.x;
    if (i < n) atomicAdd(&cnt[__ldg(key + i)], 1);
}

__global__ void scan1_kernel(const int* __restrict__ in, int* __restrict__ out,
                             int* __restrict__ bsums, int n) {
    __shared__ int sh[1024];
    int i = blockIdx.x * 1024 + threadIdx.x;
    int v = (i < n) ? in[i] : 0;
    sh[threadIdx.x] = v;
    __syncthreads();
#pragma unroll
    for (int o = 1; o < 1024; o <<= 1) {
        int t = (threadIdx.x >= o) ? sh[threadIdx.x - o] : 0;
        __syncthreads();
        sh[threadIdx.x] += t;
        __syncthreads();
    }
    if (i < n) out[i] = sh[threadIdx.x] - v;
    if (threadIdx.x == 1023) bsums[blockIdx.x] = sh[1023];
}

__global__ void scan2_kernel(int* bsums, int nb) {
    __shared__ int sh[1024];
    int v = (threadIdx.x < nb) ? bsums[threadIdx.x] : 0;
    sh[threadIdx.x] = v;
    __syncthreads();
#pragma unroll
    for (int o = 1; o < 1024; o <<= 1) {
        int t = (threadIdx.x >= o) ? sh[threadIdx.x - o] : 0;
        __syncthreads();
        sh[threadIdx.x] += t;
        __syncthreads();
    }
    if (threadIdx.x < nb) bsums[threadIdx.x] = sh[threadIdx.x] - v;
}

__global__ void scan3_kernel(int* __restrict__ out, const int* __restrict__ bsums,
                             const int* __restrict__ cnt, int n) {
    int i = blockIdx.x * 1024 + threadIdx.x;
    if (i < n) {
        int v = out[i] + bsums[i >> 10];
        out[i] = v;
        if (i == n - 1) out[n] = v + cnt[i];
    }
}

__global__ void fill_kernel(const int* __restrict__ key, const int* __restrict__ val,
                            int* cursor, int* __restrict__ ci, int n) {
    int i = blockIdx.x * 256 + threadIdx.x;
    if (i >= n) return;
    int pos = atomicAdd(&cursor[__ldg(key + i)], 1);
    ci[pos] = val ? __ldg(val + i) : i;
}

// ---------------- weight pack kernels (f32 -> fp16, m16n8k16 B-fragment order) --------
// Lane uint4 = {b0(n0), b1(n0), b0(n1), b1(n1)}; b0 = h2(W[k+2t][n], W[k+2t+1][n]),
// b1 = h2(W[k+2t+8][n], W[k+2t+9][n]), n1 = n0 + 8.

// H x H (gemm1): per matrix [kt(8)][s(2)][wN(4)][nf4(4)][lane(32)] uint4
__global__ void pack256_kernel(const float* __restrict__ W, __half* __restrict__ out, int nmat) {
    int gid = blockIdx.x * 256 + threadIdx.x;
    if (gid >= nmat * 8192) return;
    int m = gid >> 13, o = gid & 8191;
    int kt = o >> 10, s = (o >> 9) & 1, wN = (o >> 7) & 3, nf4 = (o >> 5) & 3, lane = o & 31;
    int t = lane & 3, g = lane >> 2;
    int k = kt * 32 + s * 16 + 2 * t;
    int n0 = wN * 64 + nf4 * 16 + g, n1 = n0 + 8;
    const float* Wm = W + (size_t)m * 65536;
    uint4 v;
    v.x = pk2(Wm[k * 256 + n0], Wm[(k + 1) * 256 + n0]);
    v.y = pk2(Wm[(k + 8) * 256 + n0], Wm[(k + 9) * 256 + n0]);
    v.z = pk2(Wm[k * 256 + n1], Wm[(k + 1) * 256 + n1]);
    v.w = pk2(Wm[(k + 8) * 256 + n1], Wm[(k + 9) * 256 + n1]);
    ((uint4*)out)[gid] = v;
}

// w_ff1 [256,1024]: per matrix [c(4)][kt(8)][s(2)][wN(8)][nf4(2)][lane] uint4
__global__ void packff1_kernel(const float* __restrict__ W, __half* __restrict__ out, int nmat) {
    int gid = blockIdx.x * 256 + threadIdx.x;
    if (gid >= nmat * 32768) return;
    int m = gid >> 15, o = gid & 32767;
    int c = o >> 13, r = o & 8191;
    int kt = r >> 10, s = (r >> 9) & 1, wN = (r >> 6) & 7, nf4 = (r >> 5) & 1, lane = r & 31;
    int t = lane & 3, g = lane >> 2;
    int k = kt * 32 + s * 16 + 2 * t;
    int n0 = c * 256 + wN * 32 + nf4 * 16 + g, n1 = n0 + 8;
    const float* Wm = W + (size_t)m * 262144;
    uint4 v;
    v.x = pk2(Wm[k * 1024 + n0], Wm[(k + 1) * 1024 + n0]);
    v.y = pk2(Wm[(k + 8) * 1024 + n0], Wm[(k + 9) * 1024 + n0]);
    v.z = pk2(Wm[k * 1024 + n1], Wm[(k + 1) * 1024 + n1]);
    v.w = pk2(Wm[(k + 8) * 1024 + n1], Wm[(k + 9) * 1024 + n1]);
    ((uint4*)out)[gid] = v;
}

// w_ff2 [1024,256]: per matrix [c(4)][kt(8)][s(2)][wN(8)][nf4(2)][lane] uint4
__global__ void packff2_kernel(const float* __restrict__ W, __half* __restrict__ out, int nmat) {
    int gid = blockIdx.x * 256 + threadIdx.x;
    if (gid >= nmat * 32768) return;
    int m = gid >> 15, o = gid & 32767;
    int c = o >> 13, r = o & 8191;
    int kt = r >> 10, s = (r >> 9) & 1, wN = (r >> 6) & 7, nf4 = (r >> 5) & 1, lane = r & 31;
    int t = lane & 3, g = lane >> 2;
    int k = c * 256 + kt * 32 + s * 16 + 2 * t;
    int n0 = wN * 32 + nf4 * 16 + g, n1 = n0 + 8;
    const float* Wm = W + (size_t)m * 262144;
    uint4 v;
    v.x = pk2(Wm[k * 256 + n0], Wm[(k + 1) * 256 + n0]);
    v.y = pk2(Wm[(k + 8) * 256 + n0], Wm[(k + 9) * 256 + n0]);
    v.z = pk2(Wm[k * 256 + n1], Wm[(k + 1) * 256 + n1]);
    v.w = pk2(Wm[(k + 8) * 256 + n1], Wm[(k + 9) * 256 + n1]);
    ((uint4*)out)[gid] = v;
}

// ---------------- small kernels (fp16 activations) ----------------

__global__ void cvth_kernel(const float* __restrict__ in, __half* __restrict__ out, int n8) {
    int i = blockIdx.x * 256 + threadIdx.x;
    if (i >= n8) return;
    const float* p = in + (size_t)i * 8;
    float4 v0 = ((const float4*)p)[0], v1 = ((const float4*)p)[1];
    uint4 o;
    o.x = pk2(v0.x, v0.y); o.y = pk2(v0.z, v0.w);
    o.z = pk2(v1.x, v1.y); o.w = pk2(v1.z, v1.w);
    ((uint4*)out)[i] = o;
}

__global__ void embed_kernel(const float* __restrict__ rel, const int* __restrict__ feat,
                             __half* __restrict__ out) {
    int gid = blockIdx.x * 256 + threadIdx.x;
    int e = gid >> 5;
    if (e >= NEDGE) return;
    int c8 = (gid & 31) * 8;
    int r = __ldg(feat + e);
    const float* p = rel + (size_t)r * H + c8;
    float4 v0 = ((const float4*)p)[0], v1 = ((const float4*)p)[1];
    uint4 o;
    o.x = pk2(v0.x, v0.y); o.y = pk2(v0.z, v0.w);
    o.z = pk2(v1.x, v1.y); o.w = pk2(v1.z, v1.w);
    *(uint4*)(out + (size_t)e * H + c8) = o;
}

__global__ void gather2_kernel(const __half* __restrict__ x, const int* __restrict__ s,
                               const int* __restrict__ d, __half* __restrict__ out, int n) {
    int gid = blockIdx.x * 256 + threadIdx.x;
    int e = gid >> 5;
    if (e >= n) return;
    int c8 = (gid & 31) * 8;
    int si = __ldg(s + e), di = __ldg(d + e);
    uint4 ua = *(const uint4*)(x + (size_t)si * H + c8);
    uint4 ub = *(const uint4*)(x + (size_t)di * H + c8);
    const uint32_t* ap = (const uint32_t*)&ua;
    const uint32_t* bp = (const uint32_t*)&ub;
    uint4 o; uint32_t* op = (uint32_t*)&o;
#pragma unroll
    for (int i = 0; i < 4; i++) {
        float2 fa = uph2(ap[i]), fb = uph2(bp[i]);
        op[i] = pkh2(fa.x + fb.x, fa.y + fb.y);
    }
    *(uint4*)(out + (size_t)e * H + c8) = o;
}

__global__ void segsum_kernel(const __half* __restrict__ rows, const int* __restrict__ rp,
                              const int* __restrict__ ci, __half* __restrict__ out, int nseg) {
    int row = blockIdx.x * 8 + (threadIdx.x >> 5);
    if (row >= nseg) return;
    int lane = threadIdx.x & 31;
    int beg = __ldg(rp + row), end = __ldg(rp + row + 1);
    float a[8] = {0.f,0.f,0.f,0.f,0.f,0.f,0.f,0.f};
    float b[8] = {0.f,0.f,0.f,0.f,0.f,0.f,0.f,0.f};
    int j = beg;
    for (; j + 1 < end; j += 2) {
        uint4 u = *(const uint4*)(rows + (size_t)__ldg(ci + j) * H + lane * 8);
        uint4 v = *(const uint4*)(rows + (size_t)__ldg(ci + j + 1) * H + lane * 8);
        const uint32_t* up = (const uint32_t*)&u;
        const uint32_t* vp = (const uint32_t*)&v;
#pragma unroll
        for (int i = 0; i < 4; i++) {
            float2 f = uph2(up[i]); a[2*i] += f.x; a[2*i+1] += f.y;
            float2 q = uph2(vp[i]); b[2*i] += q.x; b[2*i+1] += q.y;
        }
    }
    if (j < end) {
        uint4 u = *(const uint4*)(rows + (size_t)__ldg(ci + j) * H + lane * 8);
        const uint32_t* up = (const uint32_t*)&u;
#pragma unroll
        for (int i = 0; i < 4; i++) {
            float2 f = uph2(up[i]); a[2*i] += f.x; a[2*i+1] += f.y;
        }
    }
    uint4 o; uint32_t* op = (uint32_t*)&o;
#pragma unroll
    for (int i = 0; i < 4; i++) op[i] = pkh2(a[2*i] + b[2*i], a[2*i+1] + b[2*i+1]);
    *(uint4*)(out + (size_t)row * H + lane * 8) = o;
}

__global__ void segsum_rel_kernel(const float* __restrict__ rel, const int* __restrict__ feat,
                                  const int* __restrict__ rp, const int* __restrict__ ci,
                                  __half* __restrict__ out, int nseg) {
    int row = blockIdx.x * 8 + (threadIdx.x >> 5);
    if (row >= nseg) return;
    int lane = threadIdx.x & 31;
    int beg = __ldg(rp + row), end = __ldg(rp + row + 1);
    float a[8] = {0.f,0.f,0.f,0.f,0.f,0.f,0.f,0.f};
    for (int j = beg; j < end; j++) {
        int r = __ldg(feat + __ldg(ci + j));
        const float* p = rel + (size_t)r * H + lane * 8;
        float4 v0 = ((const float4*)p)[0], v1 = ((const float4*)p)[1];
        float2 q;
        q = uph2(pk2(v0.x, v0.y)); a[0] += q.x; a[1] += q.y;
        q = uph2(pk2(v0.z, v0.w)); a[2] += q.x; a[3] += q.y;
        q = uph2(pk2(v1.x, v1.y)); a[4] += q.x; a[5] += q.y;
        q = uph2(pk2(v1.z, v1.w)); a[6] += q.x; a[7] += q.y;
    }
    uint4 o; uint32_t* op = (uint32_t*)&o;
#pragma unroll
    for (int i = 0; i < 4; i++) op[i] = pkh2(a[2*i], a[2*i+1]);
    *(uint4*)(out + (size_t)row * H + lane * 8) = o;
}

// ================= GEMM1 + LN1 fused (fp16), m32n64 warp tile =================
#define G1_SMEM_BYTES (10240 + 32768 + 5 * 1024)

struct G1Args {
    const __half* A[6];
    const __half* W[6];
    const float* Bias[6];
    const __half* xres;
    const float* gamma;
    const float* beta;
};

__global__ void __launch_bounds__(256, 2)
gemm1_ln_kernel(G1Args args, int M, __half* __restrict__ out) {
    extern __shared__ char smraw[];
    __half* As = (__half*)smraw;                // 2 x 2560 halves (stride 40)
    __half* Bs = As + 2 * 2560;                 // 2 x 8192 halves
    float* bias_s = (float*)(Bs + 2 * 8192);
    float* gs  = bias_s + 256;
    float* bt  = gs + 256;
    float* lnS = bt + 256;
    float* lnQ = lnS + 256;
    __half* xs = (__half*)smraw;                // alias after mainloop, stride 264

    int tid = threadIdx.x;
    int bm = blockIdx.x * 64;
    {
        float b = 0.f;
#pragma unroll
        for (int j = 0; j < 6; j++) b += __ldg(args.Bias[j] + tid);
        bias_s[tid] = b;
        gs[tid] = __ldg(args.gamma + tid);
        bt[tid] = __ldg(args.beta + tid);
    }

    uint32_t sbase = (uint32_t)__cvta_generic_to_shared(smraw);
    uint32_t a_base = sbase;
    uint32_t b_base = sbase + 10240;

    int warp = tid >> 5, lane = tid & 31, g = lane >> 2, t = lane & 3;
    int wm = (warp >> 2) * 32;
    int wN = warp & 3;
    int wn = wN * 64;

    float acc[2][8][4];
#pragma unroll
    for (int mt = 0; mt < 2; mt++)
#pragma unroll
        for (int nf = 0; nf < 8; nf++)
#pragma unroll
            for (int i = 0; i < 4; i++) acc[mt][nf][i] = 0.f;

    auto issue = [&](int tt, int buf) {
        int j = tt >> 3, kt = tt & 7;
        const __half* A = args.A[j];
        const uint4* Wp = (const uint4*)args.W[j] + (size_t)kt * 1024;
        {
            int r = tid >> 2, cp = tid & 3;
            int row = bm + r;
            uint32_t dst = a_base + (uint32_t)(buf * 5120 + r * 80 + cp * 16);
            const __half* src = A + (size_t)row * H + kt * 32 + cp * 8;
            int sz = (row < M) ? 16 : 0;
            asm volatile("cp.async.cg.shared.global [%0], [%1], 16, %2;\n"
                         :: "r"(dst), "l"(src), "r"(sz));
        }
#pragma unroll
        for (int i = 0; i < 4; i++) {
            int idx = tid + i * 256;
            uint32_t dst = b_base + (uint32_t)(buf * 16384 + idx * 16);
            asm volatile("cp.async.cg.shared.global [%0], [%1], 16;\n"
                         :: "r"(dst), "l"(Wp + idx));
        }
        asm volatile("cp.async.commit_group;\n");
    };

    issue(0, 0);
    for (int tt = 0; tt < 48; tt++) {
        asm volatile("cp.async.wait_group 0;\n");
        __syncthreads();
        if (tt + 1 < 48) issue(tt + 1, (tt + 1) & 1);
        const __half* Ab = As + (tt & 1) * 2560;
        const uint4* Bb4 = (const uint4*)(Bs + (tt & 1) * 8192) + wN * 128 + lane;
#pragma unroll
        for (int s = 0; s < 2; s++) {
            int k0 = s * 16 + 2 * t;
            const __half* Ar0 = Ab + (wm + g) * 40 + k0;
            const __half* Ar1 = Ab + (wm + 8 + g) * 40 + k0;
            const __half* Ar2 = Ab + (wm + 16 + g) * 40 + k0;
            const __half* Ar3 = Ab + (wm + 24 + g) * 40 + k0;
            uint32_t a0[4], a1[4];
            a0[0] = *(const uint32_t*)Ar0;
            a0[1] = *(const uint32_t*)Ar1;
            a0[2] = *(const uint32_t*)(Ar0 + 8);
            a0[3] = *(const uint32_t*)(Ar1 + 8);
            a1[0] = *(const uint32_t*)Ar2;
            a1[1] = *(const uint32_t*)Ar3;
            a1[2] = *(const uint32_t*)(Ar2 + 8);
            a1[3] = *(const uint32_t*)(Ar3 + 8);
#pragma unroll
            for (int nf4 = 0; nf4 < 4; nf4++) {
                uint4 bv = Bb4[s * 512 + nf4 * 32];
                uint32_t b0[2] = {bv.x, bv.y};
                uint32_t b1[2] = {bv.z, bv.w};
                mma_f16(acc[0][2 * nf4], a0, b0);
                mma_f16(acc[1][2 * nf4], a1, b0);
                mma_f16(acc[0][2 * nf4 + 1], a0, b1);
                mma_f16(acc[1][2 * nf4 + 1], a1, b1);
            }
        }
    }
    __syncthreads();

#pragma unroll
    for (int i = 0; i < 8; i++) {
        int idx = tid + i * 256;
        int r = idx >> 5, c8 = (idx & 31) * 8;
        int row = bm + r;
        uint4 v = make_uint4(0, 0, 0, 0);
        if (row < M) v = *(const uint4*)(args.xres + (size_t)row * H + c8);
        *(uint4*)(xs + r * 264 + c8) = v;
    }
    __syncthreads();

#pragma unroll
    for (int mt = 0; mt < 2; mt++) {
#pragma unroll
        for (int h = 0; h < 2; h++) {
            int row = wm + mt * 16 + h * 8 + g;
            float s = 0.f, q = 0.f;
#pragma unroll
            for (int nf = 0; nf < 8; nf++) {
                int col = wn + nf * 8 + 2 * t;
                float2 xv = uph2(*(const uint32_t*)(xs + row * 264 + col));
                float v0 = xv.x + gelu_exact(acc[mt][nf][2 * h]     + bias_s[col]);
                float v1 = xv.y + gelu_exact(acc[mt][nf][2 * h + 1] + bias_s[col + 1]);
                acc[mt][nf][2 * h] = v0; acc[mt][nf][2 * h + 1] = v1;
                s += v0 + v1; q += v0 * v0 + v1 * v1;
            }
#pragma unroll
            for (int o = 1; o <= 2; o <<= 1) {
                s += __shfl_xor_sync(0xffffffffu, s, o);
                q += __shfl_xor_sync(0xffffffffu, q, o);
            }
            if (t == 0) { lnS[row * 4 + wN] = s; lnQ[row * 4 + wN] = q; }
        }
    }
    __syncthreads();
#pragma unroll
    for (int mt = 0; mt < 2; mt++) {
#pragma unroll
        for (int h = 0; h < 2; h++) {
            int row = wm + mt * 16 + h * 8 + g;
            float S = lnS[row * 4] + lnS[row * 4 + 1] + lnS[row * 4 + 2] + lnS[row * 4 + 3];
            float Q = lnQ[row * 4] + lnQ[row * 4 + 1] + lnQ[row * 4 + 2] + lnQ[row * 4 + 3];
            float m = S * (1.f / H), v = Q * (1.f / H) - m * m, rs = rsqrtf(v + 1e-5f);
            if (bm + row < M) {
#pragma unroll
                for (int nf = 0; nf < 8; nf++) {
                    int col = wn + nf * 8 + 2 * t;
                    float o0 = (acc[mt][nf][2 * h]     - m) * rs * gs[col]     + bt[col];
                    float o1 = (acc[mt][nf][2 * h + 1] - m) * rs * gs[col + 1] + bt[col + 1];
                    *(uint32_t*)(out + (size_t)(bm + row) * H + col) = pkh2(o0, o1);
                }
            }
        }
    }
}

// ================= fused FFN + LN2 (fp16), 4 chunks of 256, mW=2 x nW=8 =============
#define F_SMEM_BYTES (33792 + 33792 + 32768 + 8192)   // 108544

struct FArgs {
    const __half* w1;
    const float* b1;
    const __half* w2;
    const float* b2;
    const float* gamma;
    const float* beta;
};

__global__ void __launch_bounds__(512, 1)
ffn_kernel(FArgs args, int M, const __half* __restrict__ in1,
           void* __restrict__ outv, int out_half) {
    extern __shared__ char smraw[];
    __half* xs  = (__half*)smraw;            // 64 x 264 halves
    __half* hb  = xs + 64 * 264;             // 64 x 264 halves (256 used)
    __half* Bst = hb + 64 * 264;             // 2 x 8192 halves
    float* b2s = (float*)(Bst + 2 * 8192);
    float* gs  = b2s + 256;
    float* bt  = gs + 256;
    float* b1c = bt + 256;                   // 256
    float* lnS = b1c + 256;                  // 512
    float* lnQ = lnS + 512;                  // 512

    int tid = threadIdx.x;
    int bm = blockIdx.x * 64;

    if (tid < 256) {
        b2s[tid] = __ldg(args.b2 + tid);
        gs[tid]  = __ldg(args.gamma + tid);
        bt[tid]  = __ldg(args.beta + tid);
    }
#pragma unroll
    for (int i = 0; i < 4; i++) {
        int idx = tid + i * 512;
        int r = idx >> 5, c8 = (idx & 31) * 8;
        int row = bm + r;
        uint4 v = make_uint4(0, 0, 0, 0);
        if (row < M) v = *(const uint4*)(in1 + (size_t)row * H + c8);
        *(uint4*)(xs + r * 264 + c8) = v;
    }

    uint32_t bst_base = (uint32_t)__cvta_generic_to_shared(Bst);
    int warp = tid >> 5, lane = tid & 31, g = lane >> 2, t = lane & 3;
    int wm = (warp >> 3) * 32;    // 2 m-warps x 32 rows
    int wN = warp & 7;            // 8 n-warps x 32 cols
    int wn = wN * 32;

    float acc2[2][4][4];
#pragma unroll
    for (int mt = 0; mt < 2; mt++)
#pragma unroll
        for (int nf = 0; nf < 4; nf++)
#pragma unroll
            for (int i = 0; i < 4; i++) acc2[mt][nf][i] = 0.f;

    __syncthreads();

    for (int c = 0; c < 4; c++) {
        if (c > 0) __syncthreads();
        if (tid < 256) b1c[tid] = __ldg(args.b1 + c * 256 + tid);

        float acc1[2][4][4];
#pragma unroll
        for (int mt = 0; mt < 2; mt++)
#pragma unroll
            for (int nf = 0; nf < 4; nf++)
#pragma unroll
                for (int i = 0; i < 4; i++) acc1[mt][nf][i] = 0.f;

        const uint4* W1p = (const uint4*)args.w1 + (size_t)c * 8192;
        auto issue1 = [&](int kt, int buf) {
#pragma unroll
            for (int i = 0; i < 2; i++) {
                int idx = tid + i * 512;
                uint32_t dst = bst_base + (uint32_t)(buf * 16384 + idx * 16);
                asm volatile("cp.async.cg.shared.global [%0], [%1], 16;\n"
                             :: "r"(dst), "l"(W1p + kt * 1024 + idx));
            }
            asm volatile("cp.async.commit_group;\n");
        };

        issue1(0, 0);
        for (int kt = 0; kt < 8; kt++) {
            asm volatile("cp.async.wait_group 0;\n");
            __syncthreads();
            if (kt + 1 < 8) issue1(kt + 1, (kt + 1) & 1);
            const uint4* Bb4 = (const uint4*)(Bst + (kt & 1) * 8192) + wN * 64 + lane;
#pragma unroll
            for (int s = 0; s < 2; s++) {
                int kg = kt * 32 + s * 16 + 2 * t;
                const __half* Ar0 = xs + (wm + g) * 264 + kg;
                const __half* Ar1 = xs + (wm + 8 + g) * 264 + kg;
                const __half* Ar2 = xs + (wm + 16 + g) * 264 + kg;
                const __half* Ar3 = xs + (wm + 24 + g) * 264 + kg;
                uint32_t a0[4], a1[4];
                a0[0] = *(const uint32_t*)Ar0;
                a0[1] = *(const uint32_t*)Ar1;
                a0[2] = *(const uint32_t*)(Ar0 + 8);
                a0[3] = *(const uint32_t*)(Ar1 + 8);
                a1[0] = *(const uint32_t*)Ar2;
                a1[1] = *(const uint32_t*)Ar3;
                a1[2] = *(const uint32_t*)(Ar2 + 8);
                a1[3] = *(const uint32_t*)(Ar3 + 8);
#pragma unroll
                for (int nf4 = 0; nf4 < 2; nf4++) {
                    uint4 bv = Bb4[s * 512 + nf4 * 32];
                    uint32_t b0[2] = {bv.x, bv.y};
                    uint32_t b1[2] = {bv.z, bv.w};
                    mma_f16(acc1[0][2 * nf4], a0, b0);
                    mma_f16(acc1[1][2 * nf4], a1, b0);
                    mma_f16(acc1[0][2 * nf4 + 1], a0, b1);
                    mma_f16(acc1[1][2 * nf4 + 1], a1, b1);
                }
            }
        }

        // h = h16(gelu(acc1 + b1)) -> hb
#pragma unroll
        for (int mt = 0; mt < 2; mt++) {
#pragma unroll
            for (int nf = 0; nf < 4; nf++) {
                int col = wn + nf * 8 + 2 * t;
                float h0 = gelu_exact(acc1[mt][nf][0] + b1c[col]);
                float h1 = gelu_exact(acc1[mt][nf][1] + b1c[col + 1]);
                float h2v = gelu_exact(acc1[mt][nf][2] + b1c[col]);
                float h3v = gelu_exact(acc1[mt][nf][3] + b1c[col + 1]);
                *(uint32_t*)(hb + (wm + mt * 16 + g) * 264 + col)     = pkh2(h0, h1);
                *(uint32_t*)(hb + (wm + mt * 16 + 8 + g) * 264 + col) = pkh2(h2v, h3v);
            }
        }
        __syncthreads();

        const uint4* W2p = (const uint4*)args.w2 + (size_t)c * 8192;
        auto issue2 = [&](int kt, int buf) {
#pragma unroll
            for (int i = 0; i < 2; i++) {
                int idx = tid + i * 512;
                uint32_t dst = bst_base + (uint32_t)(buf * 16384 + idx * 16);
                asm volatile("cp.async.cg.shared.global [%0], [%1], 16;\n"
                             :: "r"(dst), "l"(W2p + kt * 1024 + idx));
            }
            asm volatile("cp.async.commit_group;\n");
        };

        issue2(0, 0);
        for (int kt = 0; kt < 8; kt++) {
            asm volatile("cp.async.wait_group 0;\n");
            __syncthreads();
            if (kt + 1 < 8) issue2(kt + 1, (kt + 1) & 1);
            const uint4* Bb4 = (const uint4*)(Bst + (kt & 1) * 8192) + wN * 64 + lane;
#pragma unroll
            for (int s = 0; s < 2; s++) {
                int kg = kt * 32 + s * 16 + 2 * t;
                const __half* Ar0 = hb + (wm + g) * 264 + kg;
                const __half* Ar1 = hb + (wm + 8 + g) * 264 + kg;
                const __half* Ar2 = hb + (wm + 16 + g) * 264 + kg;
                const __half* Ar3 = hb + (wm + 24 + g) * 264 + kg;
                uint32_t a0[4], a1[4];
                a0[0] = *(const uint32_t*)Ar0;
                a0[1] = *(const uint32_t*)Ar1;
                a0[2] = *(const uint32_t*)(Ar0 + 8);
                a0[3] = *(const uint32_t*)(Ar1 + 8);
                a1[0] = *(const uint32_t*)Ar2;
                a1[1] = *(const uint32_t*)Ar3;
                a1[2] = *(const uint32_t*)(Ar2 + 8);
                a1[3] = *(const uint32_t*)(Ar3 + 8);
#pragma unroll
                for (int nf4 = 0; nf4 < 2; nf4++) {
                    uint4 bv = Bb4[s * 512 + nf4 * 32];
                    uint32_t b0[2] = {bv.x, bv.y};
                    uint32_t b1[2] = {bv.z, bv.w};
                    mma_f16(acc2[0][2 * nf4], a0, b0);
                    mma_f16(acc2[1][2 * nf4], a1, b0);
                    mma_f16(acc2[0][2 * nf4 + 1], a0, b1);
                    mma_f16(acc2[1][2 * nf4 + 1], a1, b1);
                }
            }
        }
    }

    // LN2 epilogue
#pragma unroll
    for (int mt = 0; mt < 2; mt++) {
#pragma unroll
        for (int h = 0; h < 2; h++) {
            int row = wm + mt * 16 + h * 8 + g;
            float s = 0.f, q = 0.f;
#pragma unroll
            for (int nf = 0; nf < 4; nf++) {
                int col = wn + nf * 8 + 2 * t;
                float2 xv = uph2(*(const uint32_t*)(xs + row * 264 + col));
                float v0 = xv.x + acc2[mt][nf][2 * h]     + b2s[col];
                float v1 = xv.y + acc2[mt][nf][2 * h + 1] + b2s[col + 1];
                acc2[mt][nf][2 * h] = v0; acc2[mt][nf][2 * h + 1] = v1;
                s += v0 + v1; q += v0 * v0 + v1 * v1;
            }
#pragma unroll
            for (int o = 1; o <= 2; o <<= 1) {
                s += __shfl_xor_sync(0xffffffffu, s, o);
                q += __shfl_xor_sync(0xffffffffu, q, o);
            }
            if (t == 0) { lnS[row * 8 + wN] = s; lnQ[row * 8 + wN] = q; }
        }
    }
    __syncthreads();
#pragma unroll
    for (int mt = 0; mt < 2; mt++) {
#pragma unroll
        for (int h = 0; h < 2; h++) {
            int row = wm + mt * 16 + h * 8 + g;
            float S = 0.f, Q = 0.f;
#pragma unroll
            for (int i = 0; i < 8; i++) { S += lnS[row * 8 + i]; Q += lnQ[row * 8 + i]; }
            float m = S * (1.f / H), v = Q * (1.f / H) - m * m, rs = rsqrtf(v + 1e-5f);
            if (bm + row < M) {
#pragma unroll
                for (int nf = 0; nf < 4; nf++) {
                    int col = wn + nf * 8 + 2 * t;
                    float o0 = (acc2[mt][nf][2 * h]     - m) * rs * gs[col]     + bt[col];
                    float o1 = (acc2[mt][nf][2 * h + 1] - m) * rs * gs[col + 1] + bt[col + 1];
                    if (out_half) {
                        *(uint32_t*)((__half*)outv + (size_t)(bm + row) * H + col) = pkh2(o0, o1);
                    } else {
                        *(float2*)((float*)outv + (size_t)(bm + row) * H + col) = make_float2(o0, o1);
                    }
                }
            }
        }
    }
}

// ---------------- host orchestration ----------------

struct Net {
    const float *b_self, *b_khop, *b_fuse, *b_ff1, *b_ff2;
    const float *ln1g, *ln1b, *ln2g, *ln2b;
    __half* wbuf;
};

static void run_core(const Net& n, int l, int c, int M, __half* const* z,
                     const __half* xin, const __half* fused, __half* out1buf,
                     void* outp, int out_half, cudaStream_t st) {
    size_t lc = (size_t)(l * 2 + c);
    G1Args ga;
    ga.A[0] = xin;
    ga.W[0] = n.wbuf + OFFH_WSELF + lc * 65536;
    ga.Bias[0] = n.b_self + lc * H;
    for (int i = 0; i < 4; i++) {
        ga.A[1 + i] = z[i];
        ga.W[1 + i] = n.wbuf + OFFH_WKHOP + (lc * 4 + i) * (size_t)65536;
        ga.Bias[1 + i] = n.b_khop + (lc * 4 + i) * (size_t)H;
    }
    ga.A[5] = fused;
    ga.W[5] = n.wbuf + OFFH_WFUSE + lc * 65536;
    ga.Bias[5] = n.b_fuse + lc * H;
    ga.xres = xin;
    ga.gamma = n.ln1g + lc * H;
    ga.beta  = n.ln1b + lc * H;

    int grid = (M + 63) / 64;
    gemm1_ln_kernel<<<grid, 256, G1_SMEM_BYTES, st>>>(ga, M, out1buf);

    FArgs fa;
    fa.w1 = n.wbuf + OFFH_WFF1 + lc * (size_t)262144;
    fa.b1 = n.b_ff1 + lc * FH;
    fa.w2 = n.wbuf + OFFH_WFF2 + lc * (size_t)262144;
    fa.b2 = n.b_ff2 + lc * H;
    fa.gamma = n.ln2g + lc * H;
    fa.beta  = n.ln2b + lc * H;
    ffn_kernel<<<grid, 512, F_SMEM_BYTES, st>>>(fa, M, out1buf, outp, out_half);
}

static void exclusive_scan(int* cnt, int* rp, int* bsums, int n, cudaStream_t st) {
    int nb = (n + 1023) / 1024;
    scan1_kernel<<<nb, 1024, 0, st>>>(cnt, rp, bsums, n);
    scan2_kernel<<<1, 1024, 0, st>>>(bsums, nb);
    scan3_kernel<<<nb, 1024, 0, st>>>(rp, bsums, cnt, n);
}

extern "C" void kernel_launch(void* const* d_in, const int* in_sizes, int n_in,
                              void* d_out, int out_size) {
    const float* x_in = (const float*)d_in[0];
    const int* feat   = (const int*)d_in[1];
    const int* eig    = (const int*)d_in[2];
    const int* eil    = (const int*)d_in[3];
    const float* rel  = (const float*)d_in[4];

    const float* w_self = (const float*)d_in[5];
    const float* w_khop = (const float*)d_in[7];
    const float* w_fuse = (const float*)d_in[9];
    const float* w_ff1  = (const float*)d_in[11];
    const float* w_ff2  = (const float*)d_in[13];

    Net n;
    n.b_self = (const float*)d_in[6];
    n.b_khop = (const float*)d_in[8];
    n.b_fuse = (const float*)d_in[10];
    n.b_ff1  = (const float*)d_in[12];
    n.b_ff2  = (const float*)d_in[14];
    n.ln1g   = (const float*)d_in[15]; n.ln1b = (const float*)d_in[16];
    n.ln2g   = (const float*)d_in[17]; n.ln2b = (const float*)d_in[18];

    cudaFuncSetAttribute(gemm1_ln_kernel,
                         cudaFuncAttributeMaxDynamicSharedMemorySize, G1_SMEM_BYTES);
    cudaFuncSetAttribute(ffn_kernel,
                         cudaFuncAttributeMaxDynamicSharedMemorySize, F_SMEM_BYTES);

    static cudaStream_t s2 = nullptr;
    static cudaEvent_t ev_start, ev_prep, ev_x0, ev_lg0, ev_fin;
    if (!s2) {
        cudaStreamCreateWithFlags(&s2, cudaStreamNonBlocking);
        cudaEventCreateWithFlags(&ev_start, cudaEventDisableTiming);
        cudaEventCreateWithFlags(&ev_prep,  cudaEventDisableTiming);
        cudaEventCreateWithFlags(&ev_x0,    cudaEventDisableTiming);
        cudaEventCreateWithFlags(&ev_lg0,   cudaEventDisableTiming);
        cudaEventCreateWithFlags(&ev_fin,   cudaEventDisableTiming);
    }

    __half *px0, *plg0, *pfn, *pfe, *pfe2, *pzbase, *pznb, *pout1, *pout1n, *pwbuf;
    int *rp_nd, *ci_nd, *rp_fn, *ci_fn, *rp_lg, *ci_lg;
    int *pcnt, *pcur, *pbs, *pcnt2, *pcur2, *pbs2;
    cudaGetSymbolAddress((void**)&px0,   h_x);
    cudaGetSymbolAddress((void**)&plg0,  h_lg);
    cudaGetSymbolAddress((void**)&pfn,   h_fn);
    cudaGetSymbolAddress((void**)&pfe,   h_fe);
    cudaGetSymbolAddress((void**)&pfe2,  h_fe2);
    cudaGetSymbolAddress((void**)&pzbase,h_z);
    cudaGetSymbolAddress((void**)&pznb,  h_zn);
    cudaGetSymbolAddress((void**)&pout1, h_out1);
    cudaGetSymbolAddress((void**)&pout1n,h_out1n);
    cudaGetSymbolAddress((void**)&pwbuf, g_wbufh);
    cudaGetSymbolAddress((void**)&rp_nd, g_rp_nd);
    cudaGetSymbolAddress((void**)&ci_nd, g_ci_nd);
    cudaGetSymbolAddress((void**)&rp_fn, g_rp_fn);
    cudaGetSymbolAddress((void**)&ci_fn, g_ci_fn);
    cudaGetSymbolAddress((void**)&rp_lg, g_rp_lg);
    cudaGetSymbolAddress((void**)&ci_lg, g_ci_lg);
    cudaGetSymbolAddress((void**)&pcnt,  g_cnt);
    cudaGetSymbolAddress((void**)&pcur,  g_cur);
    cudaGetSymbolAddress((void**)&pbs,   g_bs);
    cudaGetSymbolAddress((void**)&pcnt2, g_cnt2);
    cudaGetSymbolAddress((void**)&pcur2, g_cur2);
    cudaGetSymbolAddress((void**)&pbs2,  g_bs2);

    n.wbuf = pwbuf;
    __half* px[2]  = {px0,  px0  + (size_t)NNODE * H};
    __half* plg[2] = {plg0, plg0 + (size_t)NEDGE * H};
    __half* ze[4]; __half* zn[4];
    for (int i = 0; i < 4; i++) {
        ze[i] = pzbase + (size_t)i * NEDGE * H;
        zn[i] = pznb + (size_t)i * NNODE * H;
    }

    const int* src_g = eig;  const int* dst_g = eig + NEDGE;
    const int* src_l = eil;  const int* dst_l = eil + NLG;

    // fork point for capture
    cudaEventRecord(ev_start, 0);
    cudaStreamWaitEvent(s2, ev_start, 0);

    // ===== stream s2: packs + init + gather2-l0 =====
    cvth_kernel<<<(NNODE * H / 8 + 255) / 256, 256, 0, s2>>>(x_in, px[0], NNODE * H / 8);
    embed_kernel<<<NEDGE * 32 / 256, 256, 0, s2>>>(rel, feat, plg[0]);
    pack256_kernel<<<(4 * 8192 + 255) / 256, 256, 0, s2>>>(w_self, pwbuf + OFFH_WSELF, 4);
    pack256_kernel<<<(16 * 8192 + 255) / 256, 256, 0, s2>>>(w_khop, pwbuf + OFFH_WKHOP, 16);
    pack256_kernel<<<(4 * 8192 + 255) / 256, 256, 0, s2>>>(w_fuse, pwbuf + OFFH_WFUSE, 4);
    packff1_kernel<<<(4 * 32768 + 255) / 256, 256, 0, s2>>>(w_ff1, pwbuf + OFFH_WFF1, 4);
    packff2_kernel<<<(4 * 32768 + 255) / 256, 256, 0, s2>>>(w_ff2, pwbuf + OFFH_WFF2, 4);
    gather2_kernel<<<NEDGE * 32 / 256, 256, 0, s2>>>(px[0], src_g, dst_g, pfe, NEDGE);
    cudaEventRecord(ev_prep, s2);

    // ===== stream s2: node CSRs + node core layer 0 =====
    cudaMemsetAsync(pcnt2, 0, NNODE * sizeof(int), s2);
    hist_kernel<<<(NEDGE + 255) / 256, 256, 0, s2>>>(dst_g, pcnt2, NEDGE);
    exclusive_scan(pcnt2, rp_nd, pbs2, NNODE, s2);
    cudaMemcpyAsync(pcur2, rp_nd, NNODE * sizeof(int), cudaMemcpyDeviceToDevice, s2);
    fill_kernel<<<(NEDGE + 255) / 256, 256, 0, s2>>>(dst_g, src_g, pcur2, ci_nd, NEDGE);

    cudaMemsetAsync(pcnt2, 0, NNODE * sizeof(int), s2);
    hist_kernel<<<(NEDGE + 255) / 256, 256, 0, s2>>>(src_g, pcnt2, NEDGE);
    hist_kernel<<<(NEDGE + 255) / 256, 256, 0, s2>>>(dst_g, pcnt2, NEDGE);
    exclusive_scan(pcnt2, rp_fn, pbs2, NNODE, s2);
    cudaMemcpyAsync(pcur2, rp_fn, NNODE * sizeof(int), cudaMemcpyDeviceToDevice, s2);
    fill_kernel<<<(NEDGE + 255) / 256, 256, 0, s2>>>(src_g, nullptr, pcur2, ci_fn, NEDGE);
    fill_kernel<<<(NEDGE + 255) / 256, 256, 0, s2>>>(dst_g, nullptr, pcur2, ci_fn, NEDGE);

    segsum_kernel<<<(NNODE + 7) / 8, 256, 0, s2>>>(plg[0], rp_fn, ci_fn, pfn, NNODE);
    {
        const __half* prev = px[0];
        for (int i = 0; i < 4; i++) {
            segsum_kernel<<<(NNODE + 7) / 8, 256, 0, s2>>>(prev, rp_nd, ci_nd, zn[i], NNODE);
            prev = zn[i];
        }
    }
    run_core(n, 0, 0, NNODE, zn, px[0], pfn, pout1n, px[1], 1, s2);
    // gather2 for layer-1 edge core (px[1] is s2-local; writes pfe2, no race with pfe)
    gather2_kernel<<<NEDGE * 32 / 256, 256, 0, s2>>>(px[1], src_g, dst_g, pfe2, NEDGE);
    cudaEventRecord(ev_x0, s2);

    // ===== stream 0: lg CSR + layer-0 edge khops =====
    cudaMemsetAsync(pcnt, 0, NEDGE * sizeof(int), 0);
    hist_kernel<<<(NLG + 255) / 256, 256>>>(dst_l, pcnt, NLG);
    exclusive_scan(pcnt, rp_lg, pbs, NEDGE, 0);
    cudaMemcpyAsync(pcur, rp_lg, NEDGE * sizeof(int), cudaMemcpyDeviceToDevice, 0);
    fill_kernel<<<(NLG + 255) / 256, 256>>>(dst_l, src_l, pcur, ci_lg, NLG);

    segsum_rel_kernel<<<(NEDGE + 7) / 8, 256>>>(rel, feat, rp_lg, ci_lg, ze[0], NEDGE);
    segsum_kernel<<<(NEDGE + 7) / 8, 256>>>(ze[0], rp_lg, ci_lg, ze[1], NEDGE);
    segsum_kernel<<<(NEDGE + 7) / 8, 256>>>(ze[1], rp_lg, ci_lg, ze[2], NEDGE);
    segsum_kernel<<<(NEDGE + 7) / 8, 256>>>(ze[2], rp_lg, ci_lg, ze[3], NEDGE);

    // ===== stream 0: edge core, layer 0 =====
    cudaStreamWaitEvent(0, ev_prep, 0);
    run_core(n, 0, 1, NEDGE, ze, plg[0], pfe, pout1, plg[1], 1, (cudaStream_t)0);
    cudaEventRecord(ev_lg0, 0);

    // ===== stream s2: node core, layer 1 =====
    cudaStreamWaitEvent(s2, ev_lg0, 0);
    segsum_kernel<<<(NNODE + 7) / 8, 256, 0, s2>>>(plg[1], rp_fn, ci_fn, pfn, NNODE);
    {
        const __half* prev = px[1];
        for (int i = 0; i < 4; i++) {
            segsum_kernel<<<(NNODE + 7) / 8, 256, 0, s2>>>(prev, rp_nd, ci_nd, zn[i], NNODE);
            prev = zn[i];
        }
    }
    run_core(n, 1, 0, NNODE, zn, px[1], pfn, pout1n, (float*)d_out, 0, s2);
    cudaEventRecord(ev_fin, s2);

    // ===== stream 0: edge core, layer 1 (hops need only plg[1], no cross-stream wait) ====
    {
        const __half* prev = plg[1];
        for (int i = 0; i < 4; i++) {
            segsum_kernel<<<(NEDGE + 7) / 8, 256>>>(prev, rp_lg, ci_lg, ze[i], NEDGE);
            prev = ze[i];
        }
    }
    cudaStreamWaitEvent(0, ev_x0, 0);
    run_core(n, 1, 1, NEDGE, ze, plg[1], pfe2, pout1,
             (float*)d_out + (size_t)NNODE * H, 0, (cudaStream_t)0);

    cudaStreamWaitEvent(0, ev_fin, 0);
    (void)in_sizes; (void)n_in; (void)out_size;
}